// round 3
// baseline (speedup 1.0000x reference)
#include <cuda_runtime.h>
#include <math.h>

#define NN 30000
#define RR 1000
#define TT 300000
#define DD 128
#define BB 1024
#define NZ 600000
#define OUTD 768
#define GAMMA_C 3.0f

// ---------------- scratch (device globals; no allocations allowed) ----------------
__device__ float g_tri[(size_t)TT * DD];     // tri_rel -> normalized tri_hat (in place)
__device__ float g_attw[4 * TT];             // att logits -> softmax weights (in place)
__device__ float g_m[4 * NN];                // segment max
__device__ float g_s[4 * NN];                // segment expsum
__device__ float g_featE[(size_t)NN * DD];
__device__ float g_featR[(size_t)NN * DD];
__device__ float g_degE[NN];
__device__ float g_degR[NN];
__device__ float g_fcur[(size_t)NN * DD];
__device__ float g_fnew[(size_t)NN * DD];
__device__ float g_emb[(size_t)NN * OUTD];   // final concat embedding
__device__ float g_nb[NN];                   // ||emb_j||^2
__device__ int   g_idxA[2 * BB];
__device__ float g_na[2 * BB];
__device__ float g_pos[BB];
__device__ int   g_lp[BB];
__device__ int   g_rp[BB];
__device__ float g_S[(size_t)2 * BB * NN];   // loss matrix 2048 x 30000
__device__ float g_lse[2 * BB];

__device__ __forceinline__ float warp_sum(float v) {
#pragma unroll
    for (int o = 16; o > 0; o >>= 1) v += __shfl_xor_sync(0xffffffffu, v, o);
    return v;
}

__device__ __forceinline__ void atomicMaxF(float* addr, float v) {
    if (v >= 0.f) atomicMax((int*)addr, __float_as_int(v));
    else          atomicMin((unsigned int*)addr, __float_as_uint(v));
}

// ---------------- init ----------------
__global__ void k_init() {
    size_t gid = (size_t)blockIdx.x * blockDim.x + threadIdx.x;
    size_t stride = (size_t)gridDim.x * blockDim.x;
    for (size_t i = gid; i < (size_t)TT * DD; i += stride) g_tri[i] = 0.f;
    for (size_t i = gid; i < (size_t)NN * DD; i += stride) { g_featE[i] = 0.f; g_featR[i] = 0.f; }
    for (size_t i = gid; i < NN; i += stride) { g_degE[i] = 0.f; g_degR[i] = 0.f; }
    for (size_t i = gid; i < 4 * (size_t)NN; i += stride) { g_m[i] = -3.0e38f; g_s[i] = 0.f; }
}

// ---------------- tri_rel scatter + normalize + attention logits ----------------
__global__ void k_tri_scatter(const int* __restrict__ r_index,
                              const float* __restrict__ r_val,
                              const float* __restrict__ rel_emb) {
    int gid = blockIdx.x * blockDim.x + threadIdx.x;
    int t = gid >> 5;
    if (t >= TT) return;
    int d = (gid & 31) * 4;
    int dst = r_index[t];
    int rel = r_index[TT + t];
    float v = r_val[t];
    const float4 e = *(const float4*)&rel_emb[(size_t)rel * DD + d];
    float* p = &g_tri[(size_t)dst * DD + d];
    atomicAdd(p + 0, v * e.x); atomicAdd(p + 1, v * e.y);
    atomicAdd(p + 2, v * e.z); atomicAdd(p + 3, v * e.w);
}

__global__ void k_tri_norm(const float* __restrict__ attn_e, const float* __restrict__ attn_r) {
    int gid = blockIdx.x * blockDim.x + threadIdx.x;
    int t = gid >> 5;
    if (t >= TT) return;
    int lane = gid & 31;
    int d = lane * 4;
    float4 u = *(const float4*)&g_tri[(size_t)t * DD + d];
    float ss = u.x * u.x + u.y * u.y + u.z * u.z + u.w * u.w;
    ss = warp_sum(ss);
    float inv = 1.f / fmaxf(sqrtf(ss), 1e-12f);
    u.x *= inv; u.y *= inv; u.z *= inv; u.w *= inv;
    *(float4*)&g_tri[(size_t)t * DD + d] = u;
    const float* ks[4] = { attn_e, attn_e + DD, attn_r, attn_r + DD };
#pragma unroll
    for (int c = 0; c < 4; c++) {
        const float4 kk = *(const float4*)&ks[c][d];
        float dot = u.x * kk.x + u.y * kk.y + u.z * kk.z + u.w * kk.w;
        dot = warp_sum(dot);
        if (lane == 0) g_attw[c * TT + t] = dot;
    }
}

// ---------------- segment softmax over rows, 4 channels ----------------
__global__ void k_smax1(const int* __restrict__ adj) {
    int gid = blockIdx.x * blockDim.x + threadIdx.x;
    if (gid >= 4 * TT) return;
    int c = gid / TT, t = gid - c * TT;
    int row = adj[t];
    atomicMaxF(&g_m[c * NN + row], g_attw[gid]);
}
__global__ void k_smax2(const int* __restrict__ adj) {
    int gid = blockIdx.x * blockDim.x + threadIdx.x;
    if (gid >= 4 * TT) return;
    int c = gid / TT, t = gid - c * TT;
    int row = adj[t];
    float e = expf(g_attw[gid] - g_m[c * NN + row]);
    g_attw[gid] = e;
    atomicAdd(&g_s[c * NN + row], e);
}
__global__ void k_smax3(const int* __restrict__ adj) {
    int gid = blockIdx.x * blockDim.x + threadIdx.x;
    if (gid >= 4 * TT) return;
    int c = gid / TT, t = gid - c * TT;
    int row = adj[t];
    g_attw[gid] /= g_s[c * NN + row];
}

// ---------------- neighbor-average features ----------------
__global__ void k_deg(const int* __restrict__ eadj, int which) {
    int e = blockIdx.x * blockDim.x + threadIdx.x;
    if (e >= NZ) return;
    float* deg = which ? g_degR : g_degE;
    atomicAdd(&deg[eadj[e]], 1.f);
}
__global__ void k_avg_scatter(const int* __restrict__ eadj,
                              const float* __restrict__ src, int which) {
    int gid = blockIdx.x * blockDim.x + threadIdx.x;
    int e = gid >> 5;
    if (e >= NZ) return;
    int d = (gid & 31) * 4;
    int row = eadj[e], col = eadj[NZ + e];
    float* feat = which ? g_featR : g_featE;
    const float4 v = *(const float4*)&src[(size_t)col * DD + d];
    float* p = &feat[(size_t)row * DD + d];
    atomicAdd(p + 0, v.x); atomicAdd(p + 1, v.y);
    atomicAdd(p + 2, v.z); atomicAdd(p + 3, v.w);
}
__global__ void k_avg_div(int which) {
    int idx = blockIdx.x * blockDim.x + threadIdx.x;
    if (idx >= NN * DD) return;
    float* feat = which ? g_featR : g_featE;
    const float* deg = which ? g_degR : g_degE;
    float dg = deg[idx / DD];
    if (dg > 0.f) feat[idx] /= dg;
}

// ---------------- GAT ----------------
__global__ void k_tanh_write(int srcSel, int base) {
    int idx = blockIdx.x * blockDim.x + threadIdx.x;
    if (idx >= NN * DD) return;
    const float* src = (srcSel == 0) ? g_featE : (srcSel == 1) ? g_featR : g_fnew;
    float v = tanhf(src[idx]);
    g_fcur[idx] = v;
    int n = idx / DD, d = idx - n * DD;
    g_emb[(size_t)n * OUTD + base + d] = v;
}
__global__ void k_zero_fnew() {
    int idx = blockIdx.x * blockDim.x + threadIdx.x;
    if (idx < NN * DD) g_fnew[idx] = 0.f;
}
__global__ void k_edge_gat(const int* __restrict__ adj, int c) {
    int gid = blockIdx.x * blockDim.x + threadIdx.x;
    int t = gid >> 5;
    if (t >= TT) return;
    int lane = gid & 31;
    int d = lane * 4;
    int row = adj[t], col = adj[TT + t];
    float4 u = *(const float4*)&g_tri[(size_t)t * DD + d];
    float4 x = *(const float4*)&g_fcur[(size_t)col * DD + d];
    float dot = warp_sum(x.x * u.x + x.y * u.y + x.z * u.z + x.w * u.w);
    float wgt = g_attw[c * TT + t];
    float s2 = 2.f * dot;
    float* p = &g_fnew[(size_t)row * DD + d];
    atomicAdd(p + 0, wgt * (x.x - s2 * u.x));
    atomicAdd(p + 1, wgt * (x.y - s2 * u.y));
    atomicAdd(p + 2, wgt * (x.z - s2 * u.z));
    atomicAdd(p + 3, wgt * (x.w - s2 * u.w));
}

// ---------------- loss prep ----------------
__global__ void k_prep_pairs(const int* __restrict__ pairs) {
    int p = blockIdx.x * blockDim.x + threadIdx.x;
    if (p >= BB) return;
    int lp = pairs[2 * p], rp = pairs[2 * p + 1];
    g_lp[p] = lp; g_rp[p] = rp;
    g_idxA[p] = lp; g_idxA[BB + p] = rp;
}
__global__ void k_norms() {
    int gid = blockIdx.x * blockDim.x + threadIdx.x;
    int j = gid >> 5;
    if (j >= NN) return;
    int lane = gid & 31;
    const float* row = &g_emb[(size_t)j * OUTD];
    float ss = 0.f;
    for (int k = lane * 4; k < OUTD; k += 128) {
        float4 v = *(const float4*)&row[k];
        ss += v.x * v.x + v.y * v.y + v.z * v.z + v.w * v.w;
    }
    ss = warp_sum(ss);
    if (lane == 0) g_nb[j] = ss;
}
__global__ void k_na() {
    int i = blockIdx.x * blockDim.x + threadIdx.x;
    if (i >= 2 * BB) return;
    g_na[i] = g_nb[g_idxA[i]];
}
__global__ void k_pos() {
    int gid = blockIdx.x * blockDim.x + threadIdx.x;
    int p = gid >> 5;
    if (p >= BB) return;
    int lane = gid & 31;
    const float* a = &g_emb[(size_t)g_lp[p] * OUTD];
    const float* b = &g_emb[(size_t)g_rp[p] * OUTD];
    float ss = 0.f;
    for (int k = lane * 4; k < OUTD; k += 128) {
        float4 va = *(const float4*)&a[k];
        float4 vb = *(const float4*)&b[k];
        float dx = va.x - vb.x, dy = va.y - vb.y, dz = va.z - vb.z, dw = va.w - vb.w;
        ss += dx * dx + dy * dy + dz * dz + dw * dw;
    }
    ss = warp_sum(ss);
    if (lane == 0) g_pos[p] = ss;
}

// ---------------- GEMM + loss matrix assembly ----------------
#define BM 64
#define BN 64
#define BK 16
__global__ void k_gemm() {
    __shared__ float As[BK][BM];
    __shared__ float Bs[BK][BN + 4];
    __shared__ int s_idx[BM];
    int bx = blockIdx.x, by = blockIdx.y;
    int tid = threadIdx.x;
    int tx = tid & 15, ty = tid >> 4;
    if (tid < BM) s_idx[tid] = g_idxA[by * BM + tid];
    __syncthreads();
    float acc[4][4] = {};
    int jbase = bx * BN;
    for (int k0 = 0; k0 < OUTD; k0 += BK) {
        {
            int e = tid * 4;
            int i = e >> 4;
            int k = e & 15;
            const float4 a = *(const float4*)&g_emb[(size_t)s_idx[i] * OUTD + k0 + k];
            As[k + 0][i] = a.x; As[k + 1][i] = a.y; As[k + 2][i] = a.z; As[k + 3][i] = a.w;
        }
        {
            int e = tid * 4;
            int jj = e >> 4;
            int k = e & 15;
            int j = jbase + jj;
            float4 b = make_float4(0.f, 0.f, 0.f, 0.f);
            if (j < NN) b = *(const float4*)&g_emb[(size_t)j * OUTD + k0 + k];
            Bs[k + 0][jj] = b.x; Bs[k + 1][jj] = b.y; Bs[k + 2][jj] = b.z; Bs[k + 3][jj] = b.w;
        }
        __syncthreads();
#pragma unroll
        for (int k = 0; k < BK; k++) {
            float4 a = *(const float4*)&As[k][ty * 4];
            float4 b = *(const float4*)&Bs[k][tx * 4];
            float av[4] = { a.x, a.y, a.z, a.w };
            float bv[4] = { b.x, b.y, b.z, b.w };
#pragma unroll
            for (int u = 0; u < 4; u++)
#pragma unroll
                for (int v = 0; v < 4; v++) acc[u][v] += av[u] * bv[v];
        }
        __syncthreads();
    }
#pragma unroll
    for (int u = 0; u < 4; u++) {
        int i = by * BM + ty * 4 + u;
        int p = i & (BB - 1);
        float posv = g_pos[p];
        float nai = g_na[i];
        int lp = g_lp[p], rp = g_rp[p];
#pragma unroll
        for (int v = 0; v < 4; v++) {
            int j = jbase + tx * 4 + v;
            if (j < NN) {
                float val = posv - (nai + g_nb[j] - 2.f * acc[u][v]) + GAMMA_C;
                float mask = 1.f - (float)(j == lp) - (float)(j == rp);
                g_S[(size_t)i * NN + j] = val * mask;
            }
        }
    }
}

// ---------------- per-row stats + logsumexp ----------------
__global__ void k_row_stats() {
    int i = blockIdx.x;
    const float* row = &g_S[(size_t)i * NN];
    int tid = threadIdx.x;
    double s = 0.0, q = 0.0;
    float mx = -3.0e38f;
    for (int j = tid; j < NN; j += 256) {
        float x = row[j];
        s += (double)x;
        q += (double)x * (double)x;
        mx = fmaxf(mx, x);
    }
    __shared__ double sh_s[256];
    __shared__ double sh_q[256];
    __shared__ float sh_m[256];
    sh_s[tid] = s; sh_q[tid] = q; sh_m[tid] = mx;
    __syncthreads();
    for (int o = 128; o > 0; o >>= 1) {
        if (tid < o) {
            sh_s[tid] += sh_s[tid + o];
            sh_q[tid] += sh_q[tid + o];
            sh_m[tid] = fmaxf(sh_m[tid], sh_m[tid + o]);
        }
        __syncthreads();
    }
    __shared__ float sh_mu, sh_inv, sh_zmax;
    if (tid == 0) {
        double mu = sh_s[0] / NN;
        double var = sh_q[0] / NN - mu * mu;
        if (var < 0.0) var = 0.0;
        double sd = sqrt(var);
        sh_mu = (float)mu;
        sh_inv = (float)(20.0 / sd);
        sh_zmax = (float)((sh_m[0] - mu) * (20.0 / sd)) + 8.f;
    }
    __syncthreads();
    float mu = sh_mu, inv = sh_inv, zmax = sh_zmax;
    double es = 0.0;
    for (int j = tid; j < NN; j += 256) {
        float z = (row[j] - mu) * inv + 8.f;
        es += (double)expf(z - zmax);
    }
    sh_s[tid] = es;
    __syncthreads();
    for (int o = 128; o > 0; o >>= 1) {
        if (tid < o) sh_s[tid] += sh_s[tid + o];
        __syncthreads();
    }
    if (tid == 0) g_lse[i] = zmax + logf((float)sh_s[0]);
}

__global__ void k_final(float* out) {
    int tid = threadIdx.x;
    double acc = 0.0;
    for (int p = tid; p < BB; p += 256) acc += (double)g_lse[p] + (double)g_lse[BB + p];
    __shared__ double sh[256];
    sh[tid] = acc;
    __syncthreads();
    for (int o = 128; o > 0; o >>= 1) {
        if (tid < o) sh[tid] += sh[tid + o];
        __syncthreads();
    }
    if (tid == 0) out[0] = (float)(sh[0] / BB);
}

// ---------------- driver ----------------
extern "C" void kernel_launch(void* const* d_in, const int* in_sizes, int n_in,
                              void* d_out, int out_size) {
    const float* ent_emb = (const float*)d_in[0];
    const float* rel_emb = (const float*)d_in[1];
    const float* attn_e  = (const float*)d_in[2];
    const float* attn_r  = (const float*)d_in[3];
    const float* r_val   = (const float*)d_in[4];
    const int* adj     = (const int*)d_in[5];
    const int* r_index = (const int*)d_in[6];
    const int* ent_adj = (const int*)d_in[7];
    const int* rel_adj = (const int*)d_in[8];
    const int* pairs   = (const int*)d_in[9];
    float* out = (float*)d_out;

    const int TPB = 256;
    const int gW_T  = (TT * 32 + TPB - 1) / TPB;   // warp per edge (T)
    const int gW_NZ = (NZ * 32 + TPB - 1) / TPB;   // warp per nnz
    const int gND   = (NN * DD + TPB - 1) / TPB;
    const int g4T   = (4 * TT + TPB - 1) / TPB;

    k_init<<<40000, TPB>>>();
    k_tri_scatter<<<gW_T, TPB>>>(r_index, r_val, rel_emb);
    k_tri_norm<<<gW_T, TPB>>>(attn_e, attn_r);
    k_smax1<<<g4T, TPB>>>(adj);
    k_smax2<<<g4T, TPB>>>(adj);
    k_smax3<<<g4T, TPB>>>(adj);

    k_deg<<<(NZ + TPB - 1) / TPB, TPB>>>(ent_adj, 0);
    k_deg<<<(NZ + TPB - 1) / TPB, TPB>>>(rel_adj, 1);
    k_avg_scatter<<<gW_NZ, TPB>>>(ent_adj, ent_emb, 0);
    k_avg_scatter<<<gW_NZ, TPB>>>(rel_adj, rel_emb, 1);
    k_avg_div<<<gND, TPB>>>(0);
    k_avg_div<<<gND, TPB>>>(1);

    // GAT over entity features (channels 0,1) -> emb cols [0, 384)
    k_tanh_write<<<gND, TPB>>>(0, 0);
    for (int l = 0; l < 2; l++) {
        k_zero_fnew<<<gND, TPB>>>();
        k_edge_gat<<<gW_T, TPB>>>(adj, l);
        k_tanh_write<<<gND, TPB>>>(2, (l + 1) * DD);
    }
    // GAT over relation features (channels 2,3) -> emb cols [384, 768)
    k_tanh_write<<<gND, TPB>>>(1, 3 * DD);
    for (int l = 0; l < 2; l++) {
        k_zero_fnew<<<gND, TPB>>>();
        k_edge_gat<<<gW_T, TPB>>>(adj, 2 + l);
        k_tanh_write<<<gND, TPB>>>(2, (4 + l) * DD);
    }

    k_prep_pairs<<<(BB + TPB - 1) / TPB, TPB>>>(pairs);
    k_norms<<<(NN * 32 + TPB - 1) / TPB, TPB>>>();
    k_na<<<(2 * BB + TPB - 1) / TPB, TPB>>>();
    k_pos<<<(BB * 32 + TPB - 1) / TPB, TPB>>>();

    dim3 gg((NN + BN - 1) / BN, (2 * BB) / BM);
    k_gemm<<<gg, 256>>>();
    k_row_stats<<<2 * BB, 256>>>();
    k_final<<<1, 256>>>(out);
}

// round 6
// speedup vs baseline: 1.4613x; 1.4613x over previous
#include <cuda_runtime.h>
#include <math.h>

#define NN 30000
#define RR 1000
#define TT 300000
#define DD 128
#define BB 1024
#define NZ 600000
#define OUTD 768
#define GAMMA_C 3.0f

// ---------------- scratch (device globals) ----------------
__device__ float g_relhat[RR * DD];          // normalized rel_emb rows
__device__ float g_logit[4 * RR];            // attention logit per (channel, rel)
__device__ float g_m[4 * NN];                // segment max per (channel, row)
__device__ float g_s[4 * NN];                // segment expsum
__device__ float g_featE[(size_t)NN * DD];
__device__ float g_featR[(size_t)NN * DD];
__device__ float g_degE[NN];
__device__ float g_degR[NN];
__device__ float g_fcurE[(size_t)NN * DD];
__device__ float g_fcurR[(size_t)NN * DD];
__device__ float g_fnewE[(size_t)NN * DD];
__device__ float g_fnewR[(size_t)NN * DD];
__device__ float g_emb[(size_t)NN * OUTD];   // final concat embedding
__device__ float g_nb[NN];                   // ||emb_j||^2
__device__ int   g_idxA[2 * BB];
__device__ float g_na[2 * BB];
__device__ float g_pos[BB];
__device__ int   g_lp[BB];
__device__ int   g_rp[BB];
__device__ float g_S[(size_t)2 * BB * NN];   // loss matrix 2048 x 30000
__device__ double g_rsum[2 * BB];
__device__ double g_rsq[2 * BB];
__device__ float  g_rmax[2 * BB];
__device__ float g_lse[2 * BB];

__device__ __forceinline__ float warp_sum(float v) {
#pragma unroll
    for (int o = 16; o > 0; o >>= 1) v += __shfl_xor_sync(0xffffffffu, v, o);
    return v;
}

__device__ __forceinline__ void atomicMaxF(float* addr, float v) {
    if (v >= 0.f) atomicMax((int*)addr, __float_as_int(v));
    else          atomicMin((unsigned int*)addr, __float_as_uint(v));
}

__device__ __forceinline__ void redAdd4(float* addr, float4 v) {
    asm volatile("red.global.add.v4.f32 [%0], {%1, %2, %3, %4};"
                 :: "l"(addr), "f"(v.x), "f"(v.y), "f"(v.z), "f"(v.w) : "memory");
}

// ---------------- init ----------------
__global__ void k_init() {
    size_t gid = (size_t)blockIdx.x * blockDim.x + threadIdx.x;
    size_t stride = (size_t)gridDim.x * blockDim.x;
    for (size_t i = gid; i < (size_t)NN * DD; i += stride) { g_featE[i] = 0.f; g_featR[i] = 0.f; }
    for (size_t i = gid; i < NN; i += stride) { g_degE[i] = 0.f; g_degR[i] = 0.f; }
    for (size_t i = gid; i < 4 * (size_t)NN; i += stride) { g_m[i] = -3.0e38f; g_s[i] = 0.f; }
    for (size_t i = gid; i < 2 * BB; i += stride) { g_rsum[i] = 0.0; g_rsq[i] = 0.0; g_rmax[i] = -3.0e38f; }
}

// ---------------- relation prep: normalized rel rows + per-channel logits ----------------
__global__ void k_relprep(const float* __restrict__ rel_emb,
                          const float* __restrict__ attn_e,
                          const float* __restrict__ attn_r) {
    int gid = blockIdx.x * blockDim.x + threadIdx.x;
    int r = gid >> 5;
    if (r >= RR) return;
    int lane = gid & 31;
    int d = lane * 4;
    float4 u = *(const float4*)&rel_emb[(size_t)r * DD + d];
    float ss = u.x * u.x + u.y * u.y + u.z * u.z + u.w * u.w;
    ss = warp_sum(ss);
    float inv = 1.f / fmaxf(sqrtf(ss), 1e-12f);
    u.x *= inv; u.y *= inv; u.z *= inv; u.w *= inv;
    *(float4*)&g_relhat[r * DD + d] = u;
    const float* ks[4] = { attn_e, attn_e + DD, attn_r, attn_r + DD };
#pragma unroll
    for (int c = 0; c < 4; c++) {
        const float4 kk = *(const float4*)&ks[c][d];
        float dot = u.x * kk.x + u.y * kk.y + u.z * kk.z + u.w * kk.w;
        dot = warp_sum(dot);
        if (lane == 0) g_logit[c * RR + r] = dot;
    }
}

// ---------------- segment softmax (max then expsum) ----------------
__global__ void k_smax_max(const int* __restrict__ adj, const int* __restrict__ r_index) {
    int gid = blockIdx.x * blockDim.x + threadIdx.x;
    if (gid >= 4 * TT) return;
    int c = gid / TT, t = gid - c * TT;
    int row = adj[t];
    int rel = r_index[TT + t];
    atomicMaxF(&g_m[c * NN + row], g_logit[c * RR + rel]);
}
__global__ void k_smax_sum(const int* __restrict__ adj, const int* __restrict__ r_index) {
    int gid = blockIdx.x * blockDim.x + threadIdx.x;
    if (gid >= 4 * TT) return;
    int c = gid / TT, t = gid - c * TT;
    int row = adj[t];
    int rel = r_index[TT + t];
    float e = expf(g_logit[c * RR + rel] - g_m[c * NN + row]);
    atomicAdd(&g_s[c * NN + row], e);
}

// ---------------- neighbor-average features ----------------
__global__ void k_deg(const int* __restrict__ eadj, int which) {
    int e = blockIdx.x * blockDim.x + threadIdx.x;
    if (e >= NZ) return;
    float* deg = which ? g_degR : g_degE;
    atomicAdd(&deg[eadj[e]], 1.f);
}
__global__ void k_avg_scatter(const int* __restrict__ eadj,
                              const float* __restrict__ src, int which) {
    int gid = blockIdx.x * blockDim.x + threadIdx.x;
    int e = gid >> 5;
    if (e >= NZ) return;
    int d = (gid & 31) * 4;
    int row = eadj[e], col = eadj[NZ + e];
    float* feat = which ? g_featR : g_featE;
    const float4 v = *(const float4*)&src[(size_t)col * DD + d];
    redAdd4(&feat[(size_t)row * DD + d], v);
}
__global__ void k_avg_div(int which) {
    int idx = blockIdx.x * blockDim.x + threadIdx.x;
    if (idx >= NN * DD) return;
    float* feat = which ? g_featR : g_featE;
    const float* deg = which ? g_degR : g_degE;
    float dg = deg[idx / DD];
    if (dg > 0.f) feat[idx] /= dg;
}

// ---------------- GAT ----------------
// srcSel 0: tanh(featE/featR); srcSel 1: tanh(fnewE/fnewR). Writes fcur and emb columns.
__global__ void k_tanh2(int srcSel, int base) {
    int idx = blockIdx.x * blockDim.x + threadIdx.x;
    if (idx >= NN * DD) return;
    const float* sE = srcSel ? g_fnewE : g_featE;
    const float* sR = srcSel ? g_fnewR : g_featR;
    float vE = tanhf(sE[idx]);
    float vR = tanhf(sR[idx]);
    g_fcurE[idx] = vE;
    g_fcurR[idx] = vR;
    int n = idx / DD, d = idx - n * DD;
    g_emb[(size_t)n * OUTD + base + d] = vE;
    g_emb[(size_t)n * OUTD + 3 * DD + base + d] = vR;
}
__global__ void k_zero2() {
    int idx = blockIdx.x * blockDim.x + threadIdx.x;
    if (idx < NN * DD) { g_fnewE[idx] = 0.f; g_fnewR[idx] = 0.f; }
}
__global__ void k_edge_fused(const int* __restrict__ adj, const int* __restrict__ r_index, int l) {
    int gid = blockIdx.x * blockDim.x + threadIdx.x;
    int t = gid >> 5;
    if (t >= TT) return;
    int lane = gid & 31;
    int d = lane * 4;
    int row = __ldg(&adj[t]), col = __ldg(&adj[TT + t]), rel = __ldg(&r_index[TT + t]);
    float4 u  = *(const float4*)&g_relhat[rel * DD + d];
    float4 xE = *(const float4*)&g_fcurE[(size_t)col * DD + d];
    float4 xR = *(const float4*)&g_fcurR[(size_t)col * DD + d];
    float dE = warp_sum(xE.x * u.x + xE.y * u.y + xE.z * u.z + xE.w * u.w);
    float dR = warp_sum(xR.x * u.x + xR.y * u.y + xR.z * u.z + xR.w * u.w);
    int cE = l, cR = 2 + l;
    float wE = expf(g_logit[cE * RR + rel] - g_m[cE * NN + row]) / g_s[cE * NN + row];
    float wR = expf(g_logit[cR * RR + rel] - g_m[cR * NN + row]) / g_s[cR * NN + row];
    float sE = 2.f * dE, sR = 2.f * dR;
    float4 oE = make_float4(wE * (xE.x - sE * u.x), wE * (xE.y - sE * u.y),
                            wE * (xE.z - sE * u.z), wE * (xE.w - sE * u.w));
    float4 oR = make_float4(wR * (xR.x - sR * u.x), wR * (xR.y - sR * u.y),
                            wR * (xR.z - sR * u.z), wR * (xR.w - sR * u.w));
    redAdd4(&g_fnewE[(size_t)row * DD + d], oE);
    redAdd4(&g_fnewR[(size_t)row * DD + d], oR);
}

// ---------------- loss prep ----------------
__global__ void k_prep_pairs(const int* __restrict__ pairs) {
    int p = blockIdx.x * blockDim.x + threadIdx.x;
    if (p >= BB) return;
    int lp = pairs[2 * p], rp = pairs[2 * p + 1];
    g_lp[p] = lp; g_rp[p] = rp;
    g_idxA[p] = lp; g_idxA[BB + p] = rp;
}
__global__ void k_norms() {
    int gid = blockIdx.x * blockDim.x + threadIdx.x;
    int j = gid >> 5;
    if (j >= NN) return;
    int lane = gid & 31;
    const float* row = &g_emb[(size_t)j * OUTD];
    float ss = 0.f;
    for (int k = lane * 4; k < OUTD; k += 128) {
        float4 v = *(const float4*)&row[k];
        ss += v.x * v.x + v.y * v.y + v.z * v.z + v.w * v.w;
    }
    ss = warp_sum(ss);
    if (lane == 0) g_nb[j] = ss;
}
__global__ void k_na() {
    int i = blockIdx.x * blockDim.x + threadIdx.x;
    if (i >= 2 * BB) return;
    g_na[i] = g_nb[g_idxA[i]];
}
__global__ void k_pos() {
    int gid = blockIdx.x * blockDim.x + threadIdx.x;
    int p = gid >> 5;
    if (p >= BB) return;
    int lane = gid & 31;
    const float* a = &g_emb[(size_t)g_lp[p] * OUTD];
    const float* b = &g_emb[(size_t)g_rp[p] * OUTD];
    float ss = 0.f;
    for (int k = lane * 4; k < OUTD; k += 128) {
        float4 va = *(const float4*)&a[k];
        float4 vb = *(const float4*)&b[k];
        float dx = va.x - vb.x, dy = va.y - vb.y, dz = va.z - vb.z, dw = va.w - vb.w;
        ss += dx * dx + dy * dy + dz * dz + dw * dw;
    }
    ss = warp_sum(ss);
    if (lane == 0) g_pos[p] = ss;
}

// ---------------- GEMM (128x128x16, 8x8 micro) + loss assembly + fused row stats ----------------
#define GM 128
#define GN 128
#define GK 16
__global__ __launch_bounds__(256, 2) void k_gemm() {
    __shared__ float As[2][GK][GM];
    __shared__ float Bs[2][GK][GN];
    __shared__ int s_idx[GM];
    const int bm = blockIdx.x;           // m tile (16)
    const int bj = blockIdx.y;           // j tile (235)
    const int tid = threadIdx.x;
    const int tx = tid & 15, ty = tid >> 4;
    const int jbase = bj * GN;
    if (tid < GM) s_idx[tid] = g_idxA[bm * GM + tid];
    const int lr = tid >> 1;             // loader row 0..127
    const int lk = (tid & 1) * 8;        // loader k offset: 0 or 8 (8 floats)
    __syncthreads();
    const float* Arow = &g_emb[(size_t)s_idx[lr] * OUTD + lk];
    const int jrow = jbase + lr;
    const bool jvalid = (jrow < NN);
    const float* Brow = &g_emb[(size_t)(jvalid ? jrow : 0) * OUTD + lk];

    // prologue: tile 0 -> buf 0
    {
        float4 a0 = *(const float4*)(Arow);
        float4 a1 = *(const float4*)(Arow + 4);
        float4 b0 = make_float4(0, 0, 0, 0), b1 = make_float4(0, 0, 0, 0);
        if (jvalid) { b0 = *(const float4*)(Brow); b1 = *(const float4*)(Brow + 4); }
        As[0][lk + 0][lr] = a0.x; As[0][lk + 1][lr] = a0.y; As[0][lk + 2][lr] = a0.z; As[0][lk + 3][lr] = a0.w;
        As[0][lk + 4][lr] = a1.x; As[0][lk + 5][lr] = a1.y; As[0][lk + 6][lr] = a1.z; As[0][lk + 7][lr] = a1.w;
        Bs[0][lk + 0][lr] = b0.x; Bs[0][lk + 1][lr] = b0.y; Bs[0][lk + 2][lr] = b0.z; Bs[0][lk + 3][lr] = b0.w;
        Bs[0][lk + 4][lr] = b1.x; Bs[0][lk + 5][lr] = b1.y; Bs[0][lk + 6][lr] = b1.z; Bs[0][lk + 7][lr] = b1.w;
    }
    __syncthreads();

    float acc[8][8] = {};
    const int NT = OUTD / GK;  // 48
    int buf = 0;
    for (int it = 0; it < NT; it++) {
        float4 pa0, pa1, pb0, pb1;
        bool pre = (it + 1 < NT);
        if (pre) {
            int k0 = (it + 1) * GK;
            pa0 = *(const float4*)(Arow + k0);
            pa1 = *(const float4*)(Arow + k0 + 4);
            pb0 = make_float4(0, 0, 0, 0); pb1 = make_float4(0, 0, 0, 0);
            if (jvalid) { pb0 = *(const float4*)(Brow + k0); pb1 = *(const float4*)(Brow + k0 + 4); }
        }
#pragma unroll
        for (int k = 0; k < GK; k++) {
            float4 af0 = *(const float4*)&As[buf][k][ty * 8];
            float4 af1 = *(const float4*)&As[buf][k][ty * 8 + 4];
            float4 bf0 = *(const float4*)&Bs[buf][k][tx * 8];
            float4 bf1 = *(const float4*)&Bs[buf][k][tx * 8 + 4];
            float av[8] = { af0.x, af0.y, af0.z, af0.w, af1.x, af1.y, af1.z, af1.w };
            float bv[8] = { bf0.x, bf0.y, bf0.z, bf0.w, bf1.x, bf1.y, bf1.z, bf1.w };
#pragma unroll
            for (int u = 0; u < 8; u++)
#pragma unroll
                for (int v = 0; v < 8; v++) acc[u][v] += av[u] * bv[v];
        }
        if (pre) {
            int nb = buf ^ 1;
            As[nb][lk + 0][lr] = pa0.x; As[nb][lk + 1][lr] = pa0.y; As[nb][lk + 2][lr] = pa0.z; As[nb][lk + 3][lr] = pa0.w;
            As[nb][lk + 4][lr] = pa1.x; As[nb][lk + 5][lr] = pa1.y; As[nb][lk + 6][lr] = pa1.z; As[nb][lk + 7][lr] = pa1.w;
            Bs[nb][lk + 0][lr] = pb0.x; Bs[nb][lk + 1][lr] = pb0.y; Bs[nb][lk + 2][lr] = pb0.z; Bs[nb][lk + 3][lr] = pb0.w;
            Bs[nb][lk + 4][lr] = pb1.x; Bs[nb][lk + 5][lr] = pb1.y; Bs[nb][lk + 6][lr] = pb1.z; Bs[nb][lk + 7][lr] = pb1.w;
        }
        __syncthreads();
        buf ^= 1;
    }

    // epilogue
    const int jcol = jbase + tx * 8;
    const bool fullj = (jcol + 8 <= NN);
    float nbv[8];
    if (fullj) {
        float4 n0 = *(const float4*)&g_nb[jcol];
        float4 n1 = *(const float4*)&g_nb[jcol + 4];
        nbv[0] = n0.x; nbv[1] = n0.y; nbv[2] = n0.z; nbv[3] = n0.w;
        nbv[4] = n1.x; nbv[5] = n1.y; nbv[6] = n1.z; nbv[7] = n1.w;
    } else {
#pragma unroll
        for (int v = 0; v < 8; v++) nbv[v] = (jcol + v < NN) ? g_nb[jcol + v] : 0.f;
    }
#pragma unroll
    for (int u = 0; u < 8; u++) {
        int i = bm * GM + ty * 8 + u;
        int p = i & (BB - 1);
        float base = g_pos[p] - g_na[i] + GAMMA_C;
        int lp = g_lp[p], rp = g_rp[p];
        float s = 0.f, q = 0.f, mx = -3.0e38f;
        float vals[8];
#pragma unroll
        for (int v = 0; v < 8; v++) {
            int j = jcol + v;
            if (j < NN) {
                float val = base - nbv[v] + 2.f * acc[u][v];
                float mask = 1.f - (float)(j == lp) - (float)(j == rp);
                val *= mask;
                vals[v] = val;
                s += val; q += val * val; mx = fmaxf(mx, val);
            }
        }
        float* srow = &g_S[(size_t)i * NN + jcol];
        if (fullj) {
            *(float4*)srow = make_float4(vals[0], vals[1], vals[2], vals[3]);
            *(float4*)(srow + 4) = make_float4(vals[4], vals[5], vals[6], vals[7]);
        } else {
#pragma unroll
            for (int v = 0; v < 8; v++) if (jcol + v < NN) srow[v] = vals[v];
        }
#pragma unroll
        for (int o = 8; o > 0; o >>= 1) {
            s += __shfl_xor_sync(0xffffffffu, s, o);
            q += __shfl_xor_sync(0xffffffffu, q, o);
            mx = fmaxf(mx, __shfl_xor_sync(0xffffffffu, mx, o));
        }
        if (tx == 0) {
            atomicAdd(&g_rsum[i], (double)s);
            atomicAdd(&g_rsq[i], (double)q);
            atomicMaxF(&g_rmax[i], mx);
        }
    }
}

// ---------------- per-row logsumexp (stats precomputed) ----------------
__global__ void k_row_exp() {
    int i = blockIdx.x;
    int tid = threadIdx.x;
    double mu_d = g_rsum[i] / NN;
    double var = g_rsq[i] / NN - mu_d * mu_d;
    if (var < 0.0) var = 0.0;
    double sd = sqrt(var);
    float mu = (float)mu_d;
    float inv = (float)(20.0 / sd);
    float zmax = (float)((g_rmax[i] - mu_d) * (20.0 / sd)) + 8.f;
    const float* row = &g_S[(size_t)i * NN];
    double es = 0.0;
    for (int j = tid; j < NN; j += 256) {
        float z = (row[j] - mu) * inv + 8.f;
        es += (double)expf(z - zmax);
    }
    __shared__ double sh[256];
    sh[tid] = es;
    __syncthreads();
    for (int o = 128; o > 0; o >>= 1) {
        if (tid < o) sh[tid] += sh[tid + o];
        __syncthreads();
    }
    if (tid == 0) g_lse[i] = zmax + logf((float)sh[0]);
}

__global__ void k_final(float* out) {
    int tid = threadIdx.x;
    double acc = 0.0;
    for (int p = tid; p < BB; p += 256) acc += (double)g_lse[p] + (double)g_lse[BB + p];
    __shared__ double sh[256];
    sh[tid] = acc;
    __syncthreads();
    for (int o = 128; o > 0; o >>= 1) {
        if (tid < o) sh[tid] += sh[tid + o];
        __syncthreads();
    }
    if (tid == 0) out[0] = (float)(sh[0] / BB);
}

// ---------------- driver ----------------
extern "C" void kernel_launch(void* const* d_in, const int* in_sizes, int n_in,
                              void* d_out, int out_size) {
    const float* ent_emb = (const float*)d_in[0];
    const float* rel_emb = (const float*)d_in[1];
    const float* attn_e  = (const float*)d_in[2];
    const float* attn_r  = (const float*)d_in[3];
    const int* adj     = (const int*)d_in[5];
    const int* r_index = (const int*)d_in[6];
    const int* ent_adj = (const int*)d_in[7];
    const int* rel_adj = (const int*)d_in[8];
    const int* pairs   = (const int*)d_in[9];
    float* out = (float*)d_out;

    const int TPB = 256;
    const int gW_T  = (TT * 32 + TPB - 1) / TPB;
    const int gW_NZ = (NZ * 32 + TPB - 1) / TPB;
    const int gND   = (NN * DD + TPB - 1) / TPB;
    const int g4T   = (4 * TT + TPB - 1) / TPB;

    k_init<<<4096, TPB>>>();
    k_relprep<<<(RR * 32 + TPB - 1) / TPB, TPB>>>(rel_emb, attn_e, attn_r);
    k_smax_max<<<g4T, TPB>>>(adj, r_index);
    k_smax_sum<<<g4T, TPB>>>(adj, r_index);

    k_deg<<<(NZ + TPB - 1) / TPB, TPB>>>(ent_adj, 0);
    k_deg<<<(NZ + TPB - 1) / TPB, TPB>>>(rel_adj, 1);
    k_avg_scatter<<<gW_NZ, TPB>>>(ent_adj, ent_emb, 0);
    k_avg_scatter<<<gW_NZ, TPB>>>(rel_adj, rel_emb, 1);
    k_avg_div<<<gND, TPB>>>(0);
    k_avg_div<<<gND, TPB>>>(1);

    // GAT layers (ent + rel fused per layer)
    k_tanh2<<<gND, TPB>>>(0, 0);
    for (int l = 0; l < 2; l++) {
        k_zero2<<<gND, TPB>>>();
        k_edge_fused<<<gW_T, TPB>>>(adj, r_index, l);
        k_tanh2<<<gND, TPB>>>(1, (l + 1) * DD);
    }

    k_prep_pairs<<<(BB + TPB - 1) / TPB, TPB>>>(pairs);
    k_norms<<<(NN * 32 + TPB - 1) / TPB, TPB>>>();
    k_na<<<(2 * BB + TPB - 1) / TPB, TPB>>>();
    k_pos<<<(BB * 32 + TPB - 1) / TPB, TPB>>>();

    dim3 gg(2 * BB / GM, (NN + GN - 1) / GN);  // (16, 235), x = m (fast) for B reuse in-wave
    k_gemm<<<gg, 256>>>();
    k_row_exp<<<2 * BB, 256>>>();
    k_final<<<1, 256>>>(out);
}

// round 7
// speedup vs baseline: 1.7200x; 1.1770x over previous
#include <cuda_runtime.h>
#include <math.h>

#define NN 30000
#define RR 1000
#define TT 300000
#define DD 128
#define BB 1024
#define NZ 600000
#define OUTD 768
#define GAMMA_C 3.0f

typedef unsigned long long u64;

// ---------------- scratch (device globals) ----------------
__device__ float g_relhat[RR * DD];          // normalized rel_emb rows
__device__ float g_logit[4 * RR];            // attention logit per (channel, rel)
__device__ float g_m[4 * NN];                // segment max per (channel, row)
__device__ float g_s[4 * NN];                // segment expsum -> reciprocal after k_sinv
__device__ float g_featE[(size_t)NN * DD];
__device__ float g_featR[(size_t)NN * DD];
__device__ float g_degE[NN];
__device__ float g_degR[NN];
__device__ float g_fcurE[(size_t)NN * DD];
__device__ float g_fcurR[(size_t)NN * DD];
__device__ float g_fnewE[(size_t)NN * DD];
__device__ float g_fnewR[(size_t)NN * DD];
__device__ float g_emb[(size_t)NN * OUTD];   // final concat embedding
__device__ float g_nb[NN];                   // ||emb_j||^2
__device__ int   g_idxA[2 * BB];
__device__ float g_na[2 * BB];
__device__ float g_pos[BB];
__device__ int   g_lp[BB];
__device__ int   g_rp[BB];
__device__ float g_S[(size_t)2 * BB * NN];   // loss matrix 2048 x 30000
__device__ double g_rsum[2 * BB];
__device__ double g_rsq[2 * BB];
__device__ float  g_rmax[2 * BB];
__device__ float g_lse[2 * BB];

__device__ __forceinline__ float warp_sum(float v) {
#pragma unroll
    for (int o = 16; o > 0; o >>= 1) v += __shfl_xor_sync(0xffffffffu, v, o);
    return v;
}

__device__ __forceinline__ void atomicMaxF(float* addr, float v) {
    if (v >= 0.f) atomicMax((int*)addr, __float_as_int(v));
    else          atomicMin((unsigned int*)addr, __float_as_uint(v));
}

__device__ __forceinline__ void redAdd4(float* addr, float4 v) {
    asm volatile("red.global.add.v4.f32 [%0], {%1, %2, %3, %4};"
                 :: "l"(addr), "f"(v.x), "f"(v.y), "f"(v.z), "f"(v.w) : "memory");
}

// exp(x) for x <= ~0 via exp2 poly on the FMA pipe (no MUFU). ~1.5e-4 rel err.
__device__ __forceinline__ float fast_exp(float x) {
    float t = fmaxf(x * 1.4426950408889634f, -80.0f);
    float fl = floorf(t);
    float f = t - fl;
    float p = 0.0013333558f;
    p = fmaf(p, f, 0.0096181291f);
    p = fmaf(p, f, 0.0555041086f);
    p = fmaf(p, f, 0.2402264476f);
    p = fmaf(p, f, 0.6931471806f);
    p = fmaf(p, f, 1.0f);
    int i = (int)fl;
    return p * __int_as_float((i + 127) << 23);
}

// ---------------- init ----------------
__global__ void k_init() {
    size_t gid = (size_t)blockIdx.x * blockDim.x + threadIdx.x;
    size_t stride = (size_t)gridDim.x * blockDim.x;
    for (size_t i = gid; i < (size_t)NN * DD; i += stride) { g_featE[i] = 0.f; g_featR[i] = 0.f; }
    for (size_t i = gid; i < NN; i += stride) { g_degE[i] = 0.f; g_degR[i] = 0.f; }
    for (size_t i = gid; i < 4 * (size_t)NN; i += stride) { g_m[i] = -3.0e38f; g_s[i] = 0.f; }
    for (size_t i = gid; i < 2 * BB; i += stride) { g_rsum[i] = 0.0; g_rsq[i] = 0.0; g_rmax[i] = -3.0e38f; }
}

// ---------------- relation prep ----------------
__global__ void k_relprep(const float* __restrict__ rel_emb,
                          const float* __restrict__ attn_e,
                          const float* __restrict__ attn_r) {
    int gid = blockIdx.x * blockDim.x + threadIdx.x;
    int r = gid >> 5;
    if (r >= RR) return;
    int lane = gid & 31;
    int d = lane * 4;
    float4 u = *(const float4*)&rel_emb[(size_t)r * DD + d];
    float ss = u.x * u.x + u.y * u.y + u.z * u.z + u.w * u.w;
    ss = warp_sum(ss);
    float inv = 1.f / fmaxf(sqrtf(ss), 1e-12f);
    u.x *= inv; u.y *= inv; u.z *= inv; u.w *= inv;
    *(float4*)&g_relhat[r * DD + d] = u;
    const float* ks[4] = { attn_e, attn_e + DD, attn_r, attn_r + DD };
#pragma unroll
    for (int c = 0; c < 4; c++) {
        const float4 kk = *(const float4*)&ks[c][d];
        float dot = u.x * kk.x + u.y * kk.y + u.z * kk.z + u.w * kk.w;
        dot = warp_sum(dot);
        if (lane == 0) g_logit[c * RR + r] = dot;
    }
}

// ---------------- segment softmax ----------------
__global__ void k_smax_max(const int* __restrict__ adj, const int* __restrict__ r_index) {
    int gid = blockIdx.x * blockDim.x + threadIdx.x;
    if (gid >= 4 * TT) return;
    int c = gid / TT, t = gid - c * TT;
    int row = adj[t];
    int rel = r_index[TT + t];
    atomicMaxF(&g_m[c * NN + row], g_logit[c * RR + rel]);
}
__global__ void k_smax_sum(const int* __restrict__ adj, const int* __restrict__ r_index) {
    int gid = blockIdx.x * blockDim.x + threadIdx.x;
    if (gid >= 4 * TT) return;
    int c = gid / TT, t = gid - c * TT;
    int row = adj[t];
    int rel = r_index[TT + t];
    float e = fast_exp(g_logit[c * RR + rel] - g_m[c * NN + row]);
    atomicAdd(&g_s[c * NN + row], e);
}
__global__ void k_sinv() {
    int idx = blockIdx.x * blockDim.x + threadIdx.x;
    if (idx >= 4 * NN) return;
    float s = g_s[idx];
    g_s[idx] = (s > 0.f) ? 1.f / s : 0.f;
}

// ---------------- neighbor-average features ----------------
__global__ void k_deg(const int* __restrict__ eadj, int which) {
    int e = blockIdx.x * blockDim.x + threadIdx.x;
    if (e >= NZ) return;
    float* deg = which ? g_degR : g_degE;
    atomicAdd(&deg[eadj[e]], 1.f);
}
__global__ void k_avg_scatter(const int* __restrict__ eadj,
                              const float* __restrict__ src, int which) {
    int gid = blockIdx.x * blockDim.x + threadIdx.x;
    int e = gid >> 5;
    if (e >= NZ) return;
    int d = (gid & 31) * 4;
    int row = eadj[e], col = eadj[NZ + e];
    float* feat = which ? g_featR : g_featE;
    const float4 v = *(const float4*)&src[(size_t)col * DD + d];
    redAdd4(&feat[(size_t)row * DD + d], v);
}
__global__ void k_avg_div(int which) {
    int idx = blockIdx.x * blockDim.x + threadIdx.x;
    if (idx >= NN * DD) return;
    float* feat = which ? g_featR : g_featE;
    const float* deg = which ? g_degR : g_degE;
    float dg = deg[idx / DD];
    if (dg > 0.f) feat[idx] /= dg;
}

// ---------------- GAT ----------------
__global__ void k_tanh2(int srcSel, int base) {
    int idx = blockIdx.x * blockDim.x + threadIdx.x;
    if (idx >= NN * DD) return;
    const float* sE = srcSel ? g_fnewE : g_featE;
    const float* sR = srcSel ? g_fnewR : g_featR;
    float vE = tanhf(sE[idx]);
    float vR = tanhf(sR[idx]);
    g_fcurE[idx] = vE;
    g_fcurR[idx] = vR;
    int n = idx / DD, d = idx - n * DD;
    g_emb[(size_t)n * OUTD + base + d] = vE;
    g_emb[(size_t)n * OUTD + 3 * DD + base + d] = vR;
}
__global__ void k_zero2() {
    int idx = blockIdx.x * blockDim.x + threadIdx.x;
    if (idx < NN * DD) { g_fnewE[idx] = 0.f; g_fnewR[idx] = 0.f; }
}
__global__ void k_edge_fused(const int* __restrict__ adj, const int* __restrict__ r_index, int l) {
    int gid = blockIdx.x * blockDim.x + threadIdx.x;
    int t = gid >> 5;
    if (t >= TT) return;
    int lane = gid & 31;
    int d = lane * 4;
    int row = __ldg(&adj[t]), col = __ldg(&adj[TT + t]), rel = __ldg(&r_index[TT + t]);
    float4 u  = *(const float4*)&g_relhat[rel * DD + d];
    float4 xE = *(const float4*)&g_fcurE[(size_t)col * DD + d];
    float4 xR = *(const float4*)&g_fcurR[(size_t)col * DD + d];
    float dE = warp_sum(xE.x * u.x + xE.y * u.y + xE.z * u.z + xE.w * u.w);
    float dR = warp_sum(xR.x * u.x + xR.y * u.y + xR.z * u.z + xR.w * u.w);
    int cE = l, cR = 2 + l;
    float wE = fast_exp(g_logit[cE * RR + rel] - g_m[cE * NN + row]) * g_s[cE * NN + row];
    float wR = fast_exp(g_logit[cR * RR + rel] - g_m[cR * NN + row]) * g_s[cR * NN + row];
    float sE = 2.f * dE, sR = 2.f * dR;
    float4 oE = make_float4(wE * (xE.x - sE * u.x), wE * (xE.y - sE * u.y),
                            wE * (xE.z - sE * u.z), wE * (xE.w - sE * u.w));
    float4 oR = make_float4(wR * (xR.x - sR * u.x), wR * (xR.y - sR * u.y),
                            wR * (xR.z - sR * u.z), wR * (xR.w - sR * u.w));
    redAdd4(&g_fnewE[(size_t)row * DD + d], oE);
    redAdd4(&g_fnewR[(size_t)row * DD + d], oR);
}

// ---------------- loss prep ----------------
__global__ void k_prep_pairs(const int* __restrict__ pairs) {
    int p = blockIdx.x * blockDim.x + threadIdx.x;
    if (p >= BB) return;
    int lp = pairs[2 * p], rp = pairs[2 * p + 1];
    g_lp[p] = lp; g_rp[p] = rp;
    g_idxA[p] = lp; g_idxA[BB + p] = rp;
}
__global__ void k_norms() {
    int gid = blockIdx.x * blockDim.x + threadIdx.x;
    int j = gid >> 5;
    if (j >= NN) return;
    int lane = gid & 31;
    const float* row = &g_emb[(size_t)j * OUTD];
    float ss = 0.f;
    for (int k = lane * 4; k < OUTD; k += 128) {
        float4 v = *(const float4*)&row[k];
        ss += v.x * v.x + v.y * v.y + v.z * v.z + v.w * v.w;
    }
    ss = warp_sum(ss);
    if (lane == 0) g_nb[j] = ss;
}
__global__ void k_na() {
    int i = blockIdx.x * blockDim.x + threadIdx.x;
    if (i >= 2 * BB) return;
    g_na[i] = g_nb[g_idxA[i]];
}
__global__ void k_pos() {
    int gid = blockIdx.x * blockDim.x + threadIdx.x;
    int p = gid >> 5;
    if (p >= BB) return;
    int lane = gid & 31;
    const float* a = &g_emb[(size_t)g_lp[p] * OUTD];
    const float* b = &g_emb[(size_t)g_rp[p] * OUTD];
    float ss = 0.f;
    for (int k = lane * 4; k < OUTD; k += 128) {
        float4 va = *(const float4*)&a[k];
        float4 vb = *(const float4*)&b[k];
        float dx = va.x - vb.x, dy = va.y - vb.y, dz = va.z - vb.z, dw = va.w - vb.w;
        ss += dx * dx + dy * dy + dz * dz + dw * dw;
    }
    ss = warp_sum(ss);
    if (lane == 0) g_pos[p] = ss;
}

// ---------------- GEMM (128x128x16, 8x8 micro, packed f32x2 FMA) ----------------
#define GM 128
#define GN 128
#define GK 16
__global__ __launch_bounds__(256, 2) void k_gemm() {
    __shared__ __align__(16) float As[2][GK][GM];
    __shared__ __align__(16) float Bs[2][GK][GN];
    __shared__ int s_idx[GM];
    const int bm = blockIdx.x;           // m tile (16)
    const int bj = blockIdx.y;           // j tile (235)
    const int tid = threadIdx.x;
    const int tx = tid & 15, ty = tid >> 4;
    const int jbase = bj * GN;
    if (tid < GM) s_idx[tid] = g_idxA[bm * GM + tid];
    const int lr = tid >> 1;             // loader row 0..127
    const int lk = (tid & 1) * 8;        // loader k offset: 0 or 8
    __syncthreads();
    const float* Arow = &g_emb[(size_t)s_idx[lr] * OUTD + lk];
    const int jrow = jbase + lr;
    const bool jvalid = (jrow < NN);
    const float* Brow = &g_emb[(size_t)(jvalid ? jrow : 0) * OUTD + lk];

    // prologue: tile 0 -> buf 0
    {
        float4 a0 = *(const float4*)(Arow);
        float4 a1 = *(const float4*)(Arow + 4);
        float4 b0 = make_float4(0, 0, 0, 0), b1 = make_float4(0, 0, 0, 0);
        if (jvalid) { b0 = *(const float4*)(Brow); b1 = *(const float4*)(Brow + 4); }
        As[0][lk + 0][lr] = a0.x; As[0][lk + 1][lr] = a0.y; As[0][lk + 2][lr] = a0.z; As[0][lk + 3][lr] = a0.w;
        As[0][lk + 4][lr] = a1.x; As[0][lk + 5][lr] = a1.y; As[0][lk + 6][lr] = a1.z; As[0][lk + 7][lr] = a1.w;
        Bs[0][lk + 0][lr] = b0.x; Bs[0][lk + 1][lr] = b0.y; Bs[0][lk + 2][lr] = b0.z; Bs[0][lk + 3][lr] = b0.w;
        Bs[0][lk + 4][lr] = b1.x; Bs[0][lk + 5][lr] = b1.y; Bs[0][lk + 6][lr] = b1.z; Bs[0][lk + 7][lr] = b1.w;
    }
    __syncthreads();

    // packed accumulators: acc2[u2][v] holds rows (ty*8 + 2*u2, ty*8 + 2*u2+1) for column v
    u64 acc2[4][8] = {};
    const int NT = OUTD / GK;  // 48
    int buf = 0;
    for (int it = 0; it < NT; it++) {
        float4 pa0, pa1, pb0, pb1;
        bool pre = (it + 1 < NT);
        if (pre) {
            int k0 = (it + 1) * GK;
            pa0 = *(const float4*)(Arow + k0);
            pa1 = *(const float4*)(Arow + k0 + 4);
            pb0 = make_float4(0, 0, 0, 0); pb1 = make_float4(0, 0, 0, 0);
            if (jvalid) { pb0 = *(const float4*)(Brow + k0); pb1 = *(const float4*)(Brow + k0 + 4); }
        }
#pragma unroll
        for (int k = 0; k < GK; k++) {
            const u64* ap = (const u64*)&As[buf][k][ty * 8];
            u64 a2[4];
            a2[0] = ap[0]; a2[1] = ap[1]; a2[2] = ap[2]; a2[3] = ap[3];
            float4 bf0 = *(const float4*)&Bs[buf][k][tx * 8];
            float4 bf1 = *(const float4*)&Bs[buf][k][tx * 8 + 4];
            float bv[8] = { bf0.x, bf0.y, bf0.z, bf0.w, bf1.x, bf1.y, bf1.z, bf1.w };
#pragma unroll
            for (int v = 0; v < 8; v++) {
                u64 bb;
                asm("mov.b64 %0, {%1, %1};" : "=l"(bb) : "f"(bv[v]));
#pragma unroll
                for (int u2 = 0; u2 < 4; u2++) {
                    asm("fma.rn.f32x2 %0, %1, %2, %0;" : "+l"(acc2[u2][v]) : "l"(a2[u2]), "l"(bb));
                }
            }
        }
        if (pre) {
            int nb = buf ^ 1;
            As[nb][lk + 0][lr] = pa0.x; As[nb][lk + 1][lr] = pa0.y; As[nb][lk + 2][lr] = pa0.z; As[nb][lk + 3][lr] = pa0.w;
            As[nb][lk + 4][lr] = pa1.x; As[nb][lk + 5][lr] = pa1.y; As[nb][lk + 6][lr] = pa1.z; As[nb][lk + 7][lr] = pa1.w;
            Bs[nb][lk + 0][lr] = pb0.x; Bs[nb][lk + 1][lr] = pb0.y; Bs[nb][lk + 2][lr] = pb0.z; Bs[nb][lk + 3][lr] = pb0.w;
            Bs[nb][lk + 4][lr] = pb1.x; Bs[nb][lk + 5][lr] = pb1.y; Bs[nb][lk + 6][lr] = pb1.z; Bs[nb][lk + 7][lr] = pb1.w;
        }
        __syncthreads();
        buf ^= 1;
    }

    // epilogue
    const int jcol = jbase + tx * 8;
    const bool fullj = (jcol + 8 <= NN);
    float nbv[8];
    if (fullj) {
        float4 n0 = *(const float4*)&g_nb[jcol];
        float4 n1 = *(const float4*)&g_nb[jcol + 4];
        nbv[0] = n0.x; nbv[1] = n0.y; nbv[2] = n0.z; nbv[3] = n0.w;
        nbv[4] = n1.x; nbv[5] = n1.y; nbv[6] = n1.z; nbv[7] = n1.w;
    } else {
#pragma unroll
        for (int v = 0; v < 8; v++) nbv[v] = (jcol + v < NN) ? g_nb[jcol + v] : 0.f;
    }
#pragma unroll
    for (int u2 = 0; u2 < 4; u2++) {
#pragma unroll
        for (int h = 0; h < 2; h++) {
            int u = u2 * 2 + h;
            int i = bm * GM + ty * 8 + u;
            int p = i & (BB - 1);
            float base = g_pos[p] - g_na[i] + GAMMA_C;
            int lp = g_lp[p], rp = g_rp[p];
            float s = 0.f, q = 0.f, mx = -3.0e38f;
            float vals[8];
#pragma unroll
            for (int v = 0; v < 8; v++) {
                int j = jcol + v;
                if (j < NN) {
                    float2 pr = *(float2*)&acc2[u2][v];
                    float accv = h ? pr.y : pr.x;
                    float val = base - nbv[v] + 2.f * accv;
                    float mask = 1.f - (float)(j == lp) - (float)(j == rp);
                    val *= mask;
                    vals[v] = val;
                    s += val; q += val * val; mx = fmaxf(mx, val);
                }
            }
            float* srow = &g_S[(size_t)i * NN + jcol];
            if (fullj) {
                *(float4*)srow = make_float4(vals[0], vals[1], vals[2], vals[3]);
                *(float4*)(srow + 4) = make_float4(vals[4], vals[5], vals[6], vals[7]);
            } else {
#pragma unroll
                for (int v = 0; v < 8; v++) if (jcol + v < NN) srow[v] = vals[v];
            }
#pragma unroll
            for (int o = 8; o > 0; o >>= 1) {
                s += __shfl_xor_sync(0xffffffffu, s, o);
                q += __shfl_xor_sync(0xffffffffu, q, o);
                mx = fmaxf(mx, __shfl_xor_sync(0xffffffffu, mx, o));
            }
            if (tx == 0) {
                atomicAdd(&g_rsum[i], (double)s);
                atomicAdd(&g_rsq[i], (double)q);
                atomicMaxF(&g_rmax[i], mx);
            }
        }
    }
}

// ---------------- per-row logsumexp (stats precomputed) ----------------
__global__ void k_row_exp() {
    int i = blockIdx.x;
    int tid = threadIdx.x;
    double mu_d = g_rsum[i] / NN;
    double var = g_rsq[i] / NN - mu_d * mu_d;
    if (var < 0.0) var = 0.0;
    double sd = sqrt(var);
    float mu = (float)mu_d;
    float inv = (float)(20.0 / sd);
    float zmax = (float)((g_rmax[i] - mu_d) * (20.0 / sd)) + 8.f;
    const float* row = &g_S[(size_t)i * NN];
    float cterm = 8.f - zmax - mu * inv;  // arg = x*inv + cterm <= ~0
    float es = 0.f;
    for (int j = tid; j < NN; j += 256) {
        es += fast_exp(fmaf(row[j], inv, cterm));
    }
    __shared__ float sh[256];
    sh[tid] = es;
    __syncthreads();
    for (int o = 128; o > 0; o >>= 1) {
        if (tid < o) sh[tid] += sh[tid + o];
        __syncthreads();
    }
    if (tid == 0) g_lse[i] = zmax + logf(sh[0]);
}

__global__ void k_final(float* out) {
    int tid = threadIdx.x;
    double acc = 0.0;
    for (int p = tid; p < BB; p += 256) acc += (double)g_lse[p] + (double)g_lse[BB + p];
    __shared__ double sh[256];
    sh[tid] = acc;
    __syncthreads();
    for (int o = 128; o > 0; o >>= 1) {
        if (tid < o) sh[tid] += sh[tid + o];
        __syncthreads();
    }
    if (tid == 0) out[0] = (float)(sh[0] / BB);
}

// ---------------- driver ----------------
extern "C" void kernel_launch(void* const* d_in, const int* in_sizes, int n_in,
                              void* d_out, int out_size) {
    const float* ent_emb = (const float*)d_in[0];
    const float* rel_emb = (const float*)d_in[1];
    const float* attn_e  = (const float*)d_in[2];
    const float* attn_r  = (const float*)d_in[3];
    const int* adj     = (const int*)d_in[5];
    const int* r_index = (const int*)d_in[6];
    const int* ent_adj = (const int*)d_in[7];
    const int* rel_adj = (const int*)d_in[8];
    const int* pairs   = (const int*)d_in[9];
    float* out = (float*)d_out;

    const int TPB = 256;
    const int gW_T  = (TT * 32 + TPB - 1) / TPB;
    const int gW_NZ = (NZ * 32 + TPB - 1) / TPB;
    const int gND   = (NN * DD + TPB - 1) / TPB;
    const int g4T   = (4 * TT + TPB - 1) / TPB;

    k_init<<<4096, TPB>>>();
    k_relprep<<<(RR * 32 + TPB - 1) / TPB, TPB>>>(rel_emb, attn_e, attn_r);
    k_smax_max<<<g4T, TPB>>>(adj, r_index);
    k_smax_sum<<<g4T, TPB>>>(adj, r_index);
    k_sinv<<<(4 * NN + TPB - 1) / TPB, TPB>>>();

    k_deg<<<(NZ + TPB - 1) / TPB, TPB>>>(ent_adj, 0);
    k_deg<<<(NZ + TPB - 1) / TPB, TPB>>>(rel_adj, 1);
    k_avg_scatter<<<gW_NZ, TPB>>>(ent_adj, ent_emb, 0);
    k_avg_scatter<<<gW_NZ, TPB>>>(rel_adj, rel_emb, 1);
    k_avg_div<<<gND, TPB>>>(0);
    k_avg_div<<<gND, TPB>>>(1);

    // GAT layers (ent + rel fused per layer)
    k_tanh2<<<gND, TPB>>>(0, 0);
    for (int l = 0; l < 2; l++) {
        k_zero2<<<gND, TPB>>>();
        k_edge_fused<<<gW_T, TPB>>>(adj, r_index, l);
        k_tanh2<<<gND, TPB>>>(1, (l + 1) * DD);
    }

    k_prep_pairs<<<(BB + TPB - 1) / TPB, TPB>>>(pairs);
    k_norms<<<(NN * 32 + TPB - 1) / TPB, TPB>>>();
    k_na<<<(2 * BB + TPB - 1) / TPB, TPB>>>();
    k_pos<<<(BB * 32 + TPB - 1) / TPB, TPB>>>();

    dim3 gg(2 * BB / GM, (NN + GN - 1) / GN);
    k_gemm<<<gg, 256>>>();
    k_row_exp<<<2 * BB, 256>>>();
    k_final<<<1, 256>>>(out);
}

// round 9
// speedup vs baseline: 2.8050x; 1.6308x over previous
#include <cuda_runtime.h>
#include <cuda_bf16.h>
#include <math.h>
#include <stdint.h>

#define NN 30000
#define RR 1000
#define TT 300000
#define DD 128
#define BB 1024
#define NZ 600000
#define OUTD 768
#define GAMMA_C 3.0f

typedef unsigned long long u64;

// ---------------- scratch (device globals) ----------------
__device__ float g_relhat[RR * DD];
__device__ float g_logit[4 * RR];
__device__ float g_m[4 * NN];
__device__ float g_s[4 * NN];                // expsum -> reciprocal after k_sinv
__device__ float g_featE[(size_t)NN * DD];
__device__ float g_featR[(size_t)NN * DD];
__device__ float g_degE[NN];
__device__ float g_degR[NN];
__device__ float g_fcurE[(size_t)NN * DD];
__device__ float g_fcurR[(size_t)NN * DD];
__device__ float g_fnewE[(size_t)NN * DD];
__device__ float g_fnewR[(size_t)NN * DD];
__device__ float g_emb[(size_t)NN * OUTD];
__device__ __nv_bfloat16 g_embH16[(size_t)NN * OUTD];   // bf16 high part
__device__ __nv_bfloat16 g_embL16[(size_t)NN * OUTD];   // bf16 residual
__device__ float g_nb[NN];
__device__ int   g_idxA[2 * BB];
__device__ float g_na[2 * BB];
__device__ float g_pos[BB];
__device__ int   g_lp[BB];
__device__ int   g_rp[BB];
__device__ float g_S[(size_t)2 * BB * NN];
__device__ double g_rsum[2 * BB];
__device__ double g_rsq[2 * BB];
__device__ float  g_rmax[2 * BB];
__device__ float g_lse[2 * BB];

__device__ __forceinline__ float warp_sum(float v) {
#pragma unroll
    for (int o = 16; o > 0; o >>= 1) v += __shfl_xor_sync(0xffffffffu, v, o);
    return v;
}
__device__ __forceinline__ void atomicMaxF(float* addr, float v) {
    if (v >= 0.f) atomicMax((int*)addr, __float_as_int(v));
    else          atomicMin((unsigned int*)addr, __float_as_uint(v));
}
__device__ __forceinline__ void redAdd4(float* addr, float4 v) {
    asm volatile("red.global.add.v4.f32 [%0], {%1, %2, %3, %4};"
                 :: "l"(addr), "f"(v.x), "f"(v.y), "f"(v.z), "f"(v.w) : "memory");
}
__device__ __forceinline__ float fast_exp(float x) {
    float t = fmaxf(x * 1.4426950408889634f, -80.0f);
    float fl = floorf(t);
    float f = t - fl;
    float p = 0.0013333558f;
    p = fmaf(p, f, 0.0096181291f);
    p = fmaf(p, f, 0.0555041086f);
    p = fmaf(p, f, 0.2402264476f);
    p = fmaf(p, f, 0.6931471806f);
    p = fmaf(p, f, 1.0f);
    int i = (int)fl;
    return p * __int_as_float((i + 127) << 23);
}
__device__ __forceinline__ uint32_t smem_u32(const void* p) {
    uint32_t a;
    asm("{ .reg .u64 t; cvta.to.shared.u64 t, %1; cvt.u32.u64 %0, t; }" : "=r"(a) : "l"(p));
    return a;
}
__device__ __forceinline__ void cpasync16(uint32_t dst, const void* src) {
    asm volatile("cp.async.cg.shared.global [%0], [%1], 16;" :: "r"(dst), "l"(src));
}
__device__ __forceinline__ void ldsm4(uint32_t* r, uint32_t addr) {
    asm volatile("ldmatrix.sync.aligned.m8n8.x4.shared.b16 {%0,%1,%2,%3}, [%4];"
                 : "=r"(r[0]), "=r"(r[1]), "=r"(r[2]), "=r"(r[3]) : "r"(addr));
}
__device__ __forceinline__ void mma_bf16(float* c, const uint32_t* a, const uint32_t* b) {
    asm volatile("mma.sync.aligned.m16n8k16.row.col.f32.bf16.bf16.f32 "
                 "{%0,%1,%2,%3}, {%4,%5,%6,%7}, {%8,%9}, {%0,%1,%2,%3};"
                 : "+f"(c[0]), "+f"(c[1]), "+f"(c[2]), "+f"(c[3])
                 : "r"(a[0]), "r"(a[1]), "r"(a[2]), "r"(a[3]), "r"(b[0]), "r"(b[1]));
}

// ---------------- init ----------------
__global__ void k_init() {
    size_t gid = (size_t)blockIdx.x * blockDim.x + threadIdx.x;
    size_t stride = (size_t)gridDim.x * blockDim.x;
    for (size_t i = gid; i < (size_t)NN * DD; i += stride) { g_featE[i] = 0.f; g_featR[i] = 0.f; }
    for (size_t i = gid; i < NN; i += stride) { g_degE[i] = 0.f; g_degR[i] = 0.f; }
    for (size_t i = gid; i < 4 * (size_t)NN; i += stride) { g_m[i] = -3.0e38f; g_s[i] = 0.f; }
    for (size_t i = gid; i < 2 * BB; i += stride) { g_rsum[i] = 0.0; g_rsq[i] = 0.0; g_rmax[i] = -3.0e38f; }
}

// ---------------- relation prep ----------------
__global__ void k_relprep(const float* __restrict__ rel_emb,
                          const float* __restrict__ attn_e,
                          const float* __restrict__ attn_r) {
    int gid = blockIdx.x * blockDim.x + threadIdx.x;
    int r = gid >> 5;
    if (r >= RR) return;
    int lane = gid & 31;
    int d = lane * 4;
    float4 u = *(const float4*)&rel_emb[(size_t)r * DD + d];
    float ss = u.x * u.x + u.y * u.y + u.z * u.z + u.w * u.w;
    ss = warp_sum(ss);
    float inv = 1.f / fmaxf(sqrtf(ss), 1e-12f);
    u.x *= inv; u.y *= inv; u.z *= inv; u.w *= inv;
    *(float4*)&g_relhat[r * DD + d] = u;
    const float* ks[4] = { attn_e, attn_e + DD, attn_r, attn_r + DD };
#pragma unroll
    for (int c = 0; c < 4; c++) {
        const float4 kk = *(const float4*)&ks[c][d];
        float dot = u.x * kk.x + u.y * kk.y + u.z * kk.z + u.w * kk.w;
        dot = warp_sum(dot);
        if (lane == 0) g_logit[c * RR + r] = dot;
    }
}

// ---------------- segment softmax ----------------
__global__ void k_smax_max(const int* __restrict__ adj, const int* __restrict__ r_index) {
    int t = blockIdx.x * blockDim.x + threadIdx.x;
    if (t >= TT) return;
    int row = adj[t], rel = r_index[TT + t];
#pragma unroll
    for (int c = 0; c < 4; c++) atomicMaxF(&g_m[c * NN + row], g_logit[c * RR + rel]);
}
__global__ void k_smax_sum(const int* __restrict__ adj, const int* __restrict__ r_index) {
    int t = blockIdx.x * blockDim.x + threadIdx.x;
    if (t >= TT) return;
    int row = adj[t], rel = r_index[TT + t];
#pragma unroll
    for (int c = 0; c < 4; c++)
        atomicAdd(&g_s[c * NN + row], fast_exp(g_logit[c * RR + rel] - g_m[c * NN + row]));
}
__global__ void k_sinv() {
    int idx = blockIdx.x * blockDim.x + threadIdx.x;
    if (idx >= 4 * NN) return;
    float s = g_s[idx];
    g_s[idx] = (s > 0.f) ? 1.f / s : 0.f;
}

// ---------------- neighbor-average features ----------------
__global__ void k_deg(const int* __restrict__ eadj, int which) {
    int e = blockIdx.x * blockDim.x + threadIdx.x;
    if (e >= NZ) return;
    float* deg = which ? g_degR : g_degE;
    atomicAdd(&deg[eadj[e]], 1.f);
}
__global__ void k_avg_scatter(const int* __restrict__ eadj,
                              const float* __restrict__ src, int which) {
    int gid = blockIdx.x * blockDim.x + threadIdx.x;
    int e = gid >> 5;
    if (e >= NZ) return;
    int d = (gid & 31) * 4;
    int row = eadj[e], col = eadj[NZ + e];
    float* feat = which ? g_featR : g_featE;
    const float4 v = *(const float4*)&src[(size_t)col * DD + d];
    redAdd4(&feat[(size_t)row * DD + d], v);
}
__global__ void k_avg_div(int which) {
    int idx = blockIdx.x * blockDim.x + threadIdx.x;
    if (idx >= NN * DD) return;
    float* feat = which ? g_featR : g_featE;
    const float* deg = which ? g_degR : g_degE;
    float dg = deg[idx / DD];
    if (dg > 0.f) feat[idx] /= dg;
}

// ---------------- GAT ----------------
__global__ void k_tanh2(int srcSel, int base) {
    int idx = blockIdx.x * blockDim.x + threadIdx.x;
    if (idx >= NN * DD) return;
    const float* sE = srcSel ? g_fnewE : g_featE;
    const float* sR = srcSel ? g_fnewR : g_featR;
    float vE = tanhf(sE[idx]);
    float vR = tanhf(sR[idx]);
    g_fcurE[idx] = vE;
    g_fcurR[idx] = vR;
    int n = idx / DD, d = idx - n * DD;
    g_emb[(size_t)n * OUTD + base + d] = vE;
    g_emb[(size_t)n * OUTD + 3 * DD + base + d] = vR;
}
__global__ void k_zero2() {
    int idx = blockIdx.x * blockDim.x + threadIdx.x;
    if (idx < NN * DD) { g_fnewE[idx] = 0.f; g_fnewR[idx] = 0.f; }
}
__global__ void k_edge_fused(const int* __restrict__ adj, const int* __restrict__ r_index, int l) {
    int gid = blockIdx.x * blockDim.x + threadIdx.x;
    int t = gid >> 5;
    if (t >= TT) return;
    int lane = gid & 31;
    int d = lane * 4;
    int row = __ldg(&adj[t]), col = __ldg(&adj[TT + t]), rel = __ldg(&r_index[TT + t]);
    float4 u  = *(const float4*)&g_relhat[rel * DD + d];
    float4 xE = *(const float4*)&g_fcurE[(size_t)col * DD + d];
    float4 xR = *(const float4*)&g_fcurR[(size_t)col * DD + d];
    float dE = warp_sum(xE.x * u.x + xE.y * u.y + xE.z * u.z + xE.w * u.w);
    float dR = warp_sum(xR.x * u.x + xR.y * u.y + xR.z * u.z + xR.w * u.w);
    int cE = l, cR = 2 + l;
    float wE = fast_exp(g_logit[cE * RR + rel] - g_m[cE * NN + row]) * g_s[cE * NN + row];
    float wR = fast_exp(g_logit[cR * RR + rel] - g_m[cR * NN + row]) * g_s[cR * NN + row];
    float sE = 2.f * dE, sR = 2.f * dR;
    float4 oE = make_float4(wE * (xE.x - sE * u.x), wE * (xE.y - sE * u.y),
                            wE * (xE.z - sE * u.z), wE * (xE.w - sE * u.w));
    float4 oR = make_float4(wR * (xR.x - sR * u.x), wR * (xR.y - sR * u.y),
                            wR * (xR.z - sR * u.z), wR * (xR.w - sR * u.w));
    redAdd4(&g_fnewE[(size_t)row * DD + d], oE);
    redAdd4(&g_fnewR[(size_t)row * DD + d], oR);
}

// ---------------- split emb into bf16 hi/lo ----------------
__global__ void k_split() {
    size_t i4 = (size_t)blockIdx.x * blockDim.x + threadIdx.x;
    if (i4 >= (size_t)NN * OUTD / 4) return;
    float4 x = *(const float4*)&g_emb[i4 * 4];
    __nv_bfloat16 h0 = __float2bfloat16(x.x);
    __nv_bfloat16 h1 = __float2bfloat16(x.y);
    __nv_bfloat16 h2 = __float2bfloat16(x.z);
    __nv_bfloat16 h3 = __float2bfloat16(x.w);
    __nv_bfloat16 l0 = __float2bfloat16(x.x - __bfloat162float(h0));
    __nv_bfloat16 l1 = __float2bfloat16(x.y - __bfloat162float(h1));
    __nv_bfloat16 l2 = __float2bfloat16(x.z - __bfloat162float(h2));
    __nv_bfloat16 l3 = __float2bfloat16(x.w - __bfloat162float(h3));
    __nv_bfloat162 hA = { h0, h1 }, hB = { h2, h3 };
    __nv_bfloat162 lA = { l0, l1 }, lB = { l2, l3 };
    *(uint2*)&g_embH16[i4 * 4] = make_uint2(*(uint32_t*)&hA, *(uint32_t*)&hB);
    *(uint2*)&g_embL16[i4 * 4] = make_uint2(*(uint32_t*)&lA, *(uint32_t*)&lB);
}

// ---------------- loss prep ----------------
__global__ void k_prep_pairs(const int* __restrict__ pairs) {
    int p = blockIdx.x * blockDim.x + threadIdx.x;
    if (p >= BB) return;
    int lp = pairs[2 * p], rp = pairs[2 * p + 1];
    g_lp[p] = lp; g_rp[p] = rp;
    g_idxA[p] = lp; g_idxA[BB + p] = rp;
}
__global__ void k_norms() {
    int gid = blockIdx.x * blockDim.x + threadIdx.x;
    int j = gid >> 5;
    if (j >= NN) return;
    int lane = gid & 31;
    const float* row = &g_emb[(size_t)j * OUTD];
    float ss = 0.f;
    for (int k = lane * 4; k < OUTD; k += 128) {
        float4 v = *(const float4*)&row[k];
        ss += v.x * v.x + v.y * v.y + v.z * v.z + v.w * v.w;
    }
    ss = warp_sum(ss);
    if (lane == 0) g_nb[j] = ss;
}
__global__ void k_na() {
    int i = blockIdx.x * blockDim.x + threadIdx.x;
    if (i >= 2 * BB) return;
    g_na[i] = g_nb[g_idxA[i]];
}
__global__ void k_pos() {
    int gid = blockIdx.x * blockDim.x + threadIdx.x;
    int p = gid >> 5;
    if (p >= BB) return;
    int lane = gid & 31;
    const float* a = &g_emb[(size_t)g_lp[p] * OUTD];
    const float* b = &g_emb[(size_t)g_rp[p] * OUTD];
    float ss = 0.f;
    for (int k = lane * 4; k < OUTD; k += 128) {
        float4 va = *(const float4*)&a[k];
        float4 vb = *(const float4*)&b[k];
        float dx = va.x - vb.x, dy = va.y - vb.y, dz = va.z - vb.z, dw = va.w - vb.w;
        ss += dx * dx + dy * dy + dz * dz + dw * dw;
    }
    ss = warp_sum(ss);
    if (lane == 0) g_pos[p] = ss;
}

// ---------------- mma.sync bf16x3 GEMM (128x128) + loss + stats ----------------
#define JT 128
#define NS (OUTD / 16)         // 48 k-stages
#define ROWB 48                // padded smem row bytes (16 bf16 = 32B used)
#define AH_O 0
#define AL_O 6144
#define BH_O 12288
#define BL_O 18432
#define STGB 24576             // bytes per stage

__global__ __launch_bounds__(256, 1) void k_gemm_mma() {
    extern __shared__ char dynsmem[];
    __shared__ int s_idx[128];
    const int tid = threadIdx.x;
    const int wid = tid >> 5;
    const int lane = tid & 31;
    const int warp_m = wid & 1;      // 2 warps in m (64 rows each)
    const int warp_n = wid >> 1;     // 4 warps in n (32 cols each)
    const int bm = blockIdx.x;
    const int jbase = blockIdx.y * JT;
    const uint32_t sbase = smem_u32(dynsmem);

    if (tid < 128) s_idx[tid] = g_idxA[bm * 128 + tid];
    __syncthreads();

    const int lrow = tid >> 1;       // loader row 0..127
    const int lhalf = tid & 1;       // 16B chunk
    int jld = jbase + lrow;
    if (jld >= NN) jld = 0;
    const size_t gaBase = (size_t)s_idx[lrow] * OUTD + lhalf * 8;
    const size_t gbBase = (size_t)jld * OUTD + lhalf * 8;
    const uint32_t dA = lrow * ROWB + lhalf * 16;

    // prologue: stage 0
    {
        uint32_t sb = sbase;
        cpasync16(sb + AH_O + dA, g_embH16 + gaBase);
        cpasync16(sb + AL_O + dA, g_embL16 + gaBase);
        cpasync16(sb + BH_O + dA, g_embH16 + gbBase);
        cpasync16(sb + BL_O + dA, g_embL16 + gbBase);
        asm volatile("cp.async.commit_group;" ::: "memory");
    }

    float acc[4][4][4] = {};
    const int rsel = lane & 15;
    const int csel = (lane >> 4) * 16;

    for (int it = 0; it < NS; it++) {
        if (it + 1 < NS) {
            uint32_t sb = sbase + ((it + 1) & 1) * STGB;
            int k0 = (it + 1) * 16;
            cpasync16(sb + AH_O + dA, g_embH16 + gaBase + k0);
            cpasync16(sb + AL_O + dA, g_embL16 + gaBase + k0);
            cpasync16(sb + BH_O + dA, g_embH16 + gbBase + k0);
            cpasync16(sb + BL_O + dA, g_embL16 + gbBase + k0);
            asm volatile("cp.async.commit_group;" ::: "memory");
            asm volatile("cp.async.wait_group 1;" ::: "memory");
        } else {
            asm volatile("cp.async.wait_group 0;" ::: "memory");
        }
        __syncthreads();

        const uint32_t sb = sbase + (it & 1) * STGB;
        uint32_t aH[4][4], aL[4][4], bH[4][2], bL[4][2];
#pragma unroll
        for (int mt = 0; mt < 4; mt++) {
            uint32_t ad = sb + AH_O + (uint32_t)((warp_m * 64 + mt * 16 + rsel) * ROWB + csel);
            ldsm4(aH[mt], ad);
            ldsm4(aL[mt], ad + (AL_O - AH_O));
        }
#pragma unroll
        for (int tp = 0; tp < 2; tp++) {
            uint32_t bd = sb + BH_O + (uint32_t)((warp_n * 32 + tp * 16 + rsel) * ROWB + csel);
            uint32_t r[4];
            ldsm4(r, bd);
            bH[tp * 2][0] = r[0]; bH[tp * 2][1] = r[2];
            bH[tp * 2 + 1][0] = r[1]; bH[tp * 2 + 1][1] = r[3];
            ldsm4(r, bd + (BL_O - BH_O));
            bL[tp * 2][0] = r[0]; bL[tp * 2][1] = r[2];
            bL[tp * 2 + 1][0] = r[1]; bL[tp * 2 + 1][1] = r[3];
        }
#pragma unroll
        for (int mt = 0; mt < 4; mt++) {
#pragma unroll
            for (int nt = 0; nt < 4; nt++) {
                mma_bf16(acc[mt][nt], aH[mt], bH[nt]);
                mma_bf16(acc[mt][nt], aH[mt], bL[nt]);
                mma_bf16(acc[mt][nt], aL[mt], bH[nt]);
            }
        }
        __syncthreads();
    }

    // ---------------- epilogue: loss assembly + fused row stats ----------------
    const int lq = lane >> 2;    // row-in-8
    const int lr = lane & 3;     // col quad
    float2 nbv[4];
#pragma unroll
    for (int nt = 0; nt < 4; nt++) {
        int j0 = jbase + warp_n * 32 + nt * 8 + 2 * lr;
        nbv[nt].x = (j0 < NN) ? g_nb[j0] : 0.f;
        nbv[nt].y = (j0 + 1 < NN) ? g_nb[j0 + 1] : 0.f;
    }
#pragma unroll
    for (int mt = 0; mt < 4; mt++) {
#pragma unroll
        for (int h = 0; h < 2; h++) {
            const int i = bm * 128 + warp_m * 64 + mt * 16 + lq + h * 8;
            const int p = i & (BB - 1);
            const float base = g_pos[p] - g_na[i] + GAMMA_C;
            const int lp = g_lp[p], rp = g_rp[p];
            float s = 0.f, q = 0.f, mx = -3.0e38f;
            float* srow = &g_S[(size_t)i * NN];
#pragma unroll
            for (int nt = 0; nt < 4; nt++) {
                int j0 = jbase + warp_n * 32 + nt * 8 + 2 * lr;
                float c0 = acc[mt][nt][h * 2 + 0];
                float c1 = acc[mt][nt][h * 2 + 1];
                if (j0 + 1 < NN) {
                    float v0 = (base - nbv[nt].x + 2.f * c0) *
                               (1.f - (float)(j0 == lp) - (float)(j0 == rp));
                    float v1 = (base - nbv[nt].y + 2.f * c1) *
                               (1.f - (float)(j0 + 1 == lp) - (float)(j0 + 1 == rp));
                    *(float2*)&srow[j0] = make_float2(v0, v1);
                    s += v0 + v1; q += v0 * v0 + v1 * v1;
                    mx = fmaxf(mx, fmaxf(v0, v1));
                } else if (j0 < NN) {
                    float v0 = (base - nbv[nt].x + 2.f * c0) *
                               (1.f - (float)(j0 == lp) - (float)(j0 == rp));
                    srow[j0] = v0;
                    s += v0; q += v0 * v0; mx = fmaxf(mx, v0);
                }
            }
#pragma unroll
            for (int o = 1; o <= 2; o <<= 1) {
                s += __shfl_xor_sync(0xffffffffu, s, o);
                q += __shfl_xor_sync(0xffffffffu, q, o);
                mx = fmaxf(mx, __shfl_xor_sync(0xffffffffu, mx, o));
            }
            if (lr == 0) {
                atomicAdd(&g_rsum[i], (double)s);
                atomicAdd(&g_rsq[i], (double)q);
                atomicMaxF(&g_rmax[i], mx);
            }
        }
    }
}

// ---------------- per-row logsumexp ----------------
__global__ void k_row_exp() {
    int i = blockIdx.x;
    int tid = threadIdx.x;
    double mu_d = g_rsum[i] / NN;
    double var = g_rsq[i] / NN - mu_d * mu_d;
    if (var < 0.0) var = 0.0;
    double sd = sqrt(var);
    float mu = (float)mu_d;
    float inv = (float)(20.0 / sd);
    float zmax = (float)((g_rmax[i] - mu_d) * (20.0 / sd)) + 8.f;
    const float* row = &g_S[(size_t)i * NN];
    float cterm = 8.f - zmax - mu * inv;
    float es = 0.f;
    for (int j = tid; j < NN; j += 256) {
        es += fast_exp(fmaf(row[j], inv, cterm));
    }
    __shared__ float sh[256];
    sh[tid] = es;
    __syncthreads();
    for (int o = 128; o > 0; o >>= 1) {
        if (tid < o) sh[tid] += sh[tid + o];
        __syncthreads();
    }
    if (tid == 0) g_lse[i] = zmax + logf(sh[0]);
}

__global__ void k_final(float* out) {
    int tid = threadIdx.x;
    double acc = 0.0;
    for (int p = tid; p < BB; p += 256) acc += (double)g_lse[p] + (double)g_lse[BB + p];
    __shared__ double sh[256];
    sh[tid] = acc;
    __syncthreads();
    for (int o = 128; o > 0; o >>= 1) {
        if (tid < o) sh[tid] += sh[tid + o];
        __syncthreads();
    }
    if (tid == 0) out[0] = (float)(sh[0] / BB);
}

// ---------------- driver ----------------
extern "C" void kernel_launch(void* const* d_in, const int* in_sizes, int n_in,
                              void* d_out, int out_size) {
    const float* ent_emb = (const float*)d_in[0];
    const float* rel_emb = (const float*)d_in[1];
    const float* attn_e  = (const float*)d_in[2];
    const float* attn_r  = (const float*)d_in[3];
    const int* adj     = (const int*)d_in[5];
    const int* r_index = (const int*)d_in[6];
    const int* ent_adj = (const int*)d_in[7];
    const int* rel_adj = (const int*)d_in[8];
    const int* pairs   = (const int*)d_in[9];
    float* out = (float*)d_out;

    const int TPB = 256;
    const int gW_T  = (TT * 32 + TPB - 1) / TPB;
    const int gW_NZ = (NZ * 32 + TPB - 1) / TPB;
    const int gND   = (NN * DD + TPB - 1) / TPB;

    k_init<<<4096, TPB>>>();
    k_relprep<<<(RR * 32 + TPB - 1) / TPB, TPB>>>(rel_emb, attn_e, attn_r);
    k_smax_max<<<(TT + TPB - 1) / TPB, TPB>>>(adj, r_index);
    k_smax_sum<<<(TT + TPB - 1) / TPB, TPB>>>(adj, r_index);
    k_sinv<<<(4 * NN + TPB - 1) / TPB, TPB>>>();

    k_deg<<<(NZ + TPB - 1) / TPB, TPB>>>(ent_adj, 0);
    k_deg<<<(NZ + TPB - 1) / TPB, TPB>>>(rel_adj, 1);
    k_avg_scatter<<<gW_NZ, TPB>>>(ent_adj, ent_emb, 0);
    k_avg_scatter<<<gW_NZ, TPB>>>(rel_adj, rel_emb, 1);
    k_avg_div<<<gND, TPB>>>(0);
    k_avg_div<<<gND, TPB>>>(1);

    k_tanh2<<<gND, TPB>>>(0, 0);
    for (int l = 0; l < 2; l++) {
        k_zero2<<<gND, TPB>>>();
        k_edge_fused<<<gW_T, TPB>>>(adj, r_index, l);
        k_tanh2<<<gND, TPB>>>(1, (l + 1) * DD);
    }

    k_prep_pairs<<<(BB + TPB - 1) / TPB, TPB>>>(pairs);
    k_split<<<(NN * OUTD / 4 + TPB - 1) / TPB, TPB>>>();
    k_norms<<<(NN * 32 + TPB - 1) / TPB, TPB>>>();
    k_na<<<(2 * BB + TPB - 1) / TPB, TPB>>>();
    k_pos<<<(BB * 32 + TPB - 1) / TPB, TPB>>>();

    cudaFuncSetAttribute(k_gemm_mma, cudaFuncAttributeMaxDynamicSharedMemorySize, 2 * STGB);
    dim3 gg(2 * BB / 128, (NN + JT - 1) / JT);   // (16, 235), bm fast for B-tile L2 reuse
    k_gemm_mma<<<gg, 256, 2 * STGB>>>();
    k_row_exp<<<2 * BB, 256>>>();
    k_final<<<1, 256>>>(out);
}

// round 10
// speedup vs baseline: 4.7584x; 1.6964x over previous
#include <cuda_runtime.h>
#include <cuda_fp16.h>
#include <math.h>
#include <stdint.h>

#define NN 30000
#define RR 1000
#define TT 300000
#define DD 128
#define BB 1024
#define NZ 600000
#define OUTD 768
#define GAMMA_C 3.0f

typedef unsigned long long u64;

// ---------------- scratch (device globals) ----------------
__device__ float g_relhat[RR * DD];
__device__ float g_logit[4 * RR];
__device__ float g_m[4 * NN];
__device__ float g_s[4 * NN];                // expsum -> reciprocal after k_sinv
__device__ float g_featE[(size_t)NN * DD];
__device__ float g_featR[(size_t)NN * DD];
__device__ float g_degE[NN];
__device__ float g_degR[NN];
__device__ float g_fcur[(size_t)NN * 256];   // interleaved: [0,128) E, [128,256) R
__device__ float g_fnew[(size_t)NN * 256];
__device__ float g_emb[(size_t)NN * OUTD];
__device__ __half g_embh[(size_t)NN * OUTD]; // fp16 copy for tensor GEMM
__device__ float g_nb[NN];
__device__ int   g_idxA[2 * BB];
__device__ float g_na[2 * BB];
__device__ float g_pos[BB];
__device__ int   g_lp[BB];
__device__ int   g_rp[BB];
__device__ float g_S[(size_t)2 * BB * NN];
__device__ double g_rsum[2 * BB];
__device__ double g_rsq[2 * BB];
__device__ float  g_rmax[2 * BB];
__device__ float g_lse[2 * BB];

__device__ __forceinline__ float warp_sum(float v) {
#pragma unroll
    for (int o = 16; o > 0; o >>= 1) v += __shfl_xor_sync(0xffffffffu, v, o);
    return v;
}
__device__ __forceinline__ void atomicMaxF(float* addr, float v) {
    if (v >= 0.f) atomicMax((int*)addr, __float_as_int(v));
    else          atomicMin((unsigned int*)addr, __float_as_uint(v));
}
__device__ __forceinline__ void redAdd4(float* addr, float4 v) {
    asm volatile("red.global.add.v4.f32 [%0], {%1, %2, %3, %4};"
                 :: "l"(addr), "f"(v.x), "f"(v.y), "f"(v.z), "f"(v.w) : "memory");
}
__device__ __forceinline__ float fast_exp(float x) {
    float t = fmaxf(x * 1.4426950408889634f, -80.0f);
    float fl = floorf(t);
    float f = t - fl;
    float p = 0.0013333558f;
    p = fmaf(p, f, 0.0096181291f);
    p = fmaf(p, f, 0.0555041086f);
    p = fmaf(p, f, 0.2402264476f);
    p = fmaf(p, f, 0.6931471806f);
    p = fmaf(p, f, 1.0f);
    int i = (int)fl;
    return p * __int_as_float((i + 127) << 23);
}
__device__ __forceinline__ uint32_t smem_u32(const void* p) {
    uint32_t a;
    asm("{ .reg .u64 t; cvta.to.shared.u64 t, %1; cvt.u32.u64 %0, t; }" : "=r"(a) : "l"(p));
    return a;
}
__device__ __forceinline__ void cpasync16(uint32_t dst, const void* src) {
    asm volatile("cp.async.cg.shared.global [%0], [%1], 16;" :: "r"(dst), "l"(src));
}
__device__ __forceinline__ void ldsm4(uint32_t* r, uint32_t addr) {
    asm volatile("ldmatrix.sync.aligned.m8n8.x4.shared.b16 {%0,%1,%2,%3}, [%4];"
                 : "=r"(r[0]), "=r"(r[1]), "=r"(r[2]), "=r"(r[3]) : "r"(addr));
}
__device__ __forceinline__ void mma_f16(float* c, const uint32_t* a, const uint32_t* b) {
    asm volatile("mma.sync.aligned.m16n8k16.row.col.f32.f16.f16.f32 "
                 "{%0,%1,%2,%3}, {%4,%5,%6,%7}, {%8,%9}, {%0,%1,%2,%3};"
                 : "+f"(c[0]), "+f"(c[1]), "+f"(c[2]), "+f"(c[3])
                 : "r"(a[0]), "r"(a[1]), "r"(a[2]), "r"(a[3]), "r"(b[0]), "r"(b[1]));
}

// ---------------- init ----------------
__global__ void k_init() {
    size_t gid = (size_t)blockIdx.x * blockDim.x + threadIdx.x;
    size_t stride = (size_t)gridDim.x * blockDim.x;
    for (size_t i = gid; i < (size_t)NN * DD; i += stride) { g_featE[i] = 0.f; g_featR[i] = 0.f; }
    for (size_t i = gid; i < NN; i += stride) { g_degE[i] = 0.f; g_degR[i] = 0.f; }
    for (size_t i = gid; i < 4 * (size_t)NN; i += stride) { g_m[i] = -3.0e38f; g_s[i] = 0.f; }
    for (size_t i = gid; i < 2 * BB; i += stride) { g_rsum[i] = 0.0; g_rsq[i] = 0.0; g_rmax[i] = -3.0e38f; }
}

// ---------------- relation prep ----------------
__global__ void k_relprep(const float* __restrict__ rel_emb,
                          const float* __restrict__ attn_e,
                          const float* __restrict__ attn_r) {
    int gid = blockIdx.x * blockDim.x + threadIdx.x;
    int r = gid >> 5;
    if (r >= RR) return;
    int lane = gid & 31;
    int d = lane * 4;
    float4 u = *(const float4*)&rel_emb[(size_t)r * DD + d];
    float ss = u.x * u.x + u.y * u.y + u.z * u.z + u.w * u.w;
    ss = warp_sum(ss);
    float inv = 1.f / fmaxf(sqrtf(ss), 1e-12f);
    u.x *= inv; u.y *= inv; u.z *= inv; u.w *= inv;
    *(float4*)&g_relhat[r * DD + d] = u;
    const float* ks[4] = { attn_e, attn_e + DD, attn_r, attn_r + DD };
#pragma unroll
    for (int c = 0; c < 4; c++) {
        const float4 kk = *(const float4*)&ks[c][d];
        float dot = u.x * kk.x + u.y * kk.y + u.z * kk.z + u.w * kk.w;
        dot = warp_sum(dot);
        if (lane == 0) g_logit[c * RR + r] = dot;
    }
}

// ---------------- segment softmax ----------------
__global__ void k_smax_max(const int* __restrict__ adj, const int* __restrict__ r_index) {
    int t = blockIdx.x * blockDim.x + threadIdx.x;
    if (t >= TT) return;
    int row = adj[t], rel = r_index[TT + t];
#pragma unroll
    for (int c = 0; c < 4; c++) atomicMaxF(&g_m[c * NN + row], g_logit[c * RR + rel]);
}
__global__ void k_smax_sum(const int* __restrict__ adj, const int* __restrict__ r_index) {
    int t = blockIdx.x * blockDim.x + threadIdx.x;
    if (t >= TT) return;
    int row = adj[t], rel = r_index[TT + t];
#pragma unroll
    for (int c = 0; c < 4; c++)
        atomicAdd(&g_s[c * NN + row], fast_exp(g_logit[c * RR + rel] - g_m[c * NN + row]));
}
__global__ void k_sinv() {
    int idx = blockIdx.x * blockDim.x + threadIdx.x;
    if (idx >= 4 * NN) return;
    float s = g_s[idx];
    g_s[idx] = (s > 0.f) ? 1.f / s : 0.f;
}

// ---------------- neighbor-average features ----------------
__global__ void k_deg(const int* __restrict__ eadj, int which) {
    int e = blockIdx.x * blockDim.x + threadIdx.x;
    if (e >= NZ) return;
    float* deg = which ? g_degR : g_degE;
    atomicAdd(&deg[eadj[e]], 1.f);
}
__global__ void k_avg_scatter(const int* __restrict__ eadj,
                              const float* __restrict__ src, int which) {
    int gid = blockIdx.x * blockDim.x + threadIdx.x;
    int e = gid >> 5;
    if (e >= NZ) return;
    int d = (gid & 31) * 4;
    int row = eadj[e], col = eadj[NZ + e];
    float* feat = which ? g_featR : g_featE;
    const float4 v = *(const float4*)&src[(size_t)col * DD + d];
    redAdd4(&feat[(size_t)row * DD + d], v);
}
__global__ void k_avg_div(int which) {
    int idx = blockIdx.x * blockDim.x + threadIdx.x;
    if (idx >= NN * DD) return;
    float* feat = which ? g_featR : g_featE;
    const float* deg = which ? g_degR : g_degE;
    float dg = deg[idx / DD];
    if (dg > 0.f) feat[idx] /= dg;
}

// ---------------- GAT ----------------
// srcSel 0: read featE/featR; srcSel 1: read g_fnew (interleaved). Always zeroes g_fnew after.
__global__ void k_tanh2(int srcSel, int base) {
    int idx = blockIdx.x * blockDim.x + threadIdx.x;
    if (idx >= NN * DD) return;
    int n = idx / DD, d = idx - n * DD;
    size_t iE = (size_t)n * 256 + d;
    size_t iR = iE + 128;
    float vE, vR;
    if (srcSel) { vE = tanhf(g_fnew[iE]); vR = tanhf(g_fnew[iR]); }
    else        { vE = tanhf(g_featE[idx]); vR = tanhf(g_featR[idx]); }
    g_fcur[iE] = vE;
    g_fcur[iR] = vR;
    g_fnew[iE] = 0.f;
    g_fnew[iR] = 0.f;
    g_emb[(size_t)n * OUTD + base + d] = vE;
    g_emb[(size_t)n * OUTD + 3 * DD + base + d] = vR;
}
__global__ void k_edge_fused(const int* __restrict__ adj, const int* __restrict__ r_index, int l) {
    int gid = blockIdx.x * blockDim.x + threadIdx.x;
    int t = gid >> 5;
    if (t >= TT) return;
    int lane = gid & 31;
    int d = lane * 4;
    int row = __ldg(&adj[t]), col = __ldg(&adj[TT + t]), rel = __ldg(&r_index[TT + t]);
    float4 u  = *(const float4*)&g_relhat[rel * DD + d];
    float4 xE = *(const float4*)&g_fcur[(size_t)col * 256 + d];
    float4 xR = *(const float4*)&g_fcur[(size_t)col * 256 + 128 + d];
    float dE = warp_sum(xE.x * u.x + xE.y * u.y + xE.z * u.z + xE.w * u.w);
    float dR = warp_sum(xR.x * u.x + xR.y * u.y + xR.z * u.z + xR.w * u.w);
    int cE = l, cR = 2 + l;
    float wE = fast_exp(g_logit[cE * RR + rel] - g_m[cE * NN + row]) * g_s[cE * NN + row];
    float wR = fast_exp(g_logit[cR * RR + rel] - g_m[cR * NN + row]) * g_s[cR * NN + row];
    float sE = 2.f * dE, sR = 2.f * dR;
    float4 oE = make_float4(wE * (xE.x - sE * u.x), wE * (xE.y - sE * u.y),
                            wE * (xE.z - sE * u.z), wE * (xE.w - sE * u.w));
    float4 oR = make_float4(wR * (xR.x - sR * u.x), wR * (xR.y - sR * u.y),
                            wR * (xR.z - sR * u.z), wR * (xR.w - sR * u.w));
    redAdd4(&g_fnew[(size_t)row * 256 + d], oE);
    redAdd4(&g_fnew[(size_t)row * 256 + 128 + d], oR);
}

// ---------------- emb prep: fp16 convert + norms (fused) ----------------
__global__ void k_prep_emb() {
    int gid = blockIdx.x * blockDim.x + threadIdx.x;
    int j = gid >> 5;
    if (j >= NN) return;
    int lane = gid & 31;
    const float* row = &g_emb[(size_t)j * OUTD];
    __half* hrow = &g_embh[(size_t)j * OUTD];
    float ss = 0.f;
#pragma unroll
    for (int k = lane * 4; k < OUTD; k += 128) {
        float4 v = *(const float4*)&row[k];
        ss += v.x * v.x + v.y * v.y + v.z * v.z + v.w * v.w;
        __half2 h0 = __floats2half2_rn(v.x, v.y);
        __half2 h1 = __floats2half2_rn(v.z, v.w);
        *(uint2*)&hrow[k] = make_uint2(*(uint32_t*)&h0, *(uint32_t*)&h1);
    }
    ss = warp_sum(ss);
    if (lane == 0) g_nb[j] = ss;
}

// ---------------- loss prep ----------------
__global__ void k_prep_pairs(const int* __restrict__ pairs) {
    int p = blockIdx.x * blockDim.x + threadIdx.x;
    if (p >= BB) return;
    int lp = pairs[2 * p], rp = pairs[2 * p + 1];
    g_lp[p] = lp; g_rp[p] = rp;
    g_idxA[p] = lp; g_idxA[BB + p] = rp;
}
__global__ void k_na() {
    int i = blockIdx.x * blockDim.x + threadIdx.x;
    if (i >= 2 * BB) return;
    g_na[i] = g_nb[g_idxA[i]];
}
__global__ void k_pos() {
    int gid = blockIdx.x * blockDim.x + threadIdx.x;
    int p = gid >> 5;
    if (p >= BB) return;
    int lane = gid & 31;
    const float* a = &g_emb[(size_t)g_lp[p] * OUTD];
    const float* b = &g_emb[(size_t)g_rp[p] * OUTD];
    float ss = 0.f;
    for (int k = lane * 4; k < OUTD; k += 128) {
        float4 va = *(const float4*)&a[k];
        float4 vb = *(const float4*)&b[k];
        float dx = va.x - vb.x, dy = va.y - vb.y, dz = va.z - vb.z, dw = va.w - vb.w;
        ss += dx * dx + dy * dy + dz * dz + dw * dw;
    }
    ss = warp_sum(ss);
    if (lane == 0) g_pos[p] = ss;
}

// ---------------- mma.sync fp16 GEMM (128x128) + loss + stats ----------------
#define JT 128
#define NS (OUTD / 16)         // 48 k-stages
#define ROWB 48                // padded smem row bytes (16 halfs = 32B used)
#define STG_A 0
#define STG_B 6144
#define STGB 12288             // bytes per stage
#define NSTG 4

__global__ __launch_bounds__(256, 2) void k_gemm_mma() {
    extern __shared__ char dynsmem[];
    __shared__ int s_idx[128];
    const int tid = threadIdx.x;
    const int wid = tid >> 5;
    const int lane = tid & 31;
    const int warp_m = wid & 1;      // 2 warps in m (64 rows each)
    const int warp_n = wid >> 1;     // 4 warps in n (32 cols each)
    const int bm = blockIdx.x;
    const int jbase = blockIdx.y * JT;
    const uint32_t sbase = smem_u32(dynsmem);

    if (tid < 128) s_idx[tid] = g_idxA[bm * 128 + tid];
    __syncthreads();

    const int lrow = tid >> 1;       // loader row 0..127
    const int lhalf = tid & 1;       // 16B chunk
    int jld = jbase + lrow;
    if (jld >= NN) jld = 0;
    const __half* gaPtr = g_embh + (size_t)s_idx[lrow] * OUTD + lhalf * 8;
    const __half* gbPtr = g_embh + (size_t)jld * OUTD + lhalf * 8;
    const uint32_t dOff = lrow * ROWB + lhalf * 16;

    // prologue: stages 0..2
#pragma unroll
    for (int p = 0; p < 3; p++) {
        uint32_t sb = sbase + p * STGB;
        cpasync16(sb + STG_A + dOff, gaPtr + p * 16);
        cpasync16(sb + STG_B + dOff, gbPtr + p * 16);
        asm volatile("cp.async.commit_group;" ::: "memory");
    }

    float acc[4][4][4] = {};
    const int rsel = lane & 15;
    const int csel = (lane >> 4) * 16;

    for (int it = 0; it < NS; it++) {
        if (it < NS - 2)      asm volatile("cp.async.wait_group 2;" ::: "memory");
        else if (it == NS - 2) asm volatile("cp.async.wait_group 1;" ::: "memory");
        else                  asm volatile("cp.async.wait_group 0;" ::: "memory");
        __syncthreads();

        if (it + 3 < NS) {
            uint32_t sb = sbase + ((it + 3) & 3) * STGB;
            cpasync16(sb + STG_A + dOff, gaPtr + (it + 3) * 16);
            cpasync16(sb + STG_B + dOff, gbPtr + (it + 3) * 16);
            asm volatile("cp.async.commit_group;" ::: "memory");
        }

        const uint32_t sb = sbase + (it & 3) * STGB;
        uint32_t aF[4][4], bF[4][2];
#pragma unroll
        for (int mt = 0; mt < 4; mt++) {
            uint32_t ad = sb + STG_A + (uint32_t)((warp_m * 64 + mt * 16 + rsel) * ROWB + csel);
            ldsm4(aF[mt], ad);
        }
#pragma unroll
        for (int tp = 0; tp < 2; tp++) {
            uint32_t bd = sb + STG_B + (uint32_t)((warp_n * 32 + tp * 16 + rsel) * ROWB + csel);
            uint32_t r[4];
            ldsm4(r, bd);
            bF[tp * 2][0] = r[0]; bF[tp * 2][1] = r[2];
            bF[tp * 2 + 1][0] = r[1]; bF[tp * 2 + 1][1] = r[3];
        }
#pragma unroll
        for (int mt = 0; mt < 4; mt++)
#pragma unroll
            for (int nt = 0; nt < 4; nt++)
                mma_f16(acc[mt][nt], aF[mt], bF[nt]);
    }

    // ---------------- epilogue: loss assembly + fused row stats ----------------
    const int lq = lane >> 2;    // row-in-8
    const int lr = lane & 3;     // col quad
    float2 nbv[4];
#pragma unroll
    for (int nt = 0; nt < 4; nt++) {
        int j0 = jbase + warp_n * 32 + nt * 8 + 2 * lr;
        nbv[nt].x = (j0 < NN) ? g_nb[j0] : 0.f;
        nbv[nt].y = (j0 + 1 < NN) ? g_nb[j0 + 1] : 0.f;
    }
#pragma unroll
    for (int mt = 0; mt < 4; mt++) {
#pragma unroll
        for (int h = 0; h < 2; h++) {
            const int i = bm * 128 + warp_m * 64 + mt * 16 + lq + h * 8;
            const int p = i & (BB - 1);
            const float base = g_pos[p] - g_na[i] + GAMMA_C;
            const int lp = g_lp[p], rp = g_rp[p];
            float s = 0.f, q = 0.f, mx = -3.0e38f;
            float* srow = &g_S[(size_t)i * NN];
#pragma unroll
            for (int nt = 0; nt < 4; nt++) {
                int j0 = jbase + warp_n * 32 + nt * 8 + 2 * lr;
                float c0 = acc[mt][nt][h * 2 + 0];
                float c1 = acc[mt][nt][h * 2 + 1];
                if (j0 + 1 < NN) {
                    float v0 = (base - nbv[nt].x + 2.f * c0) *
                               (1.f - (float)(j0 == lp) - (float)(j0 == rp));
                    float v1 = (base - nbv[nt].y + 2.f * c1) *
                               (1.f - (float)(j0 + 1 == lp) - (float)(j0 + 1 == rp));
                    *(float2*)&srow[j0] = make_float2(v0, v1);
                    s += v0 + v1; q += v0 * v0 + v1 * v1;
                    mx = fmaxf(mx, fmaxf(v0, v1));
                } else if (j0 < NN) {
                    float v0 = (base - nbv[nt].x + 2.f * c0) *
                               (1.f - (float)(j0 == lp) - (float)(j0 == rp));
                    srow[j0] = v0;
                    s += v0; q += v0 * v0; mx = fmaxf(mx, v0);
                }
            }
#pragma unroll
            for (int o = 1; o <= 2; o <<= 1) {
                s += __shfl_xor_sync(0xffffffffu, s, o);
                q += __shfl_xor_sync(0xffffffffu, q, o);
                mx = fmaxf(mx, __shfl_xor_sync(0xffffffffu, mx, o));
            }
            if (lr == 0) {
                atomicAdd(&g_rsum[i], (double)s);
                atomicAdd(&g_rsq[i], (double)q);
                atomicMaxF(&g_rmax[i], mx);
            }
        }
    }
}

// ---------------- per-row logsumexp ----------------
__global__ void k_row_exp() {
    int i = blockIdx.x;
    int tid = threadIdx.x;
    double mu_d = g_rsum[i] / NN;
    double var = g_rsq[i] / NN - mu_d * mu_d;
    if (var < 0.0) var = 0.0;
    double sd = sqrt(var);
    float mu = (float)mu_d;
    float inv = (float)(20.0 / sd);
    float zmax = (float)((g_rmax[i] - mu_d) * (20.0 / sd)) + 8.f;
    const float* row = &g_S[(size_t)i * NN];
    float cterm = 8.f - zmax - mu * inv;
    float es = 0.f;
    for (int j = tid; j < NN; j += 256) {
        es += fast_exp(fmaf(row[j], inv, cterm));
    }
    __shared__ float sh[256];
    sh[tid] = es;
    __syncthreads();
    for (int o = 128; o > 0; o >>= 1) {
        if (tid < o) sh[tid] += sh[tid + o];
        __syncthreads();
    }
    if (tid == 0) g_lse[i] = zmax + logf(sh[0]);
}

__global__ void k_final(float* out) {
    int tid = threadIdx.x;
    double acc = 0.0;
    for (int p = tid; p < BB; p += 256) acc += (double)g_lse[p] + (double)g_lse[BB + p];
    __shared__ double sh[256];
    sh[tid] = acc;
    __syncthreads();
    for (int o = 128; o > 0; o >>= 1) {
        if (tid < o) sh[tid] += sh[tid + o];
        __syncthreads();
    }
    if (tid == 0) out[0] = (float)(sh[0] / BB);
}

// ---------------- driver ----------------
extern "C" void kernel_launch(void* const* d_in, const int* in_sizes, int n_in,
                              void* d_out, int out_size) {
    const float* ent_emb = (const float*)d_in[0];
    const float* rel_emb = (const float*)d_in[1];
    const float* attn_e  = (const float*)d_in[2];
    const float* attn_r  = (const float*)d_in[3];
    const int* adj     = (const int*)d_in[5];
    const int* r_index = (const int*)d_in[6];
    const int* ent_adj = (const int*)d_in[7];
    const int* rel_adj = (const int*)d_in[8];
    const int* pairs   = (const int*)d_in[9];
    float* out = (float*)d_out;

    const int TPB = 256;
    const int gW_T  = (TT * 32 + TPB - 1) / TPB;
    const int gW_NZ = (NZ * 32 + TPB - 1) / TPB;
    const int gND   = (NN * DD + TPB - 1) / TPB;

    k_init<<<4096, TPB>>>();
    k_relprep<<<(RR * 32 + TPB - 1) / TPB, TPB>>>(rel_emb, attn_e, attn_r);
    k_smax_max<<<(TT + TPB - 1) / TPB, TPB>>>(adj, r_index);
    k_smax_sum<<<(TT + TPB - 1) / TPB, TPB>>>(adj, r_index);
    k_sinv<<<(4 * NN + TPB - 1) / TPB, TPB>>>();

    k_deg<<<(NZ + TPB - 1) / TPB, TPB>>>(ent_adj, 0);
    k_deg<<<(NZ + TPB - 1) / TPB, TPB>>>(rel_adj, 1);
    k_avg_scatter<<<gW_NZ, TPB>>>(ent_adj, ent_emb, 0);
    k_avg_scatter<<<gW_NZ, TPB>>>(rel_adj, rel_emb, 1);
    k_avg_div<<<gND, TPB>>>(0);
    k_avg_div<<<gND, TPB>>>(1);

    k_tanh2<<<gND, TPB>>>(0, 0);
    for (int l = 0; l < 2; l++) {
        k_edge_fused<<<gW_T, TPB>>>(adj, r_index, l);
        k_tanh2<<<gND, TPB>>>(1, (l + 1) * DD);
    }

    k_prep_pairs<<<(BB + TPB - 1) / TPB, TPB>>>(pairs);
    k_prep_emb<<<(NN * 32 + TPB - 1) / TPB, TPB>>>();
    k_na<<<(2 * BB + TPB - 1) / TPB, TPB>>>();
    k_pos<<<(BB * 32 + TPB - 1) / TPB, TPB>>>();

    cudaFuncSetAttribute(k_gemm_mma, cudaFuncAttributeMaxDynamicSharedMemorySize, NSTG * STGB);
    dim3 gg(2 * BB / 128, (NN + JT - 1) / JT);   // (16, 235), bm fast for B-tile L2 reuse
    k_gemm_mma<<<gg, 256, NSTG * STGB>>>();
    k_row_exp<<<2 * BB, 256>>>();
    k_final<<<1, 256>>>(out);
}

// round 11
// speedup vs baseline: 4.8460x; 1.0184x over previous
#include <cuda_runtime.h>
#include <cuda_fp16.h>
#include <math.h>
#include <stdint.h>

#define NN 30000
#define RR 1000
#define TT 300000
#define DD 128
#define BB 1024
#define NZ 600000
#define OUTD 768
#define GAMMA_C 3.0f

typedef unsigned long long u64;

// ---------------- scratch (device globals) ----------------
__device__ float g_relhat[RR * DD];
__device__ float g_logit[4 * RR];
__device__ float g_m[4 * NN];
__device__ float g_s[4 * NN];                // expsum -> reciprocal after k_sinv
__device__ float g_featE[(size_t)NN * DD];
__device__ float g_featR[(size_t)NN * DD];
__device__ float g_degE[NN];
__device__ float g_degR[NN];
__device__ float g_fcur[(size_t)NN * 256];   // interleaved: [0,128) E, [128,256) R
__device__ float g_fnew[(size_t)NN * 256];
__device__ float g_emb[(size_t)NN * OUTD];
__device__ __half g_embh[(size_t)NN * OUTD]; // fp16 copy for tensor GEMM
__device__ float g_nb[NN];
__device__ int   g_idxA[2 * BB];
__device__ float g_na[2 * BB];
__device__ float g_pos[BB];
__device__ int   g_lp[BB];
__device__ int   g_rp[BB];
__device__ float g_S[(size_t)2 * BB * NN];
__device__ double g_rsum[2 * BB];
__device__ double g_rsq[2 * BB];
__device__ float  g_rmax[2 * BB];
__device__ float g_lse[2 * BB];

__device__ __forceinline__ float warp_sum(float v) {
#pragma unroll
    for (int o = 16; o > 0; o >>= 1) v += __shfl_xor_sync(0xffffffffu, v, o);
    return v;
}
__device__ __forceinline__ void atomicMaxF(float* addr, float v) {
    if (v >= 0.f) atomicMax((int*)addr, __float_as_int(v));
    else          atomicMin((unsigned int*)addr, __float_as_uint(v));
}
__device__ __forceinline__ void redAdd4(float* addr, float4 v) {
    asm volatile("red.global.add.v4.f32 [%0], {%1, %2, %3, %4};"
                 :: "l"(addr), "f"(v.x), "f"(v.y), "f"(v.z), "f"(v.w) : "memory");
}
__device__ __forceinline__ float fast_exp(float x) {
    float t = fmaxf(x * 1.4426950408889634f, -80.0f);
    float fl = floorf(t);
    float f = t - fl;
    float p = 0.0013333558f;
    p = fmaf(p, f, 0.0096181291f);
    p = fmaf(p, f, 0.0555041086f);
    p = fmaf(p, f, 0.2402264476f);
    p = fmaf(p, f, 0.6931471806f);
    p = fmaf(p, f, 1.0f);
    int i = (int)fl;
    return p * __int_as_float((i + 127) << 23);
}
__device__ __forceinline__ uint32_t smem_u32(const void* p) {
    uint32_t a;
    asm("{ .reg .u64 t; cvta.to.shared.u64 t, %1; cvt.u32.u64 %0, t; }" : "=r"(a) : "l"(p));
    return a;
}
__device__ __forceinline__ void cpasync16(uint32_t dst, const void* src) {
    asm volatile("cp.async.cg.shared.global [%0], [%1], 16;" :: "r"(dst), "l"(src));
}
__device__ __forceinline__ void ldsm4(uint32_t* r, uint32_t addr) {
    asm volatile("ldmatrix.sync.aligned.m8n8.x4.shared.b16 {%0,%1,%2,%3}, [%4];"
                 : "=r"(r[0]), "=r"(r[1]), "=r"(r[2]), "=r"(r[3]) : "r"(addr));
}
__device__ __forceinline__ void mma_f16(float* c, const uint32_t* a, const uint32_t* b) {
    asm volatile("mma.sync.aligned.m16n8k16.row.col.f32.f16.f16.f32 "
                 "{%0,%1,%2,%3}, {%4,%5,%6,%7}, {%8,%9}, {%0,%1,%2,%3};"
                 : "+f"(c[0]), "+f"(c[1]), "+f"(c[2]), "+f"(c[3])
                 : "r"(a[0]), "r"(a[1]), "r"(a[2]), "r"(a[3]), "r"(b[0]), "r"(b[1]));
}

// ---------------- per-chain init kernels ----------------
__global__ void k_init_feat(int which) {
    size_t gid = (size_t)blockIdx.x * blockDim.x + threadIdx.x;
    size_t stride = (size_t)gridDim.x * blockDim.x;
    float* feat = which ? g_featR : g_featE;
    float* deg = which ? g_degR : g_degE;
    for (size_t i = gid; i < (size_t)NN * DD; i += stride) feat[i] = 0.f;
    for (size_t i = gid; i < NN; i += stride) deg[i] = 0.f;
}
__global__ void k_init_sm() {
    size_t gid = (size_t)blockIdx.x * blockDim.x + threadIdx.x;
    size_t stride = (size_t)gridDim.x * blockDim.x;
    for (size_t i = gid; i < 4 * (size_t)NN; i += stride) { g_m[i] = -3.0e38f; g_s[i] = 0.f; }
}
__global__ void k_init_stats() {
    int i = blockIdx.x * blockDim.x + threadIdx.x;
    if (i < 2 * BB) { g_rsum[i] = 0.0; g_rsq[i] = 0.0; g_rmax[i] = -3.0e38f; }
}

// ---------------- relation prep ----------------
__global__ void k_relprep(const float* __restrict__ rel_emb,
                          const float* __restrict__ attn_e,
                          const float* __restrict__ attn_r) {
    int gid = blockIdx.x * blockDim.x + threadIdx.x;
    int r = gid >> 5;
    if (r >= RR) return;
    int lane = gid & 31;
    int d = lane * 4;
    float4 u = *(const float4*)&rel_emb[(size_t)r * DD + d];
    float ss = u.x * u.x + u.y * u.y + u.z * u.z + u.w * u.w;
    ss = warp_sum(ss);
    float inv = 1.f / fmaxf(sqrtf(ss), 1e-12f);
    u.x *= inv; u.y *= inv; u.z *= inv; u.w *= inv;
    *(float4*)&g_relhat[r * DD + d] = u;
    const float* ks[4] = { attn_e, attn_e + DD, attn_r, attn_r + DD };
#pragma unroll
    for (int c = 0; c < 4; c++) {
        const float4 kk = *(const float4*)&ks[c][d];
        float dot = u.x * kk.x + u.y * kk.y + u.z * kk.z + u.w * kk.w;
        dot = warp_sum(dot);
        if (lane == 0) g_logit[c * RR + r] = dot;
    }
}

// ---------------- segment softmax ----------------
__global__ void k_smax_max(const int* __restrict__ adj, const int* __restrict__ r_index) {
    int t = blockIdx.x * blockDim.x + threadIdx.x;
    if (t >= TT) return;
    int row = adj[t], rel = r_index[TT + t];
#pragma unroll
    for (int c = 0; c < 4; c++) atomicMaxF(&g_m[c * NN + row], g_logit[c * RR + rel]);
}
__global__ void k_smax_sum(const int* __restrict__ adj, const int* __restrict__ r_index) {
    int t = blockIdx.x * blockDim.x + threadIdx.x;
    if (t >= TT) return;
    int row = adj[t], rel = r_index[TT + t];
#pragma unroll
    for (int c = 0; c < 4; c++)
        atomicAdd(&g_s[c * NN + row], fast_exp(g_logit[c * RR + rel] - g_m[c * NN + row]));
}
__global__ void k_sinv() {
    int idx = blockIdx.x * blockDim.x + threadIdx.x;
    if (idx >= 4 * NN) return;
    float s = g_s[idx];
    g_s[idx] = (s > 0.f) ? 1.f / s : 0.f;
}

// ---------------- neighbor-average features ----------------
__global__ void k_deg(const int* __restrict__ eadj, int which) {
    int e = blockIdx.x * blockDim.x + threadIdx.x;
    if (e >= NZ) return;
    float* deg = which ? g_degR : g_degE;
    atomicAdd(&deg[eadj[e]], 1.f);
}
__global__ void k_avg_scatter(const int* __restrict__ eadj,
                              const float* __restrict__ src, int which) {
    int gid = blockIdx.x * blockDim.x + threadIdx.x;
    int e = gid >> 5;
    if (e >= NZ) return;
    int d = (gid & 31) * 4;
    int row = eadj[e], col = eadj[NZ + e];
    float* feat = which ? g_featR : g_featE;
    const float4 v = *(const float4*)&src[(size_t)col * DD + d];
    redAdd4(&feat[(size_t)row * DD + d], v);
}
__global__ void k_avg_div(int which) {
    int idx = blockIdx.x * blockDim.x + threadIdx.x;
    if (idx >= NN * DD) return;
    float* feat = which ? g_featR : g_featE;
    const float* deg = which ? g_degR : g_degE;
    float dg = deg[idx / DD];
    if (dg > 0.f) feat[idx] /= dg;
}

// ---------------- GAT ----------------
__global__ void k_tanh2(int srcSel, int base) {
    int idx = blockIdx.x * blockDim.x + threadIdx.x;
    if (idx >= NN * DD) return;
    int n = idx / DD, d = idx - n * DD;
    size_t iE = (size_t)n * 256 + d;
    size_t iR = iE + 128;
    float vE, vR;
    if (srcSel) { vE = tanhf(g_fnew[iE]); vR = tanhf(g_fnew[iR]); }
    else        { vE = tanhf(g_featE[idx]); vR = tanhf(g_featR[idx]); }
    g_fcur[iE] = vE;
    g_fcur[iR] = vR;
    g_fnew[iE] = 0.f;
    g_fnew[iR] = 0.f;
    g_emb[(size_t)n * OUTD + base + d] = vE;
    g_emb[(size_t)n * OUTD + 3 * DD + base + d] = vR;
}
__global__ void k_edge_fused(const int* __restrict__ adj, const int* __restrict__ r_index, int l) {
    int gid = blockIdx.x * blockDim.x + threadIdx.x;
    int t = gid >> 5;
    if (t >= TT) return;
    int lane = gid & 31;
    int d = lane * 4;
    int row = __ldg(&adj[t]), col = __ldg(&adj[TT + t]), rel = __ldg(&r_index[TT + t]);
    float4 u  = *(const float4*)&g_relhat[rel * DD + d];
    float4 xE = *(const float4*)&g_fcur[(size_t)col * 256 + d];
    float4 xR = *(const float4*)&g_fcur[(size_t)col * 256 + 128 + d];
    float dE = warp_sum(xE.x * u.x + xE.y * u.y + xE.z * u.z + xE.w * u.w);
    float dR = warp_sum(xR.x * u.x + xR.y * u.y + xR.z * u.z + xR.w * u.w);
    int cE = l, cR = 2 + l;
    float wE = fast_exp(g_logit[cE * RR + rel] - g_m[cE * NN + row]) * g_s[cE * NN + row];
    float wR = fast_exp(g_logit[cR * RR + rel] - g_m[cR * NN + row]) * g_s[cR * NN + row];
    float sE = 2.f * dE, sR = 2.f * dR;
    float4 oE = make_float4(wE * (xE.x - sE * u.x), wE * (xE.y - sE * u.y),
                            wE * (xE.z - sE * u.z), wE * (xE.w - sE * u.w));
    float4 oR = make_float4(wR * (xR.x - sR * u.x), wR * (xR.y - sR * u.y),
                            wR * (xR.z - sR * u.z), wR * (xR.w - sR * u.w));
    redAdd4(&g_fnew[(size_t)row * 256 + d], oE);
    redAdd4(&g_fnew[(size_t)row * 256 + 128 + d], oR);
}

// ---------------- emb prep: fp16 convert + norms (fused) ----------------
__global__ void k_prep_emb() {
    int gid = blockIdx.x * blockDim.x + threadIdx.x;
    int j = gid >> 5;
    if (j >= NN) return;
    int lane = gid & 31;
    const float* row = &g_emb[(size_t)j * OUTD];
    __half* hrow = &g_embh[(size_t)j * OUTD];
    float ss = 0.f;
#pragma unroll
    for (int k = lane * 4; k < OUTD; k += 128) {
        float4 v = *(const float4*)&row[k];
        ss += v.x * v.x + v.y * v.y + v.z * v.z + v.w * v.w;
        __half2 h0 = __floats2half2_rn(v.x, v.y);
        __half2 h1 = __floats2half2_rn(v.z, v.w);
        *(uint2*)&hrow[k] = make_uint2(*(uint32_t*)&h0, *(uint32_t*)&h1);
    }
    ss = warp_sum(ss);
    if (lane == 0) g_nb[j] = ss;
}

// ---------------- loss prep ----------------
__global__ void k_prep_pairs(const int* __restrict__ pairs) {
    int p = blockIdx.x * blockDim.x + threadIdx.x;
    if (p >= BB) return;
    int lp = pairs[2 * p], rp = pairs[2 * p + 1];
    g_lp[p] = lp; g_rp[p] = rp;
    g_idxA[p] = lp; g_idxA[BB + p] = rp;
}
__global__ void k_na() {
    int i = blockIdx.x * blockDim.x + threadIdx.x;
    if (i >= 2 * BB) return;
    g_na[i] = g_nb[g_idxA[i]];
}
__global__ void k_pos() {
    int gid = blockIdx.x * blockDim.x + threadIdx.x;
    int p = gid >> 5;
    if (p >= BB) return;
    int lane = gid & 31;
    const float* a = &g_emb[(size_t)g_lp[p] * OUTD];
    const float* b = &g_emb[(size_t)g_rp[p] * OUTD];
    float ss = 0.f;
    for (int k = lane * 4; k < OUTD; k += 128) {
        float4 va = *(const float4*)&a[k];
        float4 vb = *(const float4*)&b[k];
        float dx = va.x - vb.x, dy = va.y - vb.y, dz = va.z - vb.z, dw = va.w - vb.w;
        ss += dx * dx + dy * dy + dz * dz + dw * dw;
    }
    ss = warp_sum(ss);
    if (lane == 0) g_pos[p] = ss;
}

// ---------------- mma.sync fp16 GEMM (128x128) + loss + stats ----------------
#define JT 128
#define NS (OUTD / 16)         // 48 k-stages
#define ROWB 48                // padded smem row bytes (16 halfs = 32B used)
#define STG_A 0
#define STG_B 6144
#define STGB 12288             // bytes per stage
#define NSTG 4

__global__ __launch_bounds__(256, 2) void k_gemm_mma() {
    extern __shared__ char dynsmem[];
    __shared__ int s_idx[128];
    const int tid = threadIdx.x;
    const int wid = tid >> 5;
    const int lane = tid & 31;
    const int warp_m = wid & 1;      // 2 warps in m (64 rows each)
    const int warp_n = wid >> 1;     // 4 warps in n (32 cols each)
    const int bm = blockIdx.x;
    const int jbase = blockIdx.y * JT;
    const uint32_t sbase = smem_u32(dynsmem);

    if (tid < 128) s_idx[tid] = g_idxA[bm * 128 + tid];
    __syncthreads();

    const int lrow = tid >> 1;       // loader row 0..127
    const int lhalf = tid & 1;       // 16B chunk
    int jld = jbase + lrow;
    if (jld >= NN) jld = 0;
    const __half* gaPtr = g_embh + (size_t)s_idx[lrow] * OUTD + lhalf * 8;
    const __half* gbPtr = g_embh + (size_t)jld * OUTD + lhalf * 8;
    const uint32_t dOff = lrow * ROWB + lhalf * 16;

    // prologue: stages 0..2
#pragma unroll
    for (int p = 0; p < 3; p++) {
        uint32_t sb = sbase + p * STGB;
        cpasync16(sb + STG_A + dOff, gaPtr + p * 16);
        cpasync16(sb + STG_B + dOff, gbPtr + p * 16);
        asm volatile("cp.async.commit_group;" ::: "memory");
    }

    float acc[4][4][4] = {};
    const int rsel = lane & 15;
    const int csel = (lane >> 4) * 16;

    for (int it = 0; it < NS; it++) {
        if (it < NS - 2)      asm volatile("cp.async.wait_group 2;" ::: "memory");
        else if (it == NS - 2) asm volatile("cp.async.wait_group 1;" ::: "memory");
        else                  asm volatile("cp.async.wait_group 0;" ::: "memory");
        __syncthreads();

        if (it + 3 < NS) {
            uint32_t sb = sbase + ((it + 3) & 3) * STGB;
            cpasync16(sb + STG_A + dOff, gaPtr + (it + 3) * 16);
            cpasync16(sb + STG_B + dOff, gbPtr + (it + 3) * 16);
            asm volatile("cp.async.commit_group;" ::: "memory");
        }

        const uint32_t sb = sbase + (it & 3) * STGB;
        uint32_t aF[4][4], bF[4][2];
#pragma unroll
        for (int mt = 0; mt < 4; mt++) {
            uint32_t ad = sb + STG_A + (uint32_t)((warp_m * 64 + mt * 16 + rsel) * ROWB + csel);
            ldsm4(aF[mt], ad);
        }
#pragma unroll
        for (int tp = 0; tp < 2; tp++) {
            uint32_t bd = sb + STG_B + (uint32_t)((warp_n * 32 + tp * 16 + rsel) * ROWB + csel);
            uint32_t r[4];
            ldsm4(r, bd);
            bF[tp * 2][0] = r[0]; bF[tp * 2][1] = r[2];
            bF[tp * 2 + 1][0] = r[1]; bF[tp * 2 + 1][1] = r[3];
        }
#pragma unroll
        for (int mt = 0; mt < 4; mt++)
#pragma unroll
            for (int nt = 0; nt < 4; nt++)
                mma_f16(acc[mt][nt], aF[mt], bF[nt]);
    }

    // ---------------- epilogue: loss assembly + fused row stats ----------------
    const int lq = lane >> 2;    // row-in-8
    const int lr = lane & 3;     // col quad
    float2 nbv[4];
#pragma unroll
    for (int nt = 0; nt < 4; nt++) {
        int j0 = jbase + warp_n * 32 + nt * 8 + 2 * lr;
        nbv[nt].x = (j0 < NN) ? g_nb[j0] : 0.f;
        nbv[nt].y = (j0 + 1 < NN) ? g_nb[j0 + 1] : 0.f;
    }
#pragma unroll
    for (int mt = 0; mt < 4; mt++) {
#pragma unroll
        for (int h = 0; h < 2; h++) {
            const int i = bm * 128 + warp_m * 64 + mt * 16 + lq + h * 8;
            const int p = i & (BB - 1);
            const float base = g_pos[p] - g_na[i] + GAMMA_C;
            const int lp = g_lp[p], rp = g_rp[p];
            float s = 0.f, q = 0.f, mx = -3.0e38f;
            float* srow = &g_S[(size_t)i * NN];
#pragma unroll
            for (int nt = 0; nt < 4; nt++) {
                int j0 = jbase + warp_n * 32 + nt * 8 + 2 * lr;
                float c0 = acc[mt][nt][h * 2 + 0];
                float c1 = acc[mt][nt][h * 2 + 1];
                if (j0 + 1 < NN) {
                    float v0 = (base - nbv[nt].x + 2.f * c0) *
                               (1.f - (float)(j0 == lp) - (float)(j0 == rp));
                    float v1 = (base - nbv[nt].y + 2.f * c1) *
                               (1.f - (float)(j0 + 1 == lp) - (float)(j0 + 1 == rp));
                    *(float2*)&srow[j0] = make_float2(v0, v1);
                    s += v0 + v1; q += v0 * v0 + v1 * v1;
                    mx = fmaxf(mx, fmaxf(v0, v1));
                } else if (j0 < NN) {
                    float v0 = (base - nbv[nt].x + 2.f * c0) *
                               (1.f - (float)(j0 == lp) - (float)(j0 == rp));
                    srow[j0] = v0;
                    s += v0; q += v0 * v0; mx = fmaxf(mx, v0);
                }
            }
#pragma unroll
            for (int o = 1; o <= 2; o <<= 1) {
                s += __shfl_xor_sync(0xffffffffu, s, o);
                q += __shfl_xor_sync(0xffffffffu, q, o);
                mx = fmaxf(mx, __shfl_xor_sync(0xffffffffu, mx, o));
            }
            if (lr == 0) {
                atomicAdd(&g_rsum[i], (double)s);
                atomicAdd(&g_rsq[i], (double)q);
                atomicMaxF(&g_rmax[i], mx);
            }
        }
    }
}

// ---------------- per-row logsumexp ----------------
__global__ void k_row_exp() {
    int i = blockIdx.x;
    int tid = threadIdx.x;
    double mu_d = g_rsum[i] / NN;
    double var = g_rsq[i] / NN - mu_d * mu_d;
    if (var < 0.0) var = 0.0;
    double sd = sqrt(var);
    float mu = (float)mu_d;
    float inv = (float)(20.0 / sd);
    float zmax = (float)((g_rmax[i] - mu_d) * (20.0 / sd)) + 8.f;
    const float4* row4 = (const float4*)&g_S[(size_t)i * NN];
    float cterm = 8.f - zmax - mu * inv;
    float es = 0.f;
    for (int j = tid; j < NN / 4; j += 256) {
        float4 v = row4[j];
        es += fast_exp(fmaf(v.x, inv, cterm));
        es += fast_exp(fmaf(v.y, inv, cterm));
        es += fast_exp(fmaf(v.z, inv, cterm));
        es += fast_exp(fmaf(v.w, inv, cterm));
    }
    __shared__ float sh[256];
    sh[tid] = es;
    __syncthreads();
    for (int o = 128; o > 0; o >>= 1) {
        if (tid < o) sh[tid] += sh[tid + o];
        __syncthreads();
    }
    if (tid == 0) g_lse[i] = zmax + logf(sh[0]);
}

__global__ void k_final(float* out) {
    int tid = threadIdx.x;
    double acc = 0.0;
    for (int p = tid; p < BB; p += 256) acc += (double)g_lse[p] + (double)g_lse[BB + p];
    __shared__ double sh[256];
    sh[tid] = acc;
    __syncthreads();
    for (int o = 128; o > 0; o >>= 1) {
        if (tid < o) sh[tid] += sh[tid + o];
        __syncthreads();
    }
    if (tid == 0) out[0] = (float)(sh[0] / BB);
}

// ---------------- driver ----------------
extern "C" void kernel_launch(void* const* d_in, const int* in_sizes, int n_in,
                              void* d_out, int out_size) {
    const float* ent_emb = (const float*)d_in[0];
    const float* rel_emb = (const float*)d_in[1];
    const float* attn_e  = (const float*)d_in[2];
    const float* attn_r  = (const float*)d_in[3];
    const int* adj     = (const int*)d_in[5];
    const int* r_index = (const int*)d_in[6];
    const int* ent_adj = (const int*)d_in[7];
    const int* rel_adj = (const int*)d_in[8];
    const int* pairs   = (const int*)d_in[9];
    float* out = (float*)d_out;

    // one-time side streams + events (host objects; created once, reused every call)
    static cudaStream_t sA = 0, sB = 0, sC = 0;
    static cudaEvent_t evRoot = 0, evA = 0, evB = 0, evC = 0;
    static bool sinit = false;
    if (!sinit) {
        cudaStreamCreateWithFlags(&sA, cudaStreamNonBlocking);
        cudaStreamCreateWithFlags(&sB, cudaStreamNonBlocking);
        cudaStreamCreateWithFlags(&sC, cudaStreamNonBlocking);
        cudaEventCreateWithFlags(&evRoot, cudaEventDisableTiming);
        cudaEventCreateWithFlags(&evA, cudaEventDisableTiming);
        cudaEventCreateWithFlags(&evB, cudaEventDisableTiming);
        cudaEventCreateWithFlags(&evC, cudaEventDisableTiming);
        sinit = true;
    }

    const int TPB = 256;
    const int gW_T  = (TT * 32 + TPB - 1) / TPB;
    const int gW_NZ = (NZ * 32 + TPB - 1) / TPB;
    const int gND   = (NN * DD + TPB - 1) / TPB;
    const int gT    = (TT + TPB - 1) / TPB;
    const int gNZ1  = (NZ + TPB - 1) / TPB;

    // root of the fork
    k_init_stats<<<(2 * BB + TPB - 1) / TPB, TPB>>>();
    cudaEventRecord(evRoot, 0);
    cudaStreamWaitEvent(sA, evRoot, 0);
    cudaStreamWaitEvent(sB, evRoot, 0);
    cudaStreamWaitEvent(sC, evRoot, 0);

    // chain A: softmax prep
    k_init_sm<<<2048, TPB, 0, sA>>>();
    k_relprep<<<(RR * 32 + TPB - 1) / TPB, TPB, 0, sA>>>(rel_emb, attn_e, attn_r);
    k_smax_max<<<gT, TPB, 0, sA>>>(adj, r_index);
    k_smax_sum<<<gT, TPB, 0, sA>>>(adj, r_index);
    k_sinv<<<(4 * NN + TPB - 1) / TPB, TPB, 0, sA>>>();
    cudaEventRecord(evA, sA);

    // chain B: entity averaging
    k_init_feat<<<2048, TPB, 0, sB>>>(0);
    k_deg<<<gNZ1, TPB, 0, sB>>>(ent_adj, 0);
    k_avg_scatter<<<gW_NZ, TPB, 0, sB>>>(ent_adj, ent_emb, 0);
    k_avg_div<<<gND, TPB, 0, sB>>>(0);
    cudaEventRecord(evB, sB);

    // chain C: relation averaging
    k_init_feat<<<2048, TPB, 0, sC>>>(1);
    k_deg<<<gNZ1, TPB, 0, sC>>>(rel_adj, 1);
    k_avg_scatter<<<gW_NZ, TPB, 0, sC>>>(rel_adj, rel_emb, 1);
    k_avg_div<<<gND, TPB, 0, sC>>>(1);
    cudaEventRecord(evC, sC);

    // join: tanh needs averages; edge additionally needs softmax chain
    cudaStreamWaitEvent(0, evB, 0);
    cudaStreamWaitEvent(0, evC, 0);
    k_tanh2<<<gND, TPB>>>(0, 0);
    cudaStreamWaitEvent(0, evA, 0);
    for (int l = 0; l < 2; l++) {
        k_edge_fused<<<gW_T, TPB>>>(adj, r_index, l);
        k_tanh2<<<gND, TPB>>>(1, (l + 1) * DD);
    }

    k_prep_pairs<<<(BB + TPB - 1) / TPB, TPB>>>(pairs);
    k_prep_emb<<<(NN * 32 + TPB - 1) / TPB, TPB>>>();
    k_na<<<(2 * BB + TPB - 1) / TPB, TPB>>>();
    k_pos<<<(BB * 32 + TPB - 1) / TPB, TPB>>>();

    cudaFuncSetAttribute(k_gemm_mma, cudaFuncAttributeMaxDynamicSharedMemorySize, NSTG * STGB);
    dim3 gg(2 * BB / 128, (NN + JT - 1) / JT);   // (16, 235), bm fast for B-tile L2 reuse
    k_gemm_mma<<<gg, 256, NSTG * STGB>>>();
    k_row_exp<<<2 * BB, 256>>>();
    k_final<<<1, 256>>>(out);
}

// round 12
// speedup vs baseline: 5.5552x; 1.1464x over previous
#include <cuda_runtime.h>
#include <cuda_fp16.h>
#include <math.h>
#include <stdint.h>

#define NN 30000
#define RR 1000
#define TT 300000
#define DD 128
#define BB 1024
#define NZ 600000
#define OUTD 768
#define GAMMA_C 3.0f

// ---------------- scratch (device globals) ----------------
__device__ float g_relhat[RR * DD];
__device__ float g_logit[4 * RR];
__device__ float g_m[4 * NN];
__device__ float g_s[4 * NN];                // reciprocal expsum per (channel,row)
__device__ float g_featE[(size_t)NN * DD];
__device__ float g_featR[(size_t)NN * DD];
__device__ float g_degE[NN];
__device__ float g_degR[NN];
__device__ float g_fcurA[(size_t)NN * 256];  // interleaved: [0,128) E, [128,256) R
__device__ float g_fcurB[(size_t)NN * 256];
__device__ __half g_embh[(size_t)NN * OUTD]; // fp16 embedding (GEMM + norms + pos)
__device__ float g_nb[NN];
__device__ int   g_rowptr[NN + 1];
__device__ int   g_cursor[NN];
__device__ int   g_ecol[TT];
__device__ int   g_erel[TT];
__device__ int   g_idxA[2 * BB];
__device__ float g_na[2 * BB];
__device__ float g_pos[BB];
__device__ int   g_lp[BB];
__device__ int   g_rp[BB];
__device__ float g_S[(size_t)2 * BB * NN];
__device__ double g_rsum[2 * BB];
__device__ double g_rsq[2 * BB];
__device__ float  g_rmax[2 * BB];
__device__ float g_lse[2 * BB];

__device__ __forceinline__ float warp_sum(float v) {
#pragma unroll
    for (int o = 16; o > 0; o >>= 1) v += __shfl_xor_sync(0xffffffffu, v, o);
    return v;
}
__device__ __forceinline__ float warp_max(float v) {
#pragma unroll
    for (int o = 16; o > 0; o >>= 1) v = fmaxf(v, __shfl_xor_sync(0xffffffffu, v, o));
    return v;
}
__device__ __forceinline__ void atomicMaxF(float* addr, float v) {
    if (v >= 0.f) atomicMax((int*)addr, __float_as_int(v));
    else          atomicMin((unsigned int*)addr, __float_as_uint(v));
}
__device__ __forceinline__ void redAdd4(float* addr, float4 v) {
    asm volatile("red.global.add.v4.f32 [%0], {%1, %2, %3, %4};"
                 :: "l"(addr), "f"(v.x), "f"(v.y), "f"(v.z), "f"(v.w) : "memory");
}
__device__ __forceinline__ float fast_exp(float x) {
    float t = fmaxf(x * 1.4426950408889634f, -80.0f);
    float fl = floorf(t);
    float f = t - fl;
    float p = 0.0013333558f;
    p = fmaf(p, f, 0.0096181291f);
    p = fmaf(p, f, 0.0555041086f);
    p = fmaf(p, f, 0.2402264476f);
    p = fmaf(p, f, 0.6931471806f);
    p = fmaf(p, f, 1.0f);
    int i = (int)fl;
    return p * __int_as_float((i + 127) << 23);
}
__device__ __forceinline__ uint32_t smem_u32(const void* p) {
    uint32_t a;
    asm("{ .reg .u64 t; cvta.to.shared.u64 t, %1; cvt.u32.u64 %0, t; }" : "=r"(a) : "l"(p));
    return a;
}
__device__ __forceinline__ void cpasync16(uint32_t dst, const void* src) {
    asm volatile("cp.async.cg.shared.global [%0], [%1], 16;" :: "r"(dst), "l"(src));
}
__device__ __forceinline__ void ldsm4(uint32_t* r, uint32_t addr) {
    asm volatile("ldmatrix.sync.aligned.m8n8.x4.shared.b16 {%0,%1,%2,%3}, [%4];"
                 : "=r"(r[0]), "=r"(r[1]), "=r"(r[2]), "=r"(r[3]) : "r"(addr));
}
__device__ __forceinline__ void mma_f16(float* c, const uint32_t* a, const uint32_t* b) {
    asm volatile("mma.sync.aligned.m16n8k16.row.col.f32.f16.f16.f32 "
                 "{%0,%1,%2,%3}, {%4,%5,%6,%7}, {%8,%9}, {%0,%1,%2,%3};"
                 : "+f"(c[0]), "+f"(c[1]), "+f"(c[2]), "+f"(c[3])
                 : "r"(a[0]), "r"(a[1]), "r"(a[2]), "r"(a[3]), "r"(b[0]), "r"(b[1]));
}
// store 4 floats as 4 halfs (8B)
__device__ __forceinline__ void st_half4(__half* dst, float a, float b, float c, float d) {
    __half2 h0 = __floats2half2_rn(a, b);
    __half2 h1 = __floats2half2_rn(c, d);
    *(uint2*)dst = make_uint2(*(uint32_t*)&h0, *(uint32_t*)&h1);
}

// ---------------- init kernels ----------------
__global__ void k_init_feat(int which) {
    size_t gid = (size_t)blockIdx.x * blockDim.x + threadIdx.x;
    size_t stride = (size_t)gridDim.x * blockDim.x;
    float* feat = which ? g_featR : g_featE;
    float* deg = which ? g_degR : g_degE;
    for (size_t i = gid; i < (size_t)NN * DD; i += stride) feat[i] = 0.f;
    for (size_t i = gid; i < NN; i += stride) deg[i] = 0.f;
}
__global__ void k_init_stats() {
    int i = blockIdx.x * blockDim.x + threadIdx.x;
    if (i < 2 * BB) { g_rsum[i] = 0.0; g_rsq[i] = 0.0; g_rmax[i] = -3.0e38f; }
    if (i < NN) g_nb[i] = 0.f;
}
__global__ void k_init_cursor() {
    int i = blockIdx.x * blockDim.x + threadIdx.x;
    if (i < NN) g_cursor[i] = 0;
}

// ---------------- relation prep ----------------
__global__ void k_relprep(const float* __restrict__ rel_emb,
                          const float* __restrict__ attn_e,
                          const float* __restrict__ attn_r) {
    int gid = blockIdx.x * blockDim.x + threadIdx.x;
    int r = gid >> 5;
    if (r >= RR) return;
    int lane = gid & 31;
    int d = lane * 4;
    float4 u = *(const float4*)&rel_emb[(size_t)r * DD + d];
    float ss = u.x * u.x + u.y * u.y + u.z * u.z + u.w * u.w;
    ss = warp_sum(ss);
    float inv = 1.f / fmaxf(sqrtf(ss), 1e-12f);
    u.x *= inv; u.y *= inv; u.z *= inv; u.w *= inv;
    *(float4*)&g_relhat[r * DD + d] = u;
    const float* ks[4] = { attn_e, attn_e + DD, attn_r, attn_r + DD };
#pragma unroll
    for (int c = 0; c < 4; c++) {
        const float4 kk = *(const float4*)&ks[c][d];
        float dot = u.x * kk.x + u.y * kk.y + u.z * kk.z + u.w * kk.w;
        dot = warp_sum(dot);
        if (lane == 0) g_logit[c * RR + r] = dot;
    }
}

// ---------------- CSR build ----------------
__global__ void k_csr_cnt(const int* __restrict__ adj) {
    int t = blockIdx.x * blockDim.x + threadIdx.x;
    if (t >= TT) return;
    atomicAdd(&g_cursor[adj[t]], 1);
}
__global__ void k_scan() {
    __shared__ int sh[1024];
    __shared__ int s_off;
    int tid = threadIdx.x;
    if (tid == 0) s_off = 0;
    __syncthreads();
    for (int base = 0; base < NN; base += 1024) {
        int i = base + tid;
        int v = (i < NN) ? g_cursor[i] : 0;
        sh[tid] = v;
        __syncthreads();
        for (int o = 1; o < 1024; o <<= 1) {
            int t2 = (tid >= o) ? sh[tid - o] : 0;
            __syncthreads();
            sh[tid] += t2;
            __syncthreads();
        }
        int excl = sh[tid] - v;
        if (i < NN) { g_rowptr[i] = s_off + excl; g_cursor[i] = s_off + excl; }
        __syncthreads();
        if (tid == 1023) s_off += sh[1023];
        __syncthreads();
    }
    if (tid == 0) g_rowptr[NN] = s_off;
}
__global__ void k_csr_fill(const int* __restrict__ adj, const int* __restrict__ r_index) {
    int t = blockIdx.x * blockDim.x + threadIdx.x;
    if (t >= TT) return;
    int r = adj[t];
    int pos = atomicAdd(&g_cursor[r], 1);
    g_ecol[pos] = adj[TT + t];
    g_erel[pos] = r_index[TT + t];
}

// ---------------- per-row softmax stats over CSR (no atomics) ----------------
__global__ void k_rowsm() {
    int gid = blockIdx.x * blockDim.x + threadIdx.x;
    int r = gid >> 5;
    if (r >= NN) return;
    int lane = gid & 31;
    int beg = g_rowptr[r], end = g_rowptr[r + 1];
    float m[4] = { -3.0e38f, -3.0e38f, -3.0e38f, -3.0e38f };
    for (int e = beg + lane; e < end; e += 32) {
        int rel = g_erel[e];
#pragma unroll
        for (int c = 0; c < 4; c++) m[c] = fmaxf(m[c], g_logit[c * RR + rel]);
    }
#pragma unroll
    for (int c = 0; c < 4; c++) m[c] = warp_max(m[c]);
    float s[4] = { 0.f, 0.f, 0.f, 0.f };
    for (int e = beg + lane; e < end; e += 32) {
        int rel = g_erel[e];
#pragma unroll
        for (int c = 0; c < 4; c++) s[c] += fast_exp(g_logit[c * RR + rel] - m[c]);
    }
#pragma unroll
    for (int c = 0; c < 4; c++) {
        s[c] = warp_sum(s[c]);
        if (lane == 0) {
            g_m[c * NN + r] = m[c];
            g_s[c * NN + r] = (s[c] > 0.f) ? 1.f / s[c] : 0.f;
        }
    }
}

// ---------------- neighbor-average features (scatter, unchanged) ----------------
__global__ void k_deg(const int* __restrict__ eadj, int which) {
    int e = blockIdx.x * blockDim.x + threadIdx.x;
    if (e >= NZ) return;
    float* deg = which ? g_degR : g_degE;
    atomicAdd(&deg[eadj[e]], 1.f);
}
__global__ void k_avg_scatter(const int* __restrict__ eadj,
                              const float* __restrict__ src, int which) {
    int gid = blockIdx.x * blockDim.x + threadIdx.x;
    int e = gid >> 5;
    if (e >= NZ) return;
    int d = (gid & 31) * 4;
    int row = eadj[e], col = eadj[NZ + e];
    float* feat = which ? g_featR : g_featE;
    const float4 v = *(const float4*)&src[(size_t)col * DD + d];
    redAdd4(&feat[(size_t)row * DD + d], v);
}

// ---------------- initial tanh: div + tanh + fcurA + embh + nb ----------------
__global__ void k_tanh0() {
    int gid = blockIdx.x * blockDim.x + threadIdx.x;
    int n = gid >> 5;
    if (n >= NN) return;
    int lane = gid & 31;
    int d = lane * 4;
    float dE = g_degE[n], dR = g_degR[n];
    float iE = (dE > 0.f) ? 1.f / dE : 0.f;
    float iR = (dR > 0.f) ? 1.f / dR : 0.f;
    float4 fe = *(const float4*)&g_featE[(size_t)n * DD + d];
    float4 fr = *(const float4*)&g_featR[(size_t)n * DD + d];
    float vE0 = tanhf(fe.x * iE), vE1 = tanhf(fe.y * iE), vE2 = tanhf(fe.z * iE), vE3 = tanhf(fe.w * iE);
    float vR0 = tanhf(fr.x * iR), vR1 = tanhf(fr.y * iR), vR2 = tanhf(fr.z * iR), vR3 = tanhf(fr.w * iR);
    *(float4*)&g_fcurA[(size_t)n * 256 + d] = make_float4(vE0, vE1, vE2, vE3);
    *(float4*)&g_fcurA[(size_t)n * 256 + 128 + d] = make_float4(vR0, vR1, vR2, vR3);
    __half* hrow = &g_embh[(size_t)n * OUTD];
    st_half4(hrow + d, vE0, vE1, vE2, vE3);
    st_half4(hrow + 384 + d, vR0, vR1, vR2, vR3);
    // nb from fp16-rounded values (consistent with GEMM)
    float ss = 0.f;
    float q[8] = { vE0, vE1, vE2, vE3, vR0, vR1, vR2, vR3 };
#pragma unroll
    for (int k = 0; k < 8; k++) {
        float qq = __half2float(__float2half_rn(q[k]));
        ss += qq * qq;
    }
    ss = warp_sum(ss);
    if (lane == 0) atomicAdd(&g_nb[n], ss);
}

// ---------------- GAT layer: warp-per-row gather over CSR ----------------
__global__ void k_gat_layer(int l, int dir /*0: A->B, 1: B->A*/) {
    int gid = blockIdx.x * blockDim.x + threadIdx.x;
    int r = gid >> 5;
    if (r >= NN) return;
    int lane = gid & 31;
    int d = lane * 4;
    const float* src = dir ? g_fcurB : g_fcurA;
    float* dst = dir ? g_fcurA : g_fcurB;
    int beg = g_rowptr[r], end = g_rowptr[r + 1];
    const int cE = l, cR = 2 + l;
    const float mE = g_m[cE * NN + r], siE = g_s[cE * NN + r];
    const float mR = g_m[cR * NN + r], siR = g_s[cR * NN + r];
    float4 accE = make_float4(0, 0, 0, 0), accR = make_float4(0, 0, 0, 0);
    for (int e = beg; e < end; e++) {
        int col = __ldg(&g_ecol[e]);
        int rel = __ldg(&g_erel[e]);
        float4 u = *(const float4*)&g_relhat[rel * DD + d];
        float4 xE = *(const float4*)&src[(size_t)col * 256 + d];
        float4 xR = *(const float4*)&src[(size_t)col * 256 + 128 + d];
        float dotE = warp_sum(xE.x * u.x + xE.y * u.y + xE.z * u.z + xE.w * u.w);
        float dotR = warp_sum(xR.x * u.x + xR.y * u.y + xR.z * u.z + xR.w * u.w);
        float wE = fast_exp(g_logit[cE * RR + rel] - mE) * siE;
        float wR = fast_exp(g_logit[cR * RR + rel] - mR) * siR;
        float sE = 2.f * dotE, sR = 2.f * dotR;
        accE.x += wE * (xE.x - sE * u.x); accE.y += wE * (xE.y - sE * u.y);
        accE.z += wE * (xE.z - sE * u.z); accE.w += wE * (xE.w - sE * u.w);
        accR.x += wR * (xR.x - sR * u.x); accR.y += wR * (xR.y - sR * u.y);
        accR.z += wR * (xR.z - sR * u.z); accR.w += wR * (xR.w - sR * u.w);
    }
    float vE0 = tanhf(accE.x), vE1 = tanhf(accE.y), vE2 = tanhf(accE.z), vE3 = tanhf(accE.w);
    float vR0 = tanhf(accR.x), vR1 = tanhf(accR.y), vR2 = tanhf(accR.z), vR3 = tanhf(accR.w);
    *(float4*)&dst[(size_t)r * 256 + d] = make_float4(vE0, vE1, vE2, vE3);
    *(float4*)&dst[(size_t)r * 256 + 128 + d] = make_float4(vR0, vR1, vR2, vR3);
    int base = (l + 1) * DD;
    __half* hrow = &g_embh[(size_t)r * OUTD];
    st_half4(hrow + base + d, vE0, vE1, vE2, vE3);
    st_half4(hrow + 384 + base + d, vR0, vR1, vR2, vR3);
    float ss = 0.f;
    float q[8] = { vE0, vE1, vE2, vE3, vR0, vR1, vR2, vR3 };
#pragma unroll
    for (int k = 0; k < 8; k++) {
        float qq = __half2float(__float2half_rn(q[k]));
        ss += qq * qq;
    }
    ss = warp_sum(ss);
    if (lane == 0) atomicAdd(&g_nb[r], ss);
}

// ---------------- loss prep ----------------
__global__ void k_prep_pairs(const int* __restrict__ pairs) {
    int p = blockIdx.x * blockDim.x + threadIdx.x;
    if (p >= BB) return;
    int lp = pairs[2 * p], rp = pairs[2 * p + 1];
    g_lp[p] = lp; g_rp[p] = rp;
    g_idxA[p] = lp; g_idxA[BB + p] = rp;
}
__global__ void k_na() {
    int i = blockIdx.x * blockDim.x + threadIdx.x;
    if (i >= 2 * BB) return;
    g_na[i] = g_nb[g_idxA[i]];
}
__global__ void k_pos() {
    int gid = blockIdx.x * blockDim.x + threadIdx.x;
    int p = gid >> 5;
    if (p >= BB) return;
    int lane = gid & 31;
    const __half* a = &g_embh[(size_t)g_lp[p] * OUTD];
    const __half* b = &g_embh[(size_t)g_rp[p] * OUTD];
    float ss = 0.f;
    for (int k = lane * 4; k < OUTD; k += 128) {
        uint2 ua = *(const uint2*)&a[k];
        uint2 ub = *(const uint2*)&b[k];
        float2 a0 = __half22float2(*(__half2*)&ua.x);
        float2 a1 = __half22float2(*(__half2*)&ua.y);
        float2 b0 = __half22float2(*(__half2*)&ub.x);
        float2 b1 = __half22float2(*(__half2*)&ub.y);
        float d0 = a0.x - b0.x, d1 = a0.y - b0.y, d2 = a1.x - b1.x, d3 = a1.y - b1.y;
        ss += d0 * d0 + d1 * d1 + d2 * d2 + d3 * d3;
    }
    ss = warp_sum(ss);
    if (lane == 0) g_pos[p] = ss;
}

// ---------------- mma.sync fp16 GEMM (128x128) + loss + stats ----------------
#define JT 128
#define NS (OUTD / 16)         // 48 k-stages
#define ROWB 48
#define STG_A 0
#define STG_B 6144
#define STGB 12288
#define NSTG 4

__global__ __launch_bounds__(256, 2) void k_gemm_mma() {
    extern __shared__ char dynsmem[];
    __shared__ int s_idx[128];
    const int tid = threadIdx.x;
    const int wid = tid >> 5;
    const int lane = tid & 31;
    const int warp_m = wid & 1;
    const int warp_n = wid >> 1;
    const int bm = blockIdx.x;
    const int jbase = blockIdx.y * JT;
    const uint32_t sbase = smem_u32(dynsmem);

    if (tid < 128) s_idx[tid] = g_idxA[bm * 128 + tid];
    __syncthreads();

    const int lrow = tid >> 1;
    const int lhalf = tid & 1;
    int jld = jbase + lrow;
    if (jld >= NN) jld = 0;
    const __half* gaPtr = g_embh + (size_t)s_idx[lrow] * OUTD + lhalf * 8;
    const __half* gbPtr = g_embh + (size_t)jld * OUTD + lhalf * 8;
    const uint32_t dOff = lrow * ROWB + lhalf * 16;

#pragma unroll
    for (int p = 0; p < 3; p++) {
        uint32_t sb = sbase + p * STGB;
        cpasync16(sb + STG_A + dOff, gaPtr + p * 16);
        cpasync16(sb + STG_B + dOff, gbPtr + p * 16);
        asm volatile("cp.async.commit_group;" ::: "memory");
    }

    float acc[4][4][4] = {};
    const int rsel = lane & 15;
    const int csel = (lane >> 4) * 16;

    for (int it = 0; it < NS; it++) {
        if (it < NS - 2)       asm volatile("cp.async.wait_group 2;" ::: "memory");
        else if (it == NS - 2) asm volatile("cp.async.wait_group 1;" ::: "memory");
        else                   asm volatile("cp.async.wait_group 0;" ::: "memory");
        __syncthreads();

        if (it + 3 < NS) {
            uint32_t sb = sbase + ((it + 3) & 3) * STGB;
            cpasync16(sb + STG_A + dOff, gaPtr + (it + 3) * 16);
            cpasync16(sb + STG_B + dOff, gbPtr + (it + 3) * 16);
            asm volatile("cp.async.commit_group;" ::: "memory");
        }

        const uint32_t sb = sbase + (it & 3) * STGB;
        uint32_t aF[4][4], bF[4][2];
#pragma unroll
        for (int mt = 0; mt < 4; mt++) {
            uint32_t ad = sb + STG_A + (uint32_t)((warp_m * 64 + mt * 16 + rsel) * ROWB + csel);
            ldsm4(aF[mt], ad);
        }
#pragma unroll
        for (int tp = 0; tp < 2; tp++) {
            uint32_t bd = sb + STG_B + (uint32_t)((warp_n * 32 + tp * 16 + rsel) * ROWB + csel);
            uint32_t r[4];
            ldsm4(r, bd);
            bF[tp * 2][0] = r[0]; bF[tp * 2][1] = r[2];
            bF[tp * 2 + 1][0] = r[1]; bF[tp * 2 + 1][1] = r[3];
        }
#pragma unroll
        for (int mt = 0; mt < 4; mt++)
#pragma unroll
            for (int nt = 0; nt < 4; nt++)
                mma_f16(acc[mt][nt], aF[mt], bF[nt]);
    }

    const int lq = lane >> 2;
    const int lr = lane & 3;
    float2 nbv[4];
#pragma unroll
    for (int nt = 0; nt < 4; nt++) {
        int j0 = jbase + warp_n * 32 + nt * 8 + 2 * lr;
        nbv[nt].x = (j0 < NN) ? g_nb[j0] : 0.f;
        nbv[nt].y = (j0 + 1 < NN) ? g_nb[j0 + 1] : 0.f;
    }
#pragma unroll
    for (int mt = 0; mt < 4; mt++) {
#pragma unroll
        for (int h = 0; h < 2; h++) {
            const int i = bm * 128 + warp_m * 64 + mt * 16 + lq + h * 8;
            const int p = i & (BB - 1);
            const float base = g_pos[p] - g_na[i] + GAMMA_C;
            const int lp = g_lp[p], rp = g_rp[p];
            float s = 0.f, q = 0.f, mx = -3.0e38f;
            float* srow = &g_S[(size_t)i * NN];
#pragma unroll
            for (int nt = 0; nt < 4; nt++) {
                int j0 = jbase + warp_n * 32 + nt * 8 + 2 * lr;
                float c0 = acc[mt][nt][h * 2 + 0];
                float c1 = acc[mt][nt][h * 2 + 1];
                if (j0 + 1 < NN) {
                    float v0 = (base - nbv[nt].x + 2.f * c0) *
                               (1.f - (float)(j0 == lp) - (float)(j0 == rp));
                    float v1 = (base - nbv[nt].y + 2.f * c1) *
                               (1.f - (float)(j0 + 1 == lp) - (float)(j0 + 1 == rp));
                    *(float2*)&srow[j0] = make_float2(v0, v1);
                    s += v0 + v1; q += v0 * v0 + v1 * v1;
                    mx = fmaxf(mx, fmaxf(v0, v1));
                } else if (j0 < NN) {
                    float v0 = (base - nbv[nt].x + 2.f * c0) *
                               (1.f - (float)(j0 == lp) - (float)(j0 == rp));
                    srow[j0] = v0;
                    s += v0; q += v0 * v0; mx = fmaxf(mx, v0);
                }
            }
#pragma unroll
            for (int o = 1; o <= 2; o <<= 1) {
                s += __shfl_xor_sync(0xffffffffu, s, o);
                q += __shfl_xor_sync(0xffffffffu, q, o);
                mx = fmaxf(mx, __shfl_xor_sync(0xffffffffu, mx, o));
            }
            if (lr == 0) {
                atomicAdd(&g_rsum[i], (double)s);
                atomicAdd(&g_rsq[i], (double)q);
                atomicMaxF(&g_rmax[i], mx);
            }
        }
    }
}

// ---------------- per-row logsumexp ----------------
__global__ void k_row_exp() {
    int i = blockIdx.x;
    int tid = threadIdx.x;
    double mu_d = g_rsum[i] / NN;
    double var = g_rsq[i] / NN - mu_d * mu_d;
    if (var < 0.0) var = 0.0;
    double sd = sqrt(var);
    float mu = (float)mu_d;
    float inv = (float)(20.0 / sd);
    float zmax = (float)((g_rmax[i] - mu_d) * (20.0 / sd)) + 8.f;
    const float4* row4 = (const float4*)&g_S[(size_t)i * NN];
    float cterm = 8.f - zmax - mu * inv;
    float es = 0.f;
    for (int j = tid; j < NN / 4; j += 256) {
        float4 v = row4[j];
        es += fast_exp(fmaf(v.x, inv, cterm));
        es += fast_exp(fmaf(v.y, inv, cterm));
        es += fast_exp(fmaf(v.z, inv, cterm));
        es += fast_exp(fmaf(v.w, inv, cterm));
    }
    __shared__ float sh[256];
    sh[tid] = es;
    __syncthreads();
    for (int o = 128; o > 0; o >>= 1) {
        if (tid < o) sh[tid] += sh[tid + o];
        __syncthreads();
    }
    if (tid == 0) g_lse[i] = zmax + logf(sh[0]);
}

__global__ void k_final(float* out) {
    int tid = threadIdx.x;
    double acc = 0.0;
    for (int p = tid; p < BB; p += 256) acc += (double)g_lse[p] + (double)g_lse[BB + p];
    __shared__ double sh[256];
    sh[tid] = acc;
    __syncthreads();
    for (int o = 128; o > 0; o >>= 1) {
        if (tid < o) sh[tid] += sh[tid + o];
        __syncthreads();
    }
    if (tid == 0) out[0] = (float)(sh[0] / BB);
}

// ---------------- driver ----------------
extern "C" void kernel_launch(void* const* d_in, const int* in_sizes, int n_in,
                              void* d_out, int out_size) {
    const float* ent_emb = (const float*)d_in[0];
    const float* rel_emb = (const float*)d_in[1];
    const float* attn_e  = (const float*)d_in[2];
    const float* attn_r  = (const float*)d_in[3];
    const int* adj     = (const int*)d_in[5];
    const int* r_index = (const int*)d_in[6];
    const int* ent_adj = (const int*)d_in[7];
    const int* rel_adj = (const int*)d_in[8];
    const int* pairs   = (const int*)d_in[9];
    float* out = (float*)d_out;

    static cudaStream_t sA = 0, sB = 0, sC = 0;
    static cudaEvent_t evRoot = 0, evA = 0, evB = 0, evC = 0;
    static bool sinit = false;
    if (!sinit) {
        cudaStreamCreateWithFlags(&sA, cudaStreamNonBlocking);
        cudaStreamCreateWithFlags(&sB, cudaStreamNonBlocking);
        cudaStreamCreateWithFlags(&sC, cudaStreamNonBlocking);
        cudaEventCreateWithFlags(&evRoot, cudaEventDisableTiming);
        cudaEventCreateWithFlags(&evA, cudaEventDisableTiming);
        cudaEventCreateWithFlags(&evB, cudaEventDisableTiming);
        cudaEventCreateWithFlags(&evC, cudaEventDisableTiming);
        sinit = true;
    }

    const int TPB = 256;
    const int gW_NZ = (NZ * 32 + TPB - 1) / TPB;
    const int gT    = (TT + TPB - 1) / TPB;
    const int gNZ1  = (NZ + TPB - 1) / TPB;
    const int gWN   = (NN * 32 + TPB - 1) / TPB;   // warp per node/row

    k_init_stats<<<(NN + TPB - 1) / TPB, TPB>>>();
    k_prep_pairs<<<(BB + TPB - 1) / TPB, TPB>>>(pairs);
    cudaEventRecord(evRoot, 0);
    cudaStreamWaitEvent(sA, evRoot, 0);
    cudaStreamWaitEvent(sB, evRoot, 0);
    cudaStreamWaitEvent(sC, evRoot, 0);

    // chain A: relation prep + CSR build + per-row softmax stats
    k_relprep<<<(RR * 32 + TPB - 1) / TPB, TPB, 0, sA>>>(rel_emb, attn_e, attn_r);
    k_init_cursor<<<(NN + TPB - 1) / TPB, TPB, 0, sA>>>();
    k_csr_cnt<<<gT, TPB, 0, sA>>>(adj);
    k_scan<<<1, 1024, 0, sA>>>();
    k_csr_fill<<<gT, TPB, 0, sA>>>(adj, r_index);
    k_rowsm<<<gWN, TPB, 0, sA>>>();
    cudaEventRecord(evA, sA);

    // chain B: entity averaging (div folded into tanh0)
    k_init_feat<<<2048, TPB, 0, sB>>>(0);
    k_deg<<<gNZ1, TPB, 0, sB>>>(ent_adj, 0);
    k_avg_scatter<<<gW_NZ, TPB, 0, sB>>>(ent_adj, ent_emb, 0);
    cudaEventRecord(evB, sB);

    // chain C: relation averaging
    k_init_feat<<<2048, TPB, 0, sC>>>(1);
    k_deg<<<gNZ1, TPB, 0, sC>>>(rel_adj, 1);
    k_avg_scatter<<<gW_NZ, TPB, 0, sC>>>(rel_adj, rel_emb, 1);
    cudaEventRecord(evC, sC);

    // join: tanh0 needs averages; layers additionally need chain A
    cudaStreamWaitEvent(0, evB, 0);
    cudaStreamWaitEvent(0, evC, 0);
    k_tanh0<<<gWN, TPB>>>();
    cudaStreamWaitEvent(0, evA, 0);
    k_gat_layer<<<gWN, TPB>>>(0, 0);   // fcurA -> fcurB
    k_gat_layer<<<gWN, TPB>>>(1, 1);   // fcurB -> fcurA

    k_na<<<(2 * BB + TPB - 1) / TPB, TPB>>>();
    k_pos<<<(BB * 32 + TPB - 1) / TPB, TPB>>>();

    cudaFuncSetAttribute(k_gemm_mma, cudaFuncAttributeMaxDynamicSharedMemorySize, NSTG * STGB);
    dim3 gg(2 * BB / 128, (NN + JT - 1) / JT);
    k_gemm_mma<<<gg, 256, NSTG * STGB>>>();
    k_row_exp<<<2 * BB, 256>>>();
    k_final<<<1, 256>>>(out);
}

// round 13
// speedup vs baseline: 6.0062x; 1.0812x over previous
#include <cuda_runtime.h>
#include <cuda_fp16.h>
#include <math.h>
#include <stdint.h>

#define NN 30000
#define RR 1000
#define TT 300000
#define DD 128
#define BB 1024
#define NZ 600000
#define OUTD 768
#define GAMMA_C 3.0f

// ---------------- scratch (device globals) ----------------
__device__ float g_relhat[RR * DD];
__device__ float g_logit[4 * RR];
__device__ float g_m[4 * NN];
__device__ float g_s[4 * NN];
__device__ float g_featE[(size_t)NN * DD];
__device__ float g_featR[(size_t)NN * DD];
__device__ float g_fcurA[(size_t)NN * 256];  // interleaved: [0,128) E, [128,256) R
__device__ float g_fcurB[(size_t)NN * 256];
__device__ __half g_embh[(size_t)NN * OUTD];
__device__ float g_nb[NN];
// adjacency CSR (GAT graph)
__device__ int g_rowptr[NN + 1];
__device__ int g_cursor[NN];
__device__ int g_ecol[TT];
__device__ int g_erel[TT];
// averaging CSRs
__device__ int g_rowptrE[NN + 1];
__device__ int g_curE[NN];
__device__ int g_ecolE[NZ];
__device__ int g_rowptrR[NN + 1];
__device__ int g_curR[NN];
__device__ int g_ecolR[NZ];
// loss
__device__ int   g_idxA[2 * BB];
__device__ float g_na[2 * BB];
__device__ float g_pos[BB];
__device__ int   g_lp[BB];
__device__ int   g_rp[BB];
__device__ float g_S[(size_t)2 * BB * NN];
__device__ double g_rsum[2 * BB];
__device__ double g_rsq[2 * BB];
__device__ float  g_rmax[2 * BB];
__device__ float g_lse[2 * BB];

__device__ __forceinline__ float warp_sum(float v) {
#pragma unroll
    for (int o = 16; o > 0; o >>= 1) v += __shfl_xor_sync(0xffffffffu, v, o);
    return v;
}
__device__ __forceinline__ float warp_max(float v) {
#pragma unroll
    for (int o = 16; o > 0; o >>= 1) v = fmaxf(v, __shfl_xor_sync(0xffffffffu, v, o));
    return v;
}
__device__ __forceinline__ void atomicMaxF(float* addr, float v) {
    if (v >= 0.f) atomicMax((int*)addr, __float_as_int(v));
    else          atomicMin((unsigned int*)addr, __float_as_uint(v));
}
__device__ __forceinline__ float fast_exp(float x) {
    float t = fmaxf(x * 1.4426950408889634f, -80.0f);
    float fl = floorf(t);
    float f = t - fl;
    float p = 0.0013333558f;
    p = fmaf(p, f, 0.0096181291f);
    p = fmaf(p, f, 0.0555041086f);
    p = fmaf(p, f, 0.2402264476f);
    p = fmaf(p, f, 0.6931471806f);
    p = fmaf(p, f, 1.0f);
    int i = (int)fl;
    return p * __int_as_float((i + 127) << 23);
}
__device__ __forceinline__ uint32_t smem_u32(const void* p) {
    uint32_t a;
    asm("{ .reg .u64 t; cvta.to.shared.u64 t, %1; cvt.u32.u64 %0, t; }" : "=r"(a) : "l"(p));
    return a;
}
__device__ __forceinline__ void cpasync16(uint32_t dst, const void* src) {
    asm volatile("cp.async.cg.shared.global [%0], [%1], 16;" :: "r"(dst), "l"(src));
}
__device__ __forceinline__ void ldsm4(uint32_t* r, uint32_t addr) {
    asm volatile("ldmatrix.sync.aligned.m8n8.x4.shared.b16 {%0,%1,%2,%3}, [%4];"
                 : "=r"(r[0]), "=r"(r[1]), "=r"(r[2]), "=r"(r[3]) : "r"(addr));
}
__device__ __forceinline__ void mma_f16(float* c, const uint32_t* a, const uint32_t* b) {
    asm volatile("mma.sync.aligned.m16n8k16.row.col.f32.f16.f16.f32 "
                 "{%0,%1,%2,%3}, {%4,%5,%6,%7}, {%8,%9}, {%0,%1,%2,%3};"
                 : "+f"(c[0]), "+f"(c[1]), "+f"(c[2]), "+f"(c[3])
                 : "r"(a[0]), "r"(a[1]), "r"(a[2]), "r"(a[3]), "r"(b[0]), "r"(b[1]));
}
__device__ __forceinline__ void st_half4(__half* dst, float a, float b, float c, float d) {
    __half2 h0 = __floats2half2_rn(a, b);
    __half2 h1 = __floats2half2_rn(c, d);
    *(uint2*)dst = make_uint2(*(uint32_t*)&h0, *(uint32_t*)&h1);
}

__device__ __forceinline__ int* cursor_of(int w) {
    return (w == 0) ? g_cursor : (w == 1) ? g_curE : g_curR;
}
__device__ __forceinline__ int* rowptr_of(int w) {
    return (w == 0) ? g_rowptr : (w == 1) ? g_rowptrE : g_rowptrR;
}

// ---------------- init (pre-fork; zeroes all cursors + stats) ----------------
__global__ void k_init_stats() {
    int i = blockIdx.x * blockDim.x + threadIdx.x;
    if (i < NN) { g_nb[i] = 0.f; g_cursor[i] = 0; g_curE[i] = 0; g_curR[i] = 0; }
    if (i < 2 * BB) { g_rsum[i] = 0.0; g_rsq[i] = 0.0; g_rmax[i] = -3.0e38f; }
}

// ---------------- relation prep ----------------
__global__ void k_relprep(const float* __restrict__ rel_emb,
                          const float* __restrict__ attn_e,
                          const float* __restrict__ attn_r) {
    int gid = blockIdx.x * blockDim.x + threadIdx.x;
    int r = gid >> 5;
    if (r >= RR) return;
    int lane = gid & 31;
    int d = lane * 4;
    float4 u = *(const float4*)&rel_emb[(size_t)r * DD + d];
    float ss = u.x * u.x + u.y * u.y + u.z * u.z + u.w * u.w;
    ss = warp_sum(ss);
    float inv = 1.f / fmaxf(sqrtf(ss), 1e-12f);
    u.x *= inv; u.y *= inv; u.z *= inv; u.w *= inv;
    *(float4*)&g_relhat[r * DD + d] = u;
    const float* ks[4] = { attn_e, attn_e + DD, attn_r, attn_r + DD };
#pragma unroll
    for (int c = 0; c < 4; c++) {
        const float4 kk = *(const float4*)&ks[c][d];
        float dot = u.x * kk.x + u.y * kk.y + u.z * kk.z + u.w * kk.w;
        dot = warp_sum(dot);
        if (lane == 0) g_logit[c * RR + r] = dot;
    }
}

// ---------------- CSR build (generic) ----------------
__global__ void k_csr_cnt(const int* __restrict__ rows, int n, int w) {
    int t = blockIdx.x * blockDim.x + threadIdx.x;
    if (t >= n) return;
    atomicAdd(&cursor_of(w)[rows[t]], 1);
}
// two-level warp-shuffle scan over NN elements; writes rowptr and resets cursor to offsets
__global__ void k_scan(int w) {
    int* cur = cursor_of(w);
    int* rp = rowptr_of(w);
    __shared__ int warpsum[32];
    __shared__ int s_off;
    int tid = threadIdx.x, lane = tid & 31, wd = tid >> 5;
    if (tid == 0) s_off = 0;
    __syncthreads();
    for (int base = 0; base < NN; base += 1024) {
        int i = base + tid;
        int v = (i < NN) ? cur[i] : 0;
        int x = v;
#pragma unroll
        for (int o = 1; o < 32; o <<= 1) {
            int t2 = __shfl_up_sync(0xffffffffu, x, o);
            if (lane >= o) x += t2;
        }
        if (lane == 31) warpsum[wd] = x;
        __syncthreads();
        if (wd == 0) {
            int y = warpsum[lane];
#pragma unroll
            for (int o = 1; o < 32; o <<= 1) {
                int t2 = __shfl_up_sync(0xffffffffu, y, o);
                if (lane >= o) y += t2;
            }
            warpsum[lane] = y;
        }
        __syncthreads();
        int excl = x - v + (wd > 0 ? warpsum[wd - 1] : 0) + s_off;
        if (i < NN) { rp[i] = excl; cur[i] = excl; }
        __syncthreads();
        if (tid == 1023) s_off = excl + v;
        __syncthreads();
    }
    if (tid == 0) rp[NN] = s_off;
}
__global__ void k_fill_adj(const int* __restrict__ adj, const int* __restrict__ r_index) {
    int t = blockIdx.x * blockDim.x + threadIdx.x;
    if (t >= TT) return;
    int pos = atomicAdd(&g_cursor[adj[t]], 1);
    g_ecol[pos] = adj[TT + t];
    g_erel[pos] = r_index[TT + t];
}
__global__ void k_fill_avg(const int* __restrict__ eadj, int w) {
    int t = blockIdx.x * blockDim.x + threadIdx.x;
    if (t >= NZ) return;
    int* cur = (w == 1) ? g_curE : g_curR;
    int* ec = (w == 1) ? g_ecolE : g_ecolR;
    int pos = atomicAdd(&cur[eadj[t]], 1);
    ec[pos] = eadj[NZ + t];
}

// ---------------- per-row softmax stats ----------------
__global__ void k_rowsm() {
    int gid = blockIdx.x * blockDim.x + threadIdx.x;
    int r = gid >> 5;
    if (r >= NN) return;
    int lane = gid & 31;
    int beg = g_rowptr[r], end = g_rowptr[r + 1];
    float m[4] = { -3.0e38f, -3.0e38f, -3.0e38f, -3.0e38f };
    for (int e = beg + lane; e < end; e += 32) {
        int rel = g_erel[e];
#pragma unroll
        for (int c = 0; c < 4; c++) m[c] = fmaxf(m[c], g_logit[c * RR + rel]);
    }
#pragma unroll
    for (int c = 0; c < 4; c++) m[c] = warp_max(m[c]);
    float s[4] = { 0.f, 0.f, 0.f, 0.f };
    for (int e = beg + lane; e < end; e += 32) {
        int rel = g_erel[e];
#pragma unroll
        for (int c = 0; c < 4; c++) s[c] += fast_exp(g_logit[c * RR + rel] - m[c]);
    }
#pragma unroll
    for (int c = 0; c < 4; c++) {
        s[c] = warp_sum(s[c]);
        if (lane == 0) {
            g_m[c * NN + r] = m[c];
            g_s[c * NN + r] = (s[c] > 0.f) ? 1.f / s[c] : 0.f;
        }
    }
}

// ---------------- neighbor-average: warp-per-row gather (no atomics) ----------------
__global__ void k_avg_gather(const float* __restrict__ src, int w /*1=E, 2=R*/) {
    int gid = blockIdx.x * blockDim.x + threadIdx.x;
    int r = gid >> 5;
    if (r >= NN) return;
    int lane = gid & 31;
    int d = lane * 4;
    const int* rp = (w == 1) ? g_rowptrE : g_rowptrR;
    const int* ec = (w == 1) ? g_ecolE : g_ecolR;
    float* feat = (w == 1) ? g_featE : g_featR;
    int beg = rp[r], end = rp[r + 1];
    float4 acc = make_float4(0, 0, 0, 0);
    for (int e = beg; e < end; e++) {
        int c = __ldg(&ec[e]);
        float4 v = *(const float4*)&src[(size_t)c * DD + d];
        acc.x += v.x; acc.y += v.y; acc.z += v.z; acc.w += v.w;
    }
    float inv = (end > beg) ? 1.f / (float)(end - beg) : 0.f;
    acc.x *= inv; acc.y *= inv; acc.z *= inv; acc.w *= inv;
    *(float4*)&feat[(size_t)r * DD + d] = acc;
}

// ---------------- initial tanh: tanh + fcurA + embh + nb ----------------
__global__ void k_tanh0() {
    int gid = blockIdx.x * blockDim.x + threadIdx.x;
    int n = gid >> 5;
    if (n >= NN) return;
    int lane = gid & 31;
    int d = lane * 4;
    float4 fe = *(const float4*)&g_featE[(size_t)n * DD + d];
    float4 fr = *(const float4*)&g_featR[(size_t)n * DD + d];
    float vE0 = tanhf(fe.x), vE1 = tanhf(fe.y), vE2 = tanhf(fe.z), vE3 = tanhf(fe.w);
    float vR0 = tanhf(fr.x), vR1 = tanhf(fr.y), vR2 = tanhf(fr.z), vR3 = tanhf(fr.w);
    *(float4*)&g_fcurA[(size_t)n * 256 + d] = make_float4(vE0, vE1, vE2, vE3);
    *(float4*)&g_fcurA[(size_t)n * 256 + 128 + d] = make_float4(vR0, vR1, vR2, vR3);
    __half* hrow = &g_embh[(size_t)n * OUTD];
    st_half4(hrow + d, vE0, vE1, vE2, vE3);
    st_half4(hrow + 384 + d, vR0, vR1, vR2, vR3);
    float ss = 0.f;
    float q[8] = { vE0, vE1, vE2, vE3, vR0, vR1, vR2, vR3 };
#pragma unroll
    for (int k = 0; k < 8; k++) {
        float qq = __half2float(__float2half_rn(q[k]));
        ss += qq * qq;
    }
    ss = warp_sum(ss);
    if (lane == 0) atomicAdd(&g_nb[n], ss);
}

// ---------------- GAT layer: warp-per-row gather over CSR ----------------
__global__ void k_gat_layer(int l, int dir) {
    int gid = blockIdx.x * blockDim.x + threadIdx.x;
    int r = gid >> 5;
    if (r >= NN) return;
    int lane = gid & 31;
    int d = lane * 4;
    const float* src = dir ? g_fcurB : g_fcurA;
    float* dst = dir ? g_fcurA : g_fcurB;
    int beg = g_rowptr[r], end = g_rowptr[r + 1];
    const int cE = l, cR = 2 + l;
    const float mE = g_m[cE * NN + r], siE = g_s[cE * NN + r];
    const float mR = g_m[cR * NN + r], siR = g_s[cR * NN + r];
    float4 accE = make_float4(0, 0, 0, 0), accR = make_float4(0, 0, 0, 0);
    for (int e = beg; e < end; e++) {
        int col = __ldg(&g_ecol[e]);
        int rel = __ldg(&g_erel[e]);
        float4 u = *(const float4*)&g_relhat[rel * DD + d];
        float4 xE = *(const float4*)&src[(size_t)col * 256 + d];
        float4 xR = *(const float4*)&src[(size_t)col * 256 + 128 + d];
        float dotE = warp_sum(xE.x * u.x + xE.y * u.y + xE.z * u.z + xE.w * u.w);
        float dotR = warp_sum(xR.x * u.x + xR.y * u.y + xR.z * u.z + xR.w * u.w);
        float wE = fast_exp(g_logit[cE * RR + rel] - mE) * siE;
        float wR = fast_exp(g_logit[cR * RR + rel] - mR) * siR;
        float sE = 2.f * dotE, sR = 2.f * dotR;
        accE.x += wE * (xE.x - sE * u.x); accE.y += wE * (xE.y - sE * u.y);
        accE.z += wE * (xE.z - sE * u.z); accE.w += wE * (xE.w - sE * u.w);
        accR.x += wR * (xR.x - sR * u.x); accR.y += wR * (xR.y - sR * u.y);
        accR.z += wR * (xR.z - sR * u.z); accR.w += wR * (xR.w - sR * u.w);
    }
    float vE0 = tanhf(accE.x), vE1 = tanhf(accE.y), vE2 = tanhf(accE.z), vE3 = tanhf(accE.w);
    float vR0 = tanhf(accR.x), vR1 = tanhf(accR.y), vR2 = tanhf(accR.z), vR3 = tanhf(accR.w);
    *(float4*)&dst[(size_t)r * 256 + d] = make_float4(vE0, vE1, vE2, vE3);
    *(float4*)&dst[(size_t)r * 256 + 128 + d] = make_float4(vR0, vR1, vR2, vR3);
    int base = (l + 1) * DD;
    __half* hrow = &g_embh[(size_t)r * OUTD];
    st_half4(hrow + base + d, vE0, vE1, vE2, vE3);
    st_half4(hrow + 384 + base + d, vR0, vR1, vR2, vR3);
    float ss = 0.f;
    float q[8] = { vE0, vE1, vE2, vE3, vR0, vR1, vR2, vR3 };
#pragma unroll
    for (int k = 0; k < 8; k++) {
        float qq = __half2float(__float2half_rn(q[k]));
        ss += qq * qq;
    }
    ss = warp_sum(ss);
    if (lane == 0) atomicAdd(&g_nb[r], ss);
}

// ---------------- loss prep ----------------
__global__ void k_prep_pairs(const int* __restrict__ pairs) {
    int p = blockIdx.x * blockDim.x + threadIdx.x;
    if (p >= BB) return;
    int lp = pairs[2 * p], rp = pairs[2 * p + 1];
    g_lp[p] = lp; g_rp[p] = rp;
    g_idxA[p] = lp; g_idxA[BB + p] = rp;
}
__global__ void k_na() {
    int i = blockIdx.x * blockDim.x + threadIdx.x;
    if (i >= 2 * BB) return;
    g_na[i] = g_nb[g_idxA[i]];
}
__global__ void k_pos() {
    int gid = blockIdx.x * blockDim.x + threadIdx.x;
    int p = gid >> 5;
    if (p >= BB) return;
    int lane = gid & 31;
    const __half* a = &g_embh[(size_t)g_lp[p] * OUTD];
    const __half* b = &g_embh[(size_t)g_rp[p] * OUTD];
    float ss = 0.f;
    for (int k = lane * 4; k < OUTD; k += 128) {
        uint2 ua = *(const uint2*)&a[k];
        uint2 ub = *(const uint2*)&b[k];
        float2 a0 = __half22float2(*(__half2*)&ua.x);
        float2 a1 = __half22float2(*(__half2*)&ua.y);
        float2 b0 = __half22float2(*(__half2*)&ub.x);
        float2 b1 = __half22float2(*(__half2*)&ub.y);
        float d0 = a0.x - b0.x, d1 = a0.y - b0.y, d2 = a1.x - b1.x, d3 = a1.y - b1.y;
        ss += d0 * d0 + d1 * d1 + d2 * d2 + d3 * d3;
    }
    ss = warp_sum(ss);
    if (lane == 0) g_pos[p] = ss;
}

// ---------------- mma.sync fp16 GEMM (128x128) + loss + stats ----------------
#define JT 128
#define NS (OUTD / 16)
#define ROWB 48
#define STG_A 0
#define STG_B 6144
#define STGB 12288
#define NSTG 4

__global__ __launch_bounds__(256, 2) void k_gemm_mma() {
    extern __shared__ char dynsmem[];
    __shared__ int s_idx[128];
    const int tid = threadIdx.x;
    const int wid = tid >> 5;
    const int lane = tid & 31;
    const int warp_m = wid & 1;
    const int warp_n = wid >> 1;
    const int bm = blockIdx.x;
    const int jbase = blockIdx.y * JT;
    const uint32_t sbase = smem_u32(dynsmem);

    if (tid < 128) s_idx[tid] = g_idxA[bm * 128 + tid];
    __syncthreads();

    const int lrow = tid >> 1;
    const int lhalf = tid & 1;
    int jld = jbase + lrow;
    if (jld >= NN) jld = 0;
    const __half* gaPtr = g_embh + (size_t)s_idx[lrow] * OUTD + lhalf * 8;
    const __half* gbPtr = g_embh + (size_t)jld * OUTD + lhalf * 8;
    const uint32_t dOff = lrow * ROWB + lhalf * 16;

#pragma unroll
    for (int p = 0; p < 3; p++) {
        uint32_t sb = sbase + p * STGB;
        cpasync16(sb + STG_A + dOff, gaPtr + p * 16);
        cpasync16(sb + STG_B + dOff, gbPtr + p * 16);
        asm volatile("cp.async.commit_group;" ::: "memory");
    }

    float acc[4][4][4] = {};
    const int rsel = lane & 15;
    const int csel = (lane >> 4) * 16;

    for (int it = 0; it < NS; it++) {
        if (it < NS - 2)       asm volatile("cp.async.wait_group 2;" ::: "memory");
        else if (it == NS - 2) asm volatile("cp.async.wait_group 1;" ::: "memory");
        else                   asm volatile("cp.async.wait_group 0;" ::: "memory");
        __syncthreads();

        if (it + 3 < NS) {
            uint32_t sb = sbase + ((it + 3) & 3) * STGB;
            cpasync16(sb + STG_A + dOff, gaPtr + (it + 3) * 16);
            cpasync16(sb + STG_B + dOff, gbPtr + (it + 3) * 16);
            asm volatile("cp.async.commit_group;" ::: "memory");
        }

        const uint32_t sb = sbase + (it & 3) * STGB;
        uint32_t aF[4][4], bF[4][2];
#pragma unroll
        for (int mt = 0; mt < 4; mt++) {
            uint32_t ad = sb + STG_A + (uint32_t)((warp_m * 64 + mt * 16 + rsel) * ROWB + csel);
            ldsm4(aF[mt], ad);
        }
#pragma unroll
        for (int tp = 0; tp < 2; tp++) {
            uint32_t bd = sb + STG_B + (uint32_t)((warp_n * 32 + tp * 16 + rsel) * ROWB + csel);
            uint32_t r[4];
            ldsm4(r, bd);
            bF[tp * 2][0] = r[0]; bF[tp * 2][1] = r[2];
            bF[tp * 2 + 1][0] = r[1]; bF[tp * 2 + 1][1] = r[3];
        }
#pragma unroll
        for (int mt = 0; mt < 4; mt++)
#pragma unroll
            for (int nt = 0; nt < 4; nt++)
                mma_f16(acc[mt][nt], aF[mt], bF[nt]);
    }

    const int lq = lane >> 2;
    const int lr = lane & 3;
    float2 nbv[4];
#pragma unroll
    for (int nt = 0; nt < 4; nt++) {
        int j0 = jbase + warp_n * 32 + nt * 8 + 2 * lr;
        nbv[nt].x = (j0 < NN) ? g_nb[j0] : 0.f;
        nbv[nt].y = (j0 + 1 < NN) ? g_nb[j0 + 1] : 0.f;
    }
#pragma unroll
    for (int mt = 0; mt < 4; mt++) {
#pragma unroll
        for (int h = 0; h < 2; h++) {
            const int i = bm * 128 + warp_m * 64 + mt * 16 + lq + h * 8;
            const int p = i & (BB - 1);
            const float base = g_pos[p] - g_na[i] + GAMMA_C;
            const int lp = g_lp[p], rp = g_rp[p];
            float s = 0.f, q = 0.f, mx = -3.0e38f;
            float* srow = &g_S[(size_t)i * NN];
#pragma unroll
            for (int nt = 0; nt < 4; nt++) {
                int j0 = jbase + warp_n * 32 + nt * 8 + 2 * lr;
                float c0 = acc[mt][nt][h * 2 + 0];
                float c1 = acc[mt][nt][h * 2 + 1];
                if (j0 + 1 < NN) {
                    float v0 = (base - nbv[nt].x + 2.f * c0) *
                               (1.f - (float)(j0 == lp) - (float)(j0 == rp));
                    float v1 = (base - nbv[nt].y + 2.f * c1) *
                               (1.f - (float)(j0 + 1 == lp) - (float)(j0 + 1 == rp));
                    *(float2*)&srow[j0] = make_float2(v0, v1);
                    s += v0 + v1; q += v0 * v0 + v1 * v1;
                    mx = fmaxf(mx, fmaxf(v0, v1));
                } else if (j0 < NN) {
                    float v0 = (base - nbv[nt].x + 2.f * c0) *
                               (1.f - (float)(j0 == lp) - (float)(j0 == rp));
                    srow[j0] = v0;
                    s += v0; q += v0 * v0; mx = fmaxf(mx, v0);
                }
            }
#pragma unroll
            for (int o = 1; o <= 2; o <<= 1) {
                s += __shfl_xor_sync(0xffffffffu, s, o);
                q += __shfl_xor_sync(0xffffffffu, q, o);
                mx = fmaxf(mx, __shfl_xor_sync(0xffffffffu, mx, o));
            }
            if (lr == 0) {
                atomicAdd(&g_rsum[i], (double)s);
                atomicAdd(&g_rsq[i], (double)q);
                atomicMaxF(&g_rmax[i], mx);
            }
        }
    }
}

// ---------------- per-row logsumexp ----------------
__global__ void k_row_exp() {
    int i = blockIdx.x;
    int tid = threadIdx.x;
    double mu_d = g_rsum[i] / NN;
    double var = g_rsq[i] / NN - mu_d * mu_d;
    if (var < 0.0) var = 0.0;
    double sd = sqrt(var);
    float mu = (float)mu_d;
    float inv = (float)(20.0 / sd);
    float zmax = (float)((g_rmax[i] - mu_d) * (20.0 / sd)) + 8.f;
    const float4* row4 = (const float4*)&g_S[(size_t)i * NN];
    float cterm = 8.f - zmax - mu * inv;
    float es = 0.f;
    for (int j = tid; j < NN / 4; j += 256) {
        float4 v = row4[j];
        es += fast_exp(fmaf(v.x, inv, cterm));
        es += fast_exp(fmaf(v.y, inv, cterm));
        es += fast_exp(fmaf(v.z, inv, cterm));
        es += fast_exp(fmaf(v.w, inv, cterm));
    }
    __shared__ float sh[256];
    sh[tid] = es;
    __syncthreads();
    for (int o = 128; o > 0; o >>= 1) {
        if (tid < o) sh[tid] += sh[tid + o];
        __syncthreads();
    }
    if (tid == 0) g_lse[i] = zmax + logf(sh[0]);
}

__global__ void k_final(float* out) {
    int tid = threadIdx.x;
    double acc = 0.0;
    for (int p = tid; p < BB; p += 256) acc += (double)g_lse[p] + (double)g_lse[BB + p];
    __shared__ double sh[256];
    sh[tid] = acc;
    __syncthreads();
    for (int o = 128; o > 0; o >>= 1) {
        if (tid < o) sh[tid] += sh[tid + o];
        __syncthreads();
    }
    if (tid == 0) out[0] = (float)(sh[0] / BB);
}

// ---------------- driver ----------------
extern "C" void kernel_launch(void* const* d_in, const int* in_sizes, int n_in,
                              void* d_out, int out_size) {
    const float* ent_emb = (const float*)d_in[0];
    const float* rel_emb = (const float*)d_in[1];
    const float* attn_e  = (const float*)d_in[2];
    const float* attn_r  = (const float*)d_in[3];
    const int* adj     = (const int*)d_in[5];
    const int* r_index = (const int*)d_in[6];
    const int* ent_adj = (const int*)d_in[7];
    const int* rel_adj = (const int*)d_in[8];
    const int* pairs   = (const int*)d_in[9];
    float* out = (float*)d_out;

    static cudaStream_t sA = 0, sB = 0, sC = 0;
    static cudaEvent_t evRoot = 0, evA = 0, evB = 0, evC = 0;
    static bool sinit = false;
    if (!sinit) {
        cudaStreamCreateWithFlags(&sA, cudaStreamNonBlocking);
        cudaStreamCreateWithFlags(&sB, cudaStreamNonBlocking);
        cudaStreamCreateWithFlags(&sC, cudaStreamNonBlocking);
        cudaEventCreateWithFlags(&evRoot, cudaEventDisableTiming);
        cudaEventCreateWithFlags(&evA, cudaEventDisableTiming);
        cudaEventCreateWithFlags(&evB, cudaEventDisableTiming);
        cudaEventCreateWithFlags(&evC, cudaEventDisableTiming);
        sinit = true;
    }

    const int TPB = 256;
    const int gT   = (TT + TPB - 1) / TPB;
    const int gNZ1 = (NZ + TPB - 1) / TPB;
    const int gWN  = (NN * 32 + TPB - 1) / TPB;

    k_init_stats<<<(NN + TPB - 1) / TPB, TPB>>>();
    k_prep_pairs<<<(BB + TPB - 1) / TPB, TPB>>>(pairs);
    cudaEventRecord(evRoot, 0);
    cudaStreamWaitEvent(sA, evRoot, 0);
    cudaStreamWaitEvent(sB, evRoot, 0);
    cudaStreamWaitEvent(sC, evRoot, 0);

    // chain A: relation prep + adj CSR + per-row softmax stats
    k_relprep<<<(RR * 32 + TPB - 1) / TPB, TPB, 0, sA>>>(rel_emb, attn_e, attn_r);
    k_csr_cnt<<<gT, TPB, 0, sA>>>(adj, TT, 0);
    k_scan<<<1, 1024, 0, sA>>>(0);
    k_fill_adj<<<gT, TPB, 0, sA>>>(adj, r_index);
    k_rowsm<<<gWN, TPB, 0, sA>>>();
    cudaEventRecord(evA, sA);

    // chain B: entity-avg CSR + gather
    k_csr_cnt<<<gNZ1, TPB, 0, sB>>>(ent_adj, NZ, 1);
    k_scan<<<1, 1024, 0, sB>>>(1);
    k_fill_avg<<<gNZ1, TPB, 0, sB>>>(ent_adj, 1);
    k_avg_gather<<<gWN, TPB, 0, sB>>>(ent_emb, 1);
    cudaEventRecord(evB, sB);

    // chain C: relation-avg CSR + gather
    k_csr_cnt<<<gNZ1, TPB, 0, sC>>>(rel_adj, NZ, 2);
    k_scan<<<1, 1024, 0, sC>>>(2);
    k_fill_avg<<<gNZ1, TPB, 0, sC>>>(rel_adj, 2);
    k_avg_gather<<<gWN, TPB, 0, sC>>>(rel_emb, 2);
    cudaEventRecord(evC, sC);

    cudaStreamWaitEvent(0, evB, 0);
    cudaStreamWaitEvent(0, evC, 0);
    k_tanh0<<<gWN, TPB>>>();
    cudaStreamWaitEvent(0, evA, 0);
    k_gat_layer<<<gWN, TPB>>>(0, 0);   // fcurA -> fcurB
    k_gat_layer<<<gWN, TPB>>>(1, 1);   // fcurB -> fcurA

    k_na<<<(2 * BB + TPB - 1) / TPB, TPB>>>();
    k_pos<<<(BB * 32 + TPB - 1) / TPB, TPB>>>();

    cudaFuncSetAttribute(k_gemm_mma, cudaFuncAttributeMaxDynamicSharedMemorySize, NSTG * STGB);
    dim3 gg(2 * BB / 128, (NN + JT - 1) / JT);
    k_gemm_mma<<<gg, 256, NSTG * STGB>>>();
    k_row_exp<<<2 * BB, 256>>>();
    k_final<<<1, 256>>>(out);
}

// round 15
// speedup vs baseline: 6.2017x; 1.0326x over previous
#include <cuda_runtime.h>
#include <cuda_fp16.h>
#include <math.h>
#include <stdint.h>

#define NN 30000
#define RR 1000
#define TT 300000
#define DD 128
#define BB 1024
#define NZ 600000
#define OUTD 768
#define GAMMA_C 3.0f

// ---------------- scratch (device globals) ----------------
__device__ float g_relhat[RR * DD];
__device__ float g_elogit[4 * RR];           // exp(logit) per (channel, rel) — no overflow, |logit|<=1.2
__device__ float g_s[4 * NN];                // reciprocal sum of elogit per (channel,row)
__device__ float g_featE[(size_t)NN * DD];
__device__ float g_featR[(size_t)NN * DD];
__device__ __half g_fcurhA[(size_t)NN * 256];  // fp16 features, interleaved E|R
__device__ __half g_fcurhB[(size_t)NN * 256];
__device__ __half g_embh[(size_t)NN * OUTD];
__device__ float g_nb[NN];
// adjacency CSR (GAT graph)
__device__ int g_rowptr[NN + 1];
__device__ int g_cursor[NN];
__device__ int g_ecol[TT];
__device__ int g_erel[TT];
// averaging CSRs
__device__ int g_rowptrE[NN + 1];
__device__ int g_curE[NN];
__device__ int g_ecolE[NZ];
__device__ int g_rowptrR[NN + 1];
__device__ int g_curR[NN];
__device__ int g_ecolR[NZ];
// loss
__device__ int   g_idxA[2 * BB];
__device__ float g_na[2 * BB];
__device__ float g_pos[BB];
__device__ int   g_lp[BB];
__device__ int   g_rp[BB];
__device__ float g_S[(size_t)2 * BB * NN];   // fp32 loss matrix (fp16 failed: |S|~100 >> sigma)
__device__ double g_rsum[2 * BB];
__device__ double g_rsq[2 * BB];
__device__ float  g_rmax[2 * BB];
__device__ float g_lse[2 * BB];

__device__ __forceinline__ float warp_sum(float v) {
#pragma unroll
    for (int o = 16; o > 0; o >>= 1) v += __shfl_xor_sync(0xffffffffu, v, o);
    return v;
}
__device__ __forceinline__ void atomicMaxF(float* addr, float v) {
    if (v >= 0.f) atomicMax((int*)addr, __float_as_int(v));
    else          atomicMin((unsigned int*)addr, __float_as_uint(v));
}
__device__ __forceinline__ float fast_exp(float x) {
    float t = fmaxf(x * 1.4426950408889634f, -80.0f);
    float fl = floorf(t);
    float f = t - fl;
    float p = 0.0013333558f;
    p = fmaf(p, f, 0.0096181291f);
    p = fmaf(p, f, 0.0555041086f);
    p = fmaf(p, f, 0.2402264476f);
    p = fmaf(p, f, 0.6931471806f);
    p = fmaf(p, f, 1.0f);
    int i = (int)fl;
    return p * __int_as_float((i + 127) << 23);
}
__device__ __forceinline__ uint32_t smem_u32(const void* p) {
    uint32_t a;
    asm("{ .reg .u64 t; cvta.to.shared.u64 t, %1; cvt.u32.u64 %0, t; }" : "=r"(a) : "l"(p));
    return a;
}
__device__ __forceinline__ void cpasync16(uint32_t dst, const void* src) {
    asm volatile("cp.async.cg.shared.global [%0], [%1], 16;" :: "r"(dst), "l"(src));
}
__device__ __forceinline__ void ldsm4(uint32_t* r, uint32_t addr) {
    asm volatile("ldmatrix.sync.aligned.m8n8.x4.shared.b16 {%0,%1,%2,%3}, [%4];"
                 : "=r"(r[0]), "=r"(r[1]), "=r"(r[2]), "=r"(r[3]) : "r"(addr));
}
__device__ __forceinline__ void mma_f16(float* c, const uint32_t* a, const uint32_t* b) {
    asm volatile("mma.sync.aligned.m16n8k16.row.col.f32.f16.f16.f32 "
                 "{%0,%1,%2,%3}, {%4,%5,%6,%7}, {%8,%9}, {%0,%1,%2,%3};"
                 : "+f"(c[0]), "+f"(c[1]), "+f"(c[2]), "+f"(c[3])
                 : "r"(a[0]), "r"(a[1]), "r"(a[2]), "r"(a[3]), "r"(b[0]), "r"(b[1]));
}
__device__ __forceinline__ void st_half4(__half* dst, float a, float b, float c, float d) {
    __half2 h0 = __floats2half2_rn(a, b);
    __half2 h1 = __floats2half2_rn(c, d);
    *(uint2*)dst = make_uint2(*(uint32_t*)&h0, *(uint32_t*)&h1);
}
__device__ __forceinline__ float4 ld_half4(const __half* src) {
    uint2 u = *(const uint2*)src;
    float2 f0 = __half22float2(*(__half2*)&u.x);
    float2 f1 = __half22float2(*(__half2*)&u.y);
    return make_float4(f0.x, f0.y, f1.x, f1.y);
}
__device__ __forceinline__ int* cursor_of(int w) {
    return (w == 0) ? g_cursor : (w == 1) ? g_curE : g_curR;
}
__device__ __forceinline__ int* rowptr_of(int w) {
    return (w == 0) ? g_rowptr : (w == 1) ? g_rowptrE : g_rowptrR;
}

// ---------------- init ----------------
__global__ void k_init_stats() {
    int i = blockIdx.x * blockDim.x + threadIdx.x;
    if (i < NN) { g_nb[i] = 0.f; g_cursor[i] = 0; g_curE[i] = 0; g_curR[i] = 0; }
    if (i < 2 * BB) { g_rsum[i] = 0.0; g_rsq[i] = 0.0; g_rmax[i] = -3.0e38f; }
}

// ---------------- relation prep: normalize + exp(logit) table ----------------
__global__ void k_relprep(const float* __restrict__ rel_emb,
                          const float* __restrict__ attn_e,
                          const float* __restrict__ attn_r) {
    int gid = blockIdx.x * blockDim.x + threadIdx.x;
    int r = gid >> 5;
    if (r >= RR) return;
    int lane = gid & 31;
    int d = lane * 4;
    float4 u = *(const float4*)&rel_emb[(size_t)r * DD + d];
    float ss = u.x * u.x + u.y * u.y + u.z * u.z + u.w * u.w;
    ss = warp_sum(ss);
    float inv = 1.f / fmaxf(sqrtf(ss), 1e-12f);
    u.x *= inv; u.y *= inv; u.z *= inv; u.w *= inv;
    *(float4*)&g_relhat[r * DD + d] = u;
    const float* ks[4] = { attn_e, attn_e + DD, attn_r, attn_r + DD };
#pragma unroll
    for (int c = 0; c < 4; c++) {
        const float4 kk = *(const float4*)&ks[c][d];
        float dot = u.x * kk.x + u.y * kk.y + u.z * kk.z + u.w * kk.w;
        dot = warp_sum(dot);
        if (lane == 0) g_elogit[c * RR + r] = fast_exp(dot);  // |dot| <= ~1.2, safe
    }
}

// ---------------- CSR build ----------------
__global__ void k_csr_cnt(const int* __restrict__ rows, int n, int w) {
    int t = blockIdx.x * blockDim.x + threadIdx.x;
    if (t >= n) return;
    atomicAdd(&cursor_of(w)[rows[t]], 1);
}
__global__ void k_scan(int w) {
    int* cur = cursor_of(w);
    int* rp = rowptr_of(w);
    __shared__ int warpsum[32];
    __shared__ int s_off;
    int tid = threadIdx.x, lane = tid & 31, wd = tid >> 5;
    if (tid == 0) s_off = 0;
    __syncthreads();
    for (int base = 0; base < NN; base += 1024) {
        int i = base + tid;
        int v = (i < NN) ? cur[i] : 0;
        int x = v;
#pragma unroll
        for (int o = 1; o < 32; o <<= 1) {
            int t2 = __shfl_up_sync(0xffffffffu, x, o);
            if (lane >= o) x += t2;
        }
        if (lane == 31) warpsum[wd] = x;
        __syncthreads();
        if (wd == 0) {
            int y = warpsum[lane];
#pragma unroll
            for (int o = 1; o < 32; o <<= 1) {
                int t2 = __shfl_up_sync(0xffffffffu, y, o);
                if (lane >= o) y += t2;
            }
            warpsum[lane] = y;
        }
        __syncthreads();
        int excl = x - v + (wd > 0 ? warpsum[wd - 1] : 0) + s_off;
        if (i < NN) { rp[i] = excl; cur[i] = excl; }
        __syncthreads();
        if (tid == 1023) s_off = excl + v;
        __syncthreads();
    }
    if (tid == 0) rp[NN] = s_off;
}
__global__ void k_fill_adj(const int* __restrict__ adj, const int* __restrict__ r_index) {
    int t = blockIdx.x * blockDim.x + threadIdx.x;
    if (t >= TT) return;
    int pos = atomicAdd(&g_cursor[adj[t]], 1);
    g_ecol[pos] = adj[TT + t];
    g_erel[pos] = r_index[TT + t];
}
__global__ void k_fill_avg(const int* __restrict__ eadj, int w) {
    int t = blockIdx.x * blockDim.x + threadIdx.x;
    if (t >= NZ) return;
    int* cur = (w == 1) ? g_curE : g_curR;
    int* ec = (w == 1) ? g_ecolE : g_ecolR;
    int pos = atomicAdd(&cur[eadj[t]], 1);
    ec[pos] = eadj[NZ + t];
}

// ---------------- per-row softmax denominators (single pass, no max needed) ----------------
__global__ void k_rowsm() {
    int gid = blockIdx.x * blockDim.x + threadIdx.x;
    int r = gid >> 5;
    if (r >= NN) return;
    int lane = gid & 31;
    int beg = g_rowptr[r], end = g_rowptr[r + 1];
    float s[4] = { 0.f, 0.f, 0.f, 0.f };
    for (int e = beg + lane; e < end; e += 32) {
        int rel = g_erel[e];
#pragma unroll
        for (int c = 0; c < 4; c++) s[c] += g_elogit[c * RR + rel];
    }
#pragma unroll
    for (int c = 0; c < 4; c++) {
        s[c] = warp_sum(s[c]);
        if (lane == 0) g_s[c * NN + r] = (s[c] > 0.f) ? 1.f / s[c] : 0.f;
    }
}

// ---------------- neighbor-average gather ----------------
__global__ void k_avg_gather(const float* __restrict__ src, int w) {
    int gid = blockIdx.x * blockDim.x + threadIdx.x;
    int r = gid >> 5;
    if (r >= NN) return;
    int lane = gid & 31;
    int d = lane * 4;
    const int* rp = (w == 1) ? g_rowptrE : g_rowptrR;
    const int* ec = (w == 1) ? g_ecolE : g_ecolR;
    float* feat = (w == 1) ? g_featE : g_featR;
    int beg = rp[r], end = rp[r + 1];
    float4 acc = make_float4(0, 0, 0, 0);
    for (int e = beg; e < end; e++) {
        int c = __ldg(&ec[e]);
        float4 v = *(const float4*)&src[(size_t)c * DD + d];
        acc.x += v.x; acc.y += v.y; acc.z += v.z; acc.w += v.w;
    }
    float inv = (end > beg) ? 1.f / (float)(end - beg) : 0.f;
    acc.x *= inv; acc.y *= inv; acc.z *= inv; acc.w *= inv;
    *(float4*)&feat[(size_t)r * DD + d] = acc;
}

// ---------------- initial tanh: tanh + fcurhA + embh + nb ----------------
__global__ void k_tanh0() {
    int gid = blockIdx.x * blockDim.x + threadIdx.x;
    int n = gid >> 5;
    if (n >= NN) return;
    int lane = gid & 31;
    int d = lane * 4;
    float4 fe = *(const float4*)&g_featE[(size_t)n * DD + d];
    float4 fr = *(const float4*)&g_featR[(size_t)n * DD + d];
    float vE0 = tanhf(fe.x), vE1 = tanhf(fe.y), vE2 = tanhf(fe.z), vE3 = tanhf(fe.w);
    float vR0 = tanhf(fr.x), vR1 = tanhf(fr.y), vR2 = tanhf(fr.z), vR3 = tanhf(fr.w);
    st_half4(&g_fcurhA[(size_t)n * 256 + d], vE0, vE1, vE2, vE3);
    st_half4(&g_fcurhA[(size_t)n * 256 + 128 + d], vR0, vR1, vR2, vR3);
    __half* hrow = &g_embh[(size_t)n * OUTD];
    st_half4(hrow + d, vE0, vE1, vE2, vE3);
    st_half4(hrow + 384 + d, vR0, vR1, vR2, vR3);
    float ss = 0.f;
    float q[8] = { vE0, vE1, vE2, vE3, vR0, vR1, vR2, vR3 };
#pragma unroll
    for (int k = 0; k < 8; k++) {
        float qq = __half2float(__float2half_rn(q[k]));
        ss += qq * qq;
    }
    ss = warp_sum(ss);
    if (lane == 0) atomicAdd(&g_nb[n], ss);
}

// ---------------- GAT layer: warp-per-row gather, fp16 features, table weights ----------------
__global__ void k_gat_layer(int l, int dir) {
    int gid = blockIdx.x * blockDim.x + threadIdx.x;
    int r = gid >> 5;
    if (r >= NN) return;
    int lane = gid & 31;
    int d = lane * 4;
    const __half* src = dir ? g_fcurhB : g_fcurhA;
    __half* dst = dir ? g_fcurhA : g_fcurhB;
    int beg = g_rowptr[r], end = g_rowptr[r + 1];
    const int cE = l, cR = 2 + l;
    const float siE = g_s[cE * NN + r];
    const float siR = g_s[cR * NN + r];
    const float* elE = &g_elogit[cE * RR];
    const float* elR = &g_elogit[cR * RR];
    float4 accE = make_float4(0, 0, 0, 0), accR = make_float4(0, 0, 0, 0);
    for (int e = beg; e < end; e++) {
        int col = __ldg(&g_ecol[e]);
        int rel = __ldg(&g_erel[e]);
        float4 u = *(const float4*)&g_relhat[rel * DD + d];
        float4 xE = ld_half4(&src[(size_t)col * 256 + d]);
        float4 xR = ld_half4(&src[(size_t)col * 256 + 128 + d]);
        float dotE = warp_sum(xE.x * u.x + xE.y * u.y + xE.z * u.z + xE.w * u.w);
        float dotR = warp_sum(xR.x * u.x + xR.y * u.y + xR.z * u.z + xR.w * u.w);
        float wE = elE[rel] * siE;
        float wR = elR[rel] * siR;
        float sE = 2.f * dotE, sR = 2.f * dotR;
        accE.x += wE * (xE.x - sE * u.x); accE.y += wE * (xE.y - sE * u.y);
        accE.z += wE * (xE.z - sE * u.z); accE.w += wE * (xE.w - sE * u.w);
        accR.x += wR * (xR.x - sR * u.x); accR.y += wR * (xR.y - sR * u.y);
        accR.z += wR * (xR.z - sR * u.z); accR.w += wR * (xR.w - sR * u.w);
    }
    float vE0 = tanhf(accE.x), vE1 = tanhf(accE.y), vE2 = tanhf(accE.z), vE3 = tanhf(accE.w);
    float vR0 = tanhf(accR.x), vR1 = tanhf(accR.y), vR2 = tanhf(accR.z), vR3 = tanhf(accR.w);
    st_half4(&dst[(size_t)r * 256 + d], vE0, vE1, vE2, vE3);
    st_half4(&dst[(size_t)r * 256 + 128 + d], vR0, vR1, vR2, vR3);
    int base = (l + 1) * DD;
    __half* hrow = &g_embh[(size_t)r * OUTD];
    st_half4(hrow + base + d, vE0, vE1, vE2, vE3);
    st_half4(hrow + 384 + base + d, vR0, vR1, vR2, vR3);
    float ss = 0.f;
    float q[8] = { vE0, vE1, vE2, vE3, vR0, vR1, vR2, vR3 };
#pragma unroll
    for (int k = 0; k < 8; k++) {
        float qq = __half2float(__float2half_rn(q[k]));
        ss += qq * qq;
    }
    ss = warp_sum(ss);
    if (lane == 0) atomicAdd(&g_nb[r], ss);
}

// ---------------- loss prep ----------------
__global__ void k_prep_pairs(const int* __restrict__ pairs) {
    int p = blockIdx.x * blockDim.x + threadIdx.x;
    if (p >= BB) return;
    int lp = pairs[2 * p], rp = pairs[2 * p + 1];
    g_lp[p] = lp; g_rp[p] = rp;
    g_idxA[p] = lp; g_idxA[BB + p] = rp;
}
__global__ void k_pairstats() {
    int gid = blockIdx.x * blockDim.x + threadIdx.x;
    int p = gid >> 5;
    if (p >= BB) return;
    int lane = gid & 31;
    int lp = g_lp[p], rp = g_rp[p];
    const __half* a = &g_embh[(size_t)lp * OUTD];
    const __half* b = &g_embh[(size_t)rp * OUTD];
    float ss = 0.f;
    for (int k = lane * 4; k < OUTD; k += 128) {
        float4 av = ld_half4(&a[k]);
        float4 bv = ld_half4(&b[k]);
        float d0 = av.x - bv.x, d1 = av.y - bv.y, d2 = av.z - bv.z, d3 = av.w - bv.w;
        ss += d0 * d0 + d1 * d1 + d2 * d2 + d3 * d3;
    }
    ss = warp_sum(ss);
    if (lane == 0) { g_pos[p] = ss; g_na[p] = g_nb[lp]; }
    if (lane == 1) g_na[BB + p] = g_nb[rp];
}

// ---------------- mma.sync fp16 GEMM (128x128) + loss + stats (fp32 S) ----------------
#define JT 128
#define NS (OUTD / 16)
#define ROWB 48
#define STG_A 0
#define STG_B 6144
#define STGB 12288
#define NSTG 4

__global__ __launch_bounds__(256, 2) void k_gemm_mma() {
    extern __shared__ char dynsmem[];
    __shared__ int s_idx[128];
    const int tid = threadIdx.x;
    const int wid = tid >> 5;
    const int lane = tid & 31;
    const int warp_m = wid & 1;
    const int warp_n = wid >> 1;
    const int bm = blockIdx.x;
    const int jbase = blockIdx.y * JT;
    const uint32_t sbase = smem_u32(dynsmem);

    if (tid < 128) s_idx[tid] = g_idxA[bm * 128 + tid];
    __syncthreads();

    const int lrow = tid >> 1;
    const int lhalf = tid & 1;
    int jld = jbase + lrow;
    if (jld >= NN) jld = 0;
    const __half* gaPtr = g_embh + (size_t)s_idx[lrow] * OUTD + lhalf * 8;
    const __half* gbPtr = g_embh + (size_t)jld * OUTD + lhalf * 8;
    const uint32_t dOff = lrow * ROWB + lhalf * 16;

#pragma unroll
    for (int p = 0; p < 3; p++) {
        uint32_t sb = sbase + p * STGB;
        cpasync16(sb + STG_A + dOff, gaPtr + p * 16);
        cpasync16(sb + STG_B + dOff, gbPtr + p * 16);
        asm volatile("cp.async.commit_group;" ::: "memory");
    }

    float acc[4][4][4] = {};
    const int rsel = lane & 15;
    const int csel = (lane >> 4) * 16;

    for (int it = 0; it < NS; it++) {
        if (it < NS - 2)       asm volatile("cp.async.wait_group 2;" ::: "memory");
        else if (it == NS - 2) asm volatile("cp.async.wait_group 1;" ::: "memory");
        else                   asm volatile("cp.async.wait_group 0;" ::: "memory");
        __syncthreads();

        if (it + 3 < NS) {
            uint32_t sb = sbase + ((it + 3) & 3) * STGB;
            cpasync16(sb + STG_A + dOff, gaPtr + (it + 3) * 16);
            cpasync16(sb + STG_B + dOff, gbPtr + (it + 3) * 16);
            asm volatile("cp.async.commit_group;" ::: "memory");
        }

        const uint32_t sb = sbase + (it & 3) * STGB;
        uint32_t aF[4][4], bF[4][2];
#pragma unroll
        for (int mt = 0; mt < 4; mt++) {
            uint32_t ad = sb + STG_A + (uint32_t)((warp_m * 64 + mt * 16 + rsel) * ROWB + csel);
            ldsm4(aF[mt], ad);
        }
#pragma unroll
        for (int tp = 0; tp < 2; tp++) {
            uint32_t bd = sb + STG_B + (uint32_t)((warp_n * 32 + tp * 16 + rsel) * ROWB + csel);
            uint32_t r[4];
            ldsm4(r, bd);
            bF[tp * 2][0] = r[0]; bF[tp * 2][1] = r[2];
            bF[tp * 2 + 1][0] = r[1]; bF[tp * 2 + 1][1] = r[3];
        }
#pragma unroll
        for (int mt = 0; mt < 4; mt++)
#pragma unroll
            for (int nt = 0; nt < 4; nt++)
                mma_f16(acc[mt][nt], aF[mt], bF[nt]);
    }

    const int lq = lane >> 2;
    const int lr = lane & 3;
    float2 nbv[4];
#pragma unroll
    for (int nt = 0; nt < 4; nt++) {
        int j0 = jbase + warp_n * 32 + nt * 8 + 2 * lr;
        nbv[nt].x = (j0 < NN) ? g_nb[j0] : 0.f;
        nbv[nt].y = (j0 + 1 < NN) ? g_nb[j0 + 1] : 0.f;
    }
#pragma unroll
    for (int mt = 0; mt < 4; mt++) {
#pragma unroll
        for (int h = 0; h < 2; h++) {
            const int i = bm * 128 + warp_m * 64 + mt * 16 + lq + h * 8;
            const int p = i & (BB - 1);
            const float base = g_pos[p] - g_na[i] + GAMMA_C;
            const int lp = g_lp[p], rp = g_rp[p];
            float s = 0.f, q = 0.f, mx = -3.0e38f;
            float* srow = &g_S[(size_t)i * NN];
#pragma unroll
            for (int nt = 0; nt < 4; nt++) {
                int j0 = jbase + warp_n * 32 + nt * 8 + 2 * lr;
                float c0 = acc[mt][nt][h * 2 + 0];
                float c1 = acc[mt][nt][h * 2 + 1];
                if (j0 + 1 < NN) {
                    float v0 = (base - nbv[nt].x + 2.f * c0) *
                               (1.f - (float)(j0 == lp) - (float)(j0 == rp));
                    float v1 = (base - nbv[nt].y + 2.f * c1) *
                               (1.f - (float)(j0 + 1 == lp) - (float)(j0 + 1 == rp));
                    *(float2*)&srow[j0] = make_float2(v0, v1);
                    s += v0 + v1; q += v0 * v0 + v1 * v1;
                    mx = fmaxf(mx, fmaxf(v0, v1));
                } else if (j0 < NN) {
                    float v0 = (base - nbv[nt].x + 2.f * c0) *
                               (1.f - (float)(j0 == lp) - (float)(j0 == rp));
                    srow[j0] = v0;
                    s += v0; q += v0 * v0; mx = fmaxf(mx, v0);
                }
            }
#pragma unroll
            for (int o = 1; o <= 2; o <<= 1) {
                s += __shfl_xor_sync(0xffffffffu, s, o);
                q += __shfl_xor_sync(0xffffffffu, q, o);
                mx = fmaxf(mx, __shfl_xor_sync(0xffffffffu, mx, o));
            }
            if (lr == 0) {
                atomicAdd(&g_rsum[i], (double)s);
                atomicAdd(&g_rsq[i], (double)q);
                atomicMaxF(&g_rmax[i], mx);
            }
        }
    }
}

// ---------------- per-row logsumexp ----------------
__global__ void k_row_exp() {
    int i = blockIdx.x;
    int tid = threadIdx.x;
    double mu_d = g_rsum[i] / NN;
    double var = g_rsq[i] / NN - mu_d * mu_d;
    if (var < 0.0) var = 0.0;
    double sd = sqrt(var);
    float mu = (float)mu_d;
    float inv = (float)(20.0 / sd);
    float zmax = (float)((g_rmax[i] - mu_d) * (20.0 / sd)) + 8.f;
    const float4* row4 = (const float4*)&g_S[(size_t)i * NN];
    float cterm = 8.f - zmax - mu * inv;
    float es = 0.f;
    for (int j = tid; j < NN / 4; j += 256) {
        float4 v = row4[j];
        es += fast_exp(fmaf(v.x, inv, cterm));
        es += fast_exp(fmaf(v.y, inv, cterm));
        es += fast_exp(fmaf(v.z, inv, cterm));
        es += fast_exp(fmaf(v.w, inv, cterm));
    }
    __shared__ float sh[256];
    sh[tid] = es;
    __syncthreads();
    for (int o = 128; o > 0; o >>= 1) {
        if (tid < o) sh[tid] += sh[tid + o];
        __syncthreads();
    }
    if (tid == 0) g_lse[i] = zmax + logf(sh[0]);
}

__global__ void k_final(float* out) {
    int tid = threadIdx.x;
    double acc = 0.0;
    for (int p = tid; p < BB; p += 256) acc += (double)g_lse[p] + (double)g_lse[BB + p];
    __shared__ double sh[256];
    sh[tid] = acc;
    __syncthreads();
    for (int o = 128; o > 0; o >>= 1) {
        if (tid < o) sh[tid] += sh[tid + o];
        __syncthreads();
    }
    if (tid == 0) out[0] = (float)(sh[0] / BB);
}

// ---------------- driver ----------------
extern "C" void kernel_launch(void* const* d_in, const int* in_sizes, int n_in,
                              void* d_out, int out_size) {
    const float* ent_emb = (const float*)d_in[0];
    const float* rel_emb = (const float*)d_in[1];
    const float* attn_e  = (const float*)d_in[2];
    const float* attn_r  = (const float*)d_in[3];
    const int* adj     = (const int*)d_in[5];
    const int* r_index = (const int*)d_in[6];
    const int* ent_adj = (const int*)d_in[7];
    const int* rel_adj = (const int*)d_in[8];
    const int* pairs   = (const int*)d_in[9];
    float* out = (float*)d_out;

    static cudaStream_t sA = 0, sB = 0, sC = 0;
    static cudaEvent_t evRoot = 0, evA = 0, evB = 0, evC = 0;
    static bool sinit = false;
    if (!sinit) {
        cudaStreamCreateWithFlags(&sA, cudaStreamNonBlocking);
        cudaStreamCreateWithFlags(&sB, cudaStreamNonBlocking);
        cudaStreamCreateWithFlags(&sC, cudaStreamNonBlocking);
        cudaEventCreateWithFlags(&evRoot, cudaEventDisableTiming);
        cudaEventCreateWithFlags(&evA, cudaEventDisableTiming);
        cudaEventCreateWithFlags(&evB, cudaEventDisableTiming);
        cudaEventCreateWithFlags(&evC, cudaEventDisableTiming);
        sinit = true;
    }

    const int TPB = 256;
    const int gT   = (TT + TPB - 1) / TPB;
    const int gNZ1 = (NZ + TPB - 1) / TPB;
    const int gWN  = (NN * 32 + TPB - 1) / TPB;

    k_init_stats<<<(NN + TPB - 1) / TPB, TPB>>>();
    k_prep_pairs<<<(BB + TPB - 1) / TPB, TPB>>>(pairs);
    cudaEventRecord(evRoot, 0);
    cudaStreamWaitEvent(sA, evRoot, 0);
    cudaStreamWaitEvent(sB, evRoot, 0);
    cudaStreamWaitEvent(sC, evRoot, 0);

    // chain A: relation prep + adj CSR + per-row softmax denominators
    k_relprep<<<(RR * 32 + TPB - 1) / TPB, TPB, 0, sA>>>(rel_emb, attn_e, attn_r);
    k_csr_cnt<<<gT, TPB, 0, sA>>>(adj, TT, 0);
    k_scan<<<1, 1024, 0, sA>>>(0);
    k_fill_adj<<<gT, TPB, 0, sA>>>(adj, r_index);
    k_rowsm<<<gWN, TPB, 0, sA>>>();
    cudaEventRecord(evA, sA);

    // chain B: entity-avg CSR + gather
    k_csr_cnt<<<gNZ1, TPB, 0, sB>>>(ent_adj, NZ, 1);
    k_scan<<<1, 1024, 0, sB>>>(1);
    k_fill_avg<<<gNZ1, TPB, 0, sB>>>(ent_adj, 1);
    k_avg_gather<<<gWN, TPB, 0, sB>>>(ent_emb, 1);
    cudaEventRecord(evB, sB);

    // chain C: relation-avg CSR + gather
    k_csr_cnt<<<gNZ1, TPB, 0, sC>>>(rel_adj, NZ, 2);
    k_scan<<<1, 1024, 0, sC>>>(2);
    k_fill_avg<<<gNZ1, TPB, 0, sC>>>(rel_adj, 2);
    k_avg_gather<<<gWN, TPB, 0, sC>>>(rel_emb, 2);
    cudaEventRecord(evC, sC);

    cudaStreamWaitEvent(0, evB, 0);
    cudaStreamWaitEvent(0, evC, 0);
    k_tanh0<<<gWN, TPB>>>();
    cudaStreamWaitEvent(0, evA, 0);
    k_gat_layer<<<gWN, TPB>>>(0, 0);   // fcurhA -> fcurhB
    k_gat_layer<<<gWN, TPB>>>(1, 1);   // fcurhB -> fcurhA

    k_pairstats<<<(BB * 32 + TPB - 1) / TPB, TPB>>>();

    cudaFuncSetAttribute(k_gemm_mma, cudaFuncAttributeMaxDynamicSharedMemorySize, NSTG * STGB);
    dim3 gg(2 * BB / 128, (NN + JT - 1) / JT);
    k_gemm_mma<<<gg, 256, NSTG * STGB>>>();
    k_row_exp<<<2 * BB, 256>>>();
    k_final<<<1, 256>>>(out);
}